// round 2
// baseline (speedup 1.0000x reference)
#include <cuda_runtime.h>
#include <math.h>

#define B_ 8
#define NPT 16384
#define SPT 1024
#define NS 64
#define DD 64
#define C0 67
#define C0P 68
#define MTOT (B_*SPT*NS)      // 524288
#define RR2 0.09f
#define EPSV 1e-5f

// ---------------- scratch (static device globals; no allocation) -------------
__device__ __align__(16) float g_ptsT[(size_t)B_*NPT*DD];       // 33.5 MB
__device__ float g_newxyz[B_*SPT*3];
__device__ int   g_fpsidx[B_*SPT];
__device__ int   g_newptr[B_*SPT];
__device__ int   g_gid[B_*SPT*NS];
__device__ __align__(16) float g_x0[(size_t)MTOT*C0P];          // 142.6 MB
__device__ __align__(16) float g_y1[(size_t)MTOT*128];          // 268 MB
__device__ __align__(16) float g_y2[(size_t)MTOT*128];          // 268 MB
__device__ __align__(16) float g_y3[(size_t)MTOT*256];          // 537 MB
__device__ float g_sum[3*256];
__device__ float g_sqs[3*256];
__device__ float g_scale[3*256];
__device__ float g_shift[3*256];

// ---------------- zero stats --------------------------------------------------
__global__ void zero_stats_kernel() {
    int t = threadIdx.x;
    if (t < 768) { g_sum[t] = 0.f; g_sqs[t] = 0.f; }
}

// ---------------- transpose points [B,64,N] -> [B,N,64] ----------------------
__global__ void transpose_kernel(const float* __restrict__ pts) {
    __shared__ float tile[32][33];
    int b = blockIdx.z;
    int n0 = blockIdx.x * 32, c0 = blockIdx.y * 32;
    int tx = threadIdx.x, ty = threadIdx.y;   // 32 x 8
    #pragma unroll
    for (int j = 0; j < 32; j += 8)
        tile[ty + j][tx] = pts[((size_t)b*DD + c0 + ty + j)*NPT + n0 + tx];
    __syncthreads();
    #pragma unroll
    for (int j = 0; j < 32; j += 8)
        g_ptsT[((size_t)b*NPT + n0 + ty + j)*DD + c0 + tx] = tile[tx][ty + j];
}

// ---------------- FPS: one CTA per batch, coords in SMEM ---------------------
#define FPS_SMEM ((3*NPT + 64) * 4)
__global__ void __launch_bounds__(1024, 1)
fps_kernel(const float* __restrict__ xyz, const int* __restrict__ idx,
           float* __restrict__ out_xyz) {
    extern __shared__ float fsm[];
    float* sx = fsm;
    float* sy = sx + NPT;
    float* sz = sy + NPT;
    float* redv = sz + NPT;        // 32
    int*   redi = (int*)(redv + 32);
    __shared__ int s_far;

    const int b = blockIdx.x, t = threadIdx.x;
    const float* px = xyz + (size_t)b*3*NPT;
    const float* py = px + NPT;
    const float* pz = py + NPT;

    for (int n = t; n < NPT; n += 1024) { sx[n]=px[n]; sy[n]=py[n]; sz[n]=pz[n]; }

    float dist[16];
    #pragma unroll
    for (int j = 0; j < 16; j++) dist[j] = 1e10f;
    if (t == 0) s_far = 0;
    __syncthreads();

    for (int i = 0; i < SPT; i++) {
        int far = s_far;
        float cx = sx[far], cy = sy[far], cz = sz[far];
        if (t == 0) {
            g_fpsidx[b*SPT + i] = far;
            g_newptr[b*SPT + i] = idx[b*NPT + far];
            g_newxyz[(b*SPT + i)*3 + 0] = cx;
            g_newxyz[(b*SPT + i)*3 + 1] = cy;
            g_newxyz[(b*SPT + i)*3 + 2] = cz;
            out_xyz[(b*3 + 0)*SPT + i] = cx;
            out_xyz[(b*3 + 1)*SPT + i] = cy;
            out_xyz[(b*3 + 2)*SPT + i] = cz;
        }
        if (i == SPT - 1) break;

        float best = -1.f; int bi = 0;
        #pragma unroll
        for (int j = 0; j < 16; j++) {
            int n = t + j*1024;
            float dx = sx[n]-cx, dy = sy[n]-cy, dz = sz[n]-cz;
            float d = dx*dx + dy*dy + dz*dz;
            float dm = fminf(dist[j], d);
            dist[j] = dm;
            if (dm > best) { best = dm; bi = n; }   // ascending n keeps first max
        }
        // warp argmax (first-index tie break)
        #pragma unroll
        for (int o = 16; o > 0; o >>= 1) {
            float ov = __shfl_down_sync(0xffffffffu, best, o);
            int   oi = __shfl_down_sync(0xffffffffu, bi,   o);
            if (ov > best || (ov == best && oi < bi)) { best = ov; bi = oi; }
        }
        if ((t & 31) == 0) { redv[t >> 5] = best; redi[t >> 5] = bi; }
        __syncthreads();
        if (t < 32) {
            best = redv[t]; bi = redi[t];
            #pragma unroll
            for (int o = 16; o > 0; o >>= 1) {
                float ov = __shfl_down_sync(0xffffffffu, best, o);
                int   oi = __shfl_down_sync(0xffffffffu, bi,   o);
                if (ov > best || (ov == best && oi < bi)) { best = ov; bi = oi; }
            }
            if (t == 0) s_far = bi;
        }
        __syncthreads();
    }
}

// ---------------- ball query: one warp per (b,s) -----------------------------
__global__ void __launch_bounds__(256)
ballquery_kernel(const float* __restrict__ xyz, const int* __restrict__ idx) {
    int warp = (blockIdx.x * blockDim.x + threadIdx.x) >> 5;
    int lane = threadIdx.x & 31;
    if (warp >= B_*SPT) return;
    int b = warp / SPT;
    float cx = g_newxyz[warp*3+0], cy = g_newxyz[warp*3+1], cz = g_newxyz[warp*3+2];
    int np = g_newptr[warp];
    float cn = cx*cx + cy*cy + cz*cz;
    const float* px = xyz + (size_t)b*3*NPT;
    const float* py = px + NPT;
    const float* pz = py + NPT;
    const int*   pid = idx + (size_t)b*NPT;
    int* gout = g_gid + (size_t)warp*NS;

    int cnt = 0, first = -1;
    for (int n0 = 0; n0 < NPT && cnt < NS; n0 += 32) {
        int n = n0 + lane;
        float x = px[n], y = py[n], z = pz[n];
        float pn = x*x + y*y + z*z;
        float sq = cn + pn - 2.f*(cx*x + cy*y + cz*z);
        bool hit = !(sq > RR2) && (pid[n] == np);
        unsigned m = __ballot_sync(0xffffffffu, hit);
        if (m) {
            if (first < 0) first = n0 + __ffs(m) - 1;
            int pos = cnt + __popc(m & ((1u << lane) - 1));
            if (hit && pos < NS) gout[pos] = n;
            cnt += __popc(m);
            if (cnt > NS) cnt = NS;
        }
    }
    if (first < 0) { first = g_fpsidx[warp]; }   // cannot happen; safety
    if (cnt == 0) { if (lane == 0) gout[0] = first; cnt = 1; }
    for (int p = cnt + lane; p < NS; p += 32) gout[p] = first;
}

// ---------------- gather/concat -> X0 [M, 68] (pts[0..63], dxyz[64..66], 0) --
__global__ void __launch_bounds__(256)
gather_kernel(const float* __restrict__ xyz) {
    int g16  = threadIdx.x >> 4;
    int lane = threadIdx.x & 15;
    size_t m = (size_t)blockIdx.x * 16 + g16;
    int bs = (int)(m >> 6);
    int b  = bs >> 10;
    int g  = g_gid[m];
    float4 v = *(const float4*)&g_ptsT[((size_t)b*NPT + g)*DD + lane*4];
    float* dst = g_x0 + m*C0P;
    *(float4*)&dst[lane*4] = v;
    if (lane == 0) {
        const float* px = xyz + (size_t)b*3*NPT;
        float cx = g_newxyz[bs*3+0], cy = g_newxyz[bs*3+1], cz = g_newxyz[bs*3+2];
        float4 w = make_float4(px[g]-cx, px[NPT+g]-cy, px[2*NPT+g]-cz, 0.f);
        *(float4*)&dst[64] = w;
    }
}

// ---------------- GEMM: Y = act(A) * W^T, fused BN-relu on A, fused stats ----
template<int LAYER>
__global__ void __launch_bounds__(256)
gemm_kernel(const float* __restrict__ W) {
    constexpr int  KD   = (LAYER == 0) ? C0P : 128;
    constexpr bool TR   = (LAYER > 0);
    constexpr bool PERM = (LAYER == 0);
    constexpr int  O    = (LAYER == 2) ? 256 : 128;
    constexpr int  WLD  = (LAYER == 0) ? C0 : 128;
    const float* A = (LAYER == 0) ? g_x0 : ((LAYER == 1) ? g_y1 : g_y2);
    float*       Y = (LAYER == 0) ? g_y1 : ((LAYER == 1) ? g_y2 : g_y3);
    const float* sc = g_scale + ((LAYER > 0) ? (LAYER - 1)*256 : 0);
    const float* sh = g_shift + ((LAYER > 0) ? (LAYER - 1)*256 : 0);
    float* gsum = g_sum + LAYER*256;
    float* gsqs = g_sqs + LAYER*256;

    extern __shared__ float sm[];
    float* As = sm;              // [KD][132]
    float* Ws = sm + KD*132;     // [KD][132]

    const int t  = threadIdx.x;
    const int tx = t & 15, ty = t >> 4;
    const size_t m0 = (size_t)blockIdx.x * 128;
    const int o0 = blockIdx.y * 128;

    // load W (permuted for layer 0: cols 0..63 = pts chans 3..66, 64..66 = xyz, 67 = 0)
    for (int i = t; i < KD*128; i += 256) {
        int c = i >> 7, o = i & 127;
        float v;
        if (PERM) {
            int csrc = (c < 64) ? (c + 3) : (c - 64);
            v = (c < C0) ? W[(o0 + o)*WLD + csrc] : 0.f;
        } else {
            v = W[(o0 + o)*WLD + c];
        }
        Ws[c*132 + o] = v;
    }
    // load A tile (vectorized), transform, store transposed
    constexpr int KD4 = KD / 4;
    for (int i = t; i < 128*KD4; i += 256) {
        int r = i / KD4, c4 = i - r*KD4;
        float4 v = *(const float4*)&A[(m0 + r)*KD + c4*4];
        if (TR) {
            int c = c4*4;
            v.x = fmaxf(0.f, fmaf(sc[c+0], v.x, sh[c+0]));
            v.y = fmaxf(0.f, fmaf(sc[c+1], v.y, sh[c+1]));
            v.z = fmaxf(0.f, fmaf(sc[c+2], v.z, sh[c+2]));
            v.w = fmaxf(0.f, fmaf(sc[c+3], v.w, sh[c+3]));
        }
        As[(c4*4+0)*132 + r] = v.x;
        As[(c4*4+1)*132 + r] = v.y;
        As[(c4*4+2)*132 + r] = v.z;
        As[(c4*4+3)*132 + r] = v.w;
    }
    __syncthreads();

    float acc[8][8];
    #pragma unroll
    for (int i = 0; i < 8; i++)
        #pragma unroll
        for (int j = 0; j < 8; j++) acc[i][j] = 0.f;

    const int r0 = ty*8, c0 = tx*8;
    #pragma unroll 4
    for (int k = 0; k < KD; k++) {
        float a[8], bb[8];
        *(float4*)(a)    = *(float4*)&As[k*132 + r0];
        *(float4*)(a+4)  = *(float4*)&As[k*132 + r0 + 4];
        *(float4*)(bb)   = *(float4*)&Ws[k*132 + c0];
        *(float4*)(bb+4) = *(float4*)&Ws[k*132 + c0 + 4];
        #pragma unroll
        for (int i = 0; i < 8; i++)
            #pragma unroll
            for (int j = 0; j < 8; j++)
                acc[i][j] = fmaf(a[i], bb[j], acc[i][j]);
    }

    // store + per-column partial stats
    float csum[8], csq[8];
    #pragma unroll
    for (int j = 0; j < 8; j++) { csum[j] = 0.f; csq[j] = 0.f; }
    #pragma unroll
    for (int i = 0; i < 8; i++) {
        size_t row = m0 + r0 + i;
        float4 v0 = make_float4(acc[i][0], acc[i][1], acc[i][2], acc[i][3]);
        float4 v1 = make_float4(acc[i][4], acc[i][5], acc[i][6], acc[i][7]);
        *(float4*)&Y[row*O + o0 + c0]     = v0;
        *(float4*)&Y[row*O + o0 + c0 + 4] = v1;
        #pragma unroll
        for (int j = 0; j < 8; j++) {
            csum[j] += acc[i][j];
            csq[j]  = fmaf(acc[i][j], acc[i][j], csq[j]);
        }
    }
    __syncthreads();
    #pragma unroll
    for (int j = 0; j < 8; j++) As[ty*128 + c0 + j] = csum[j];
    __syncthreads();
    if (t < 128) {
        float s = 0.f;
        #pragma unroll
        for (int q = 0; q < 16; q++) s += As[q*128 + t];
        atomicAdd(&gsum[o0 + t], s);
    }
    __syncthreads();
    #pragma unroll
    for (int j = 0; j < 8; j++) As[ty*128 + c0 + j] = csq[j];
    __syncthreads();
    if (t < 128) {
        float s = 0.f;
        #pragma unroll
        for (int q = 0; q < 16; q++) s += As[q*128 + t];
        atomicAdd(&gsqs[o0 + t], s);
    }
}

// ---------------- BN finalize ------------------------------------------------
__global__ void finalize_kernel(const float* __restrict__ gamma,
                                const float* __restrict__ beta,
                                int layer, int O) {
    int t = threadIdx.x;
    if (t < O) {
        const float invM = 1.f / (float)MTOT;   // 2^-19, exact
        float mu  = g_sum[layer*256 + t] * invM;
        float var = g_sqs[layer*256 + t] * invM - mu*mu;
        if (var < 0.f) var = 0.f;
        float s = gamma[t] * rsqrtf(var + EPSV);
        g_scale[layer*256 + t] = s;
        g_shift[layer*256 + t] = fmaf(-mu, s, beta[t]);
    }
}

// ---------------- BN3 + relu + max over k + transpose out --------------------
__global__ void __launch_bounds__(256)
maxpool_kernel(float* __restrict__ out_feat) {
    extern __shared__ float feat[];   // [256][65]
    int t  = threadIdx.x;
    int b  = blockIdx.x >> 4;
    int s0 = (blockIdx.x & 15) * 64;
    float sc = g_scale[512 + t], sh = g_shift[512 + t];
    for (int sl = 0; sl < 64; sl++) {
        size_t base = ((size_t)(b*SPT + s0 + sl) * NS) * 256 + t;
        float mx = -3.4e38f;
        #pragma unroll 4
        for (int k = 0; k < NS; k++) {
            float v = g_y3[base + (size_t)k*256];
            v = fmaxf(0.f, fmaf(sc, v, sh));
            mx = fmaxf(mx, v);
        }
        feat[t*65 + sl] = mx;
    }
    __syncthreads();
    for (int i = t; i < 256*64; i += 256) {
        int o = i >> 6, sl = i & 63;
        out_feat[((size_t)b*256 + o)*SPT + s0 + sl] = feat[o*65 + sl];
    }
}

// ---------------- launcher ---------------------------------------------------
extern "C" void kernel_launch(void* const* d_in, const int* in_sizes, int n_in,
                              void* d_out, int out_size) {
    const float* xyz = (const float*)d_in[0];
    const float* pts = (const float*)d_in[1];
    const int*   idx = (const int*)d_in[2];
    const float* w0  = (const float*)d_in[3];
    const float* g0  = (const float*)d_in[5];
    const float* be0 = (const float*)d_in[6];
    const float* w1  = (const float*)d_in[7];
    const float* g1  = (const float*)d_in[9];
    const float* be1 = (const float*)d_in[10];
    const float* w2  = (const float*)d_in[11];
    const float* g2  = (const float*)d_in[13];
    const float* be2 = (const float*)d_in[14];

    float* out      = (float*)d_out;
    float* out_xyz  = out;                       // [B,3,SPT]
    float* out_feat = out + (size_t)B_*3*SPT;    // [B,256,SPT]

    cudaFuncSetAttribute(fps_kernel,     cudaFuncAttributeMaxDynamicSharedMemorySize, FPS_SMEM);
    cudaFuncSetAttribute(gemm_kernel<0>, cudaFuncAttributeMaxDynamicSharedMemorySize, 2*C0P*132*4);
    cudaFuncSetAttribute(gemm_kernel<1>, cudaFuncAttributeMaxDynamicSharedMemorySize, 2*128*132*4);
    cudaFuncSetAttribute(gemm_kernel<2>, cudaFuncAttributeMaxDynamicSharedMemorySize, 2*128*132*4);
    cudaFuncSetAttribute(maxpool_kernel, cudaFuncAttributeMaxDynamicSharedMemorySize, 256*65*4);

    zero_stats_kernel<<<1, 768>>>();
    transpose_kernel<<<dim3(NPT/32, DD/32, B_), dim3(32, 8)>>>(pts);
    fps_kernel<<<B_, 1024, FPS_SMEM>>>(xyz, idx, out_xyz);
    ballquery_kernel<<<(B_*SPT)/8, 256>>>(xyz, idx);
    gather_kernel<<<MTOT/16, 256>>>(xyz);

    gemm_kernel<0><<<dim3(MTOT/128, 1), 256, 2*C0P*132*4>>>(w0);
    finalize_kernel<<<1, 256>>>(g0, be0, 0, 128);
    gemm_kernel<1><<<dim3(MTOT/128, 1), 256, 2*128*132*4>>>(w1);
    finalize_kernel<<<1, 256>>>(g1, be1, 1, 128);
    gemm_kernel<2><<<dim3(MTOT/128, 2), 256, 2*128*132*4>>>(w2);
    finalize_kernel<<<1, 256>>>(g2, be2, 2, 256);

    maxpool_kernel<<<B_*(SPT/64), 256, 256*65*4>>>(out_feat);
}

// round 3
// speedup vs baseline: 1.2276x; 1.2276x over previous
#include <cuda_runtime.h>
#include <math.h>

#define B_ 8
#define NPT 16384
#define SPT 1024
#define NS 64
#define DD 64
#define C0 67
#define C0P 72
#define MTOT (B_*SPT*NS)      // 524288
#define NGRP (MTOT/NS)        // 8192
#define RR2 0.09f
#define EPSV 1e-5f

// ---------------- scratch (static device globals; no allocation) -------------
__device__ __align__(16) float g_ptsT[(size_t)B_*NPT*DD];       // 33.5 MB
__device__ float g_newxyz[B_*SPT*3];
__device__ int   g_fpsidx[B_*SPT];
__device__ int   g_newptr[B_*SPT];
__device__ int   g_gid[B_*SPT*NS];
__device__ __align__(16) float g_x0[(size_t)MTOT*C0P];          // 151 MB
__device__ __align__(16) float g_y1[(size_t)MTOT*128];          // 268 MB
__device__ __align__(16) float g_y2[(size_t)MTOT*128];          // 268 MB
__device__ __align__(16) float g_mx[(size_t)NGRP*256];          // 8 MB
__device__ __align__(16) float g_mn[(size_t)NGRP*256];          // 8 MB
__device__ float g_sum[3*256];
__device__ float g_sqs[3*256];
__device__ float g_scale[3*256];
__device__ float g_shift[3*256];

// ---------------- zero stats --------------------------------------------------
__global__ void zero_stats_kernel() {
    int t = threadIdx.x;
    if (t < 768) { g_sum[t] = 0.f; g_sqs[t] = 0.f; }
}

// ---------------- transpose points [B,64,N] -> [B,N,64] ----------------------
__global__ void transpose_kernel(const float* __restrict__ pts) {
    __shared__ float tile[32][33];
    int b = blockIdx.z;
    int n0 = blockIdx.x * 32, c0 = blockIdx.y * 32;
    int tx = threadIdx.x, ty = threadIdx.y;   // 32 x 8
    #pragma unroll
    for (int j = 0; j < 32; j += 8)
        tile[ty + j][tx] = pts[((size_t)b*DD + c0 + ty + j)*NPT + n0 + tx];
    __syncthreads();
    #pragma unroll
    for (int j = 0; j < 32; j += 8)
        g_ptsT[((size_t)b*NPT + n0 + ty + j)*DD + c0 + tx] = tile[tx][ty + j];
}

// ---------------- FPS: one CTA per batch, coords in SMEM ---------------------
#define FPS_SMEM ((3*NPT + 64) * 4)
__global__ void __launch_bounds__(1024, 1)
fps_kernel(const float* __restrict__ xyz, const int* __restrict__ idx,
           float* __restrict__ out_xyz) {
    extern __shared__ float fsm[];
    float* sx = fsm;
    float* sy = sx + NPT;
    float* sz = sy + NPT;
    float* redv = sz + NPT;        // 32
    int*   redi = (int*)(redv + 32);
    __shared__ int s_far;

    const int b = blockIdx.x, t = threadIdx.x;
    const float* px = xyz + (size_t)b*3*NPT;
    const float* py = px + NPT;
    const float* pz = py + NPT;

    for (int n = t; n < NPT; n += 1024) { sx[n]=px[n]; sy[n]=py[n]; sz[n]=pz[n]; }

    float dist[16];
    #pragma unroll
    for (int j = 0; j < 16; j++) dist[j] = 1e10f;
    if (t == 0) s_far = 0;
    __syncthreads();

    for (int i = 0; i < SPT; i++) {
        int far = s_far;
        float cx = sx[far], cy = sy[far], cz = sz[far];
        if (t == 0) {
            g_fpsidx[b*SPT + i] = far;
            g_newptr[b*SPT + i] = idx[b*NPT + far];
            g_newxyz[(b*SPT + i)*3 + 0] = cx;
            g_newxyz[(b*SPT + i)*3 + 1] = cy;
            g_newxyz[(b*SPT + i)*3 + 2] = cz;
            out_xyz[(b*3 + 0)*SPT + i] = cx;
            out_xyz[(b*3 + 1)*SPT + i] = cy;
            out_xyz[(b*3 + 2)*SPT + i] = cz;
        }
        if (i == SPT - 1) break;

        float best = -1.f; int bi = 0;
        #pragma unroll
        for (int j = 0; j < 16; j++) {
            int n = t + j*1024;
            float dx = sx[n]-cx, dy = sy[n]-cy, dz = sz[n]-cz;
            float d = dx*dx + dy*dy + dz*dz;
            float dm = fminf(dist[j], d);
            dist[j] = dm;
            if (dm > best) { best = dm; bi = n; }   // ascending n keeps first max
        }
        // warp argmax (first-index tie break)
        #pragma unroll
        for (int o = 16; o > 0; o >>= 1) {
            float ov = __shfl_down_sync(0xffffffffu, best, o);
            int   oi = __shfl_down_sync(0xffffffffu, bi,   o);
            if (ov > best || (ov == best && oi < bi)) { best = ov; bi = oi; }
        }
        if ((t & 31) == 0) { redv[t >> 5] = best; redi[t >> 5] = bi; }
        __syncthreads();
        if (t < 32) {
            best = redv[t]; bi = redi[t];
            #pragma unroll
            for (int o = 16; o > 0; o >>= 1) {
                float ov = __shfl_down_sync(0xffffffffu, best, o);
                int   oi = __shfl_down_sync(0xffffffffu, bi,   o);
                if (ov > best || (ov == best && oi < bi)) { best = ov; bi = oi; }
            }
            if (t == 0) s_far = bi;
        }
        __syncthreads();
    }
}

// ---------------- ball query: one warp per (b,s) -----------------------------
__global__ void __launch_bounds__(256)
ballquery_kernel(const float* __restrict__ xyz, const int* __restrict__ idx) {
    int warp = (blockIdx.x * blockDim.x + threadIdx.x) >> 5;
    int lane = threadIdx.x & 31;
    if (warp >= B_*SPT) return;
    int b = warp / SPT;
    float cx = g_newxyz[warp*3+0], cy = g_newxyz[warp*3+1], cz = g_newxyz[warp*3+2];
    int np = g_newptr[warp];
    float cn = cx*cx + cy*cy + cz*cz;
    const float* px = xyz + (size_t)b*3*NPT;
    const float* py = px + NPT;
    const float* pz = py + NPT;
    const int*   pid = idx + (size_t)b*NPT;
    int* gout = g_gid + (size_t)warp*NS;

    int cnt = 0, first = -1;
    for (int n0 = 0; n0 < NPT && cnt < NS; n0 += 32) {
        int n = n0 + lane;
        float x = px[n], y = py[n], z = pz[n];
        float pn = x*x + y*y + z*z;
        float sq = cn + pn - 2.f*(cx*x + cy*y + cz*z);
        bool hit = !(sq > RR2) && (pid[n] == np);
        unsigned m = __ballot_sync(0xffffffffu, hit);
        if (m) {
            if (first < 0) first = n0 + __ffs(m) - 1;
            int pos = cnt + __popc(m & ((1u << lane) - 1));
            if (hit && pos < NS) gout[pos] = n;
            cnt += __popc(m);
            if (cnt > NS) cnt = NS;
        }
    }
    if (first < 0) { first = g_fpsidx[warp]; }   // cannot happen; safety
    if (cnt == 0) { if (lane == 0) gout[0] = first; cnt = 1; }
    for (int p = cnt + lane; p < NS; p += 32) gout[p] = first;
}

// ---------------- gather/concat -> X0 [M, 72] (pts[0..63], dxyz[64..66], 0) --
__global__ void __launch_bounds__(256)
gather_kernel(const float* __restrict__ xyz) {
    int g16  = threadIdx.x >> 4;
    int lane = threadIdx.x & 15;
    size_t m = (size_t)blockIdx.x * 16 + g16;
    int bs = (int)(m >> 6);
    int b  = bs >> 10;
    int g  = g_gid[m];
    float4 v = *(const float4*)&g_ptsT[((size_t)b*NPT + g)*DD + lane*4];
    float* dst = g_x0 + m*C0P;
    *(float4*)&dst[lane*4] = v;
    if (lane == 0) {
        const float* px = xyz + (size_t)b*3*NPT;
        float cx = g_newxyz[bs*3+0], cy = g_newxyz[bs*3+1], cz = g_newxyz[bs*3+2];
        float4 w = make_float4(px[g]-cx, px[NPT+g]-cy, px[2*NPT+g]-cz, 0.f);
        *(float4*)&dst[64] = w;
        *(float4*)&dst[68] = make_float4(0.f, 0.f, 0.f, 0.f);
    }
}

// ---------------- tf32 helpers ----------------------------------------------
__device__ __forceinline__ unsigned f2tf(float v) {
    unsigned r;
    asm("cvt.rna.tf32.f32 %0, %1;" : "=r"(r) : "f"(v));
    return r;
}

#define MMA8(d, a, b) asm volatile( \
    "mma.sync.aligned.m16n8k8.row.col.f32.tf32.tf32.f32 " \
    "{%0,%1,%2,%3},{%4,%5,%6,%7},{%8,%9},{%0,%1,%2,%3};\n" \
    : "+f"(d[0]), "+f"(d[1]), "+f"(d[2]), "+f"(d[3]) \
    : "r"(a[0]), "r"(a[1]), "r"(a[2]), "r"(a[3]), "r"(b[0]), "r"(b[1]))

// frag-layout smem indices (chunk-local k in 0..63)
__device__ __forceinline__ int a_fidx(int r, int c) {
    int kstep = c >> 3, c8 = c & 7, mb = r >> 4, r16 = r & 15;
    int ln = ((r16 & 7) << 2) | (c8 & 3);
    int sl = ((c8 >> 2) << 1) | (r16 >> 3);
    return ((kstep*8 + mb)*32 + ln)*4 + sl;
}
__device__ __forceinline__ int b_fidx(int n, int c) {
    int kstep = c >> 3, k8 = c & 7, nb = n >> 3;
    int ln = ((n & 7) << 2) | (k8 & 3);
    int sl = k8 >> 2;
    return ((kstep*16 + nb)*32 + ln)*2 + sl;
}

// ---------------- tf32x3 GEMM: Y = act(A) * W^T, fused stats (+pool L2) ------
// CTA tile 128x128, 8 warps (4 row x 2 col), warp tile 32x64.
template<int LAYER>
__global__ void __launch_bounds__(256, 1)
gemm_tc(const float* __restrict__ Wp) {
    constexpr int KP = (LAYER == 0) ? C0P : 128;   // padded K
    constexpr int WLD = (LAYER == 0) ? C0 : 128;

    const float* A = (LAYER == 0) ? g_x0 : ((LAYER == 1) ? g_y1 : g_y2);
    float*       Y = (LAYER == 0) ? g_y1 : g_y2;   // unused for LAYER==2
    const float* sc = g_scale + ((LAYER > 0) ? (LAYER - 1)*256 : 0);
    const float* sh = g_shift + ((LAYER > 0) ? (LAYER - 1)*256 : 0);

    extern __shared__ float sm[];
    float* Ah = sm;             // 8192
    float* Al = sm + 8192;
    float* Bh = sm + 16384;
    float* Bl = sm + 24576;

    const int t = threadIdx.x;
    const int lane = t & 31, w = t >> 5;
    const int wr = (w & 3) * 32, wc = (w >> 2) * 64;
    const size_t m0 = (size_t)blockIdx.x * 128;
    const int o0 = blockIdx.y * 128;

    float acc[2][8][4];
    #pragma unroll
    for (int mb = 0; mb < 2; mb++)
        #pragma unroll
        for (int nf = 0; nf < 8; nf++)
            #pragma unroll
            for (int c = 0; c < 4; c++) acc[mb][nf][c] = 0.f;

    for (int kc = 0; kc < KP; kc += 64) {
        const int ks8 = (KP - kc >= 64) ? 8 : (KP - kc) / 8;  // ksteps this chunk
        const int cw = ks8 * 2;                                // float4 per row

        // ---- load A chunk, (BN+relu), split hi/lo, store frag layout ----
        for (int i = t; i < 128*cw; i += 256) {
            int r = i / cw, c4 = i - r*cw;
            float4 v = *(const float4*)&A[(m0 + r)*KP + kc + c4*4];
            if (LAYER > 0) {
                int ch = kc + c4*4;
                v.x = fmaxf(0.f, fmaf(sc[ch+0], v.x, sh[ch+0]));
                v.y = fmaxf(0.f, fmaf(sc[ch+1], v.y, sh[ch+1]));
                v.z = fmaxf(0.f, fmaf(sc[ch+2], v.z, sh[ch+2]));
                v.w = fmaxf(0.f, fmaf(sc[ch+3], v.w, sh[ch+3]));
            }
            float e[4] = {v.x, v.y, v.z, v.w};
            #pragma unroll
            for (int j = 0; j < 4; j++) {
                unsigned hb = f2tf(e[j]);
                float hf = __uint_as_float(hb);
                unsigned lb = f2tf(e[j] - hf);
                int fi = a_fidx(r, c4*4 + j);
                Ah[fi] = hf;
                Al[fi] = __uint_as_float(lb);
            }
        }
        // ---- load W chunk ----
        if (LAYER == 0) {
            int cols = ks8 * 8;
            for (int i = t; i < 128*cols; i += 256) {
                int n = i / cols, c = i - n*cols;
                int k = kc + c;
                int csrc = (k < 64) ? (k + 3) : (k - 64);
                float v = (k < C0) ? Wp[(o0 + n)*WLD + csrc] : 0.f;
                unsigned hb = f2tf(v);
                float hf = __uint_as_float(hb);
                unsigned lb = f2tf(v - hf);
                int fi = b_fidx(n, c);
                Bh[fi] = hf;
                Bl[fi] = __uint_as_float(lb);
            }
        } else {
            for (int i = t; i < 128*cw; i += 256) {
                int n = i / cw, c4 = i - n*cw;
                float4 v = *(const float4*)&Wp[(o0 + n)*WLD + kc + c4*4];
                float e[4] = {v.x, v.y, v.z, v.w};
                #pragma unroll
                for (int j = 0; j < 4; j++) {
                    unsigned hb = f2tf(e[j]);
                    float hf = __uint_as_float(hb);
                    unsigned lb = f2tf(e[j] - hf);
                    int fi = b_fidx(n, c4*4 + j);
                    Bh[fi] = hf;
                    Bl[fi] = __uint_as_float(lb);
                }
            }
        }
        __syncthreads();

        // ---- mainloop ----
        for (int kstep = 0; kstep < ks8; kstep++) {
            unsigned ah[2][4], al[2][4];
            #pragma unroll
            for (int mb = 0; mb < 2; mb++) {
                int base = ((kstep*8 + (w & 3)*2 + mb)*32 + lane)*4;
                float4 vh = *(const float4*)&Ah[base];
                float4 vl = *(const float4*)&Al[base];
                ah[mb][0] = __float_as_uint(vh.x); ah[mb][1] = __float_as_uint(vh.y);
                ah[mb][2] = __float_as_uint(vh.z); ah[mb][3] = __float_as_uint(vh.w);
                al[mb][0] = __float_as_uint(vl.x); al[mb][1] = __float_as_uint(vl.y);
                al[mb][2] = __float_as_uint(vl.z); al[mb][3] = __float_as_uint(vl.w);
            }
            #pragma unroll
            for (int nf = 0; nf < 8; nf++) {
                int baseb = ((kstep*16 + (wc >> 3) + nf)*32 + lane)*2;
                float2 bhv = *(const float2*)&Bh[baseb];
                float2 blv = *(const float2*)&Bl[baseb];
                unsigned bh[2] = {__float_as_uint(bhv.x), __float_as_uint(bhv.y)};
                unsigned bl[2] = {__float_as_uint(blv.x), __float_as_uint(blv.y)};
                #pragma unroll
                for (int mb = 0; mb < 2; mb++) {
                    MMA8(acc[mb][nf], ah[mb], bh);
                    MMA8(acc[mb][nf], al[mb], bh);
                    MMA8(acc[mb][nf], ah[mb], bl);
                }
            }
        }
        __syncthreads();
    }

    // ---- epilogue: store Y (layers 0,1) ----
    if (LAYER < 2) {
        #pragma unroll
        for (int mb = 0; mb < 2; mb++)
            #pragma unroll
            for (int h = 0; h < 2; h++) {
                size_t row = m0 + wr + mb*16 + (lane >> 2) + h*8;
                float* yr = &Y[row*128 + wc + (lane & 3)*2];
                #pragma unroll
                for (int nf = 0; nf < 8; nf++)
                    *(float2*)&yr[nf*8] = make_float2(acc[mb][nf][h*2], acc[mb][nf][h*2+1]);
            }
    }

    // ---- per-column partial stats (sum, sumsq), and max/min for LAYER 2 ----
    float csum[8][2], csq[8][2];
    #pragma unroll
    for (int nf = 0; nf < 8; nf++)
        #pragma unroll
        for (int j = 0; j < 2; j++) { csum[nf][j] = 0.f; csq[nf][j] = 0.f; }
    float cmx[8][2], cmn[8][2];
    if (LAYER == 2) {
        #pragma unroll
        for (int nf = 0; nf < 8; nf++)
            #pragma unroll
            for (int j = 0; j < 2; j++) { cmx[nf][j] = -3.4e38f; cmn[nf][j] = 3.4e38f; }
    }
    #pragma unroll
    for (int mb = 0; mb < 2; mb++)
        #pragma unroll
        for (int nf = 0; nf < 8; nf++)
            #pragma unroll
            for (int c = 0; c < 4; c++) {
                int j = c & 1;
                float v = acc[mb][nf][c];
                csum[nf][j] += v;
                csq[nf][j] = fmaf(v, v, csq[nf][j]);
                if (LAYER == 2) {
                    cmx[nf][j] = fmaxf(cmx[nf][j], v);
                    cmn[nf][j] = fminf(cmn[nf][j], v);
                }
            }

    float* red = sm;   // [4][128] reuse
    // sum
    #pragma unroll
    for (int nf = 0; nf < 8; nf++)
        #pragma unroll
        for (int j = 0; j < 2; j++) {
            float v = csum[nf][j];
            #pragma unroll
            for (int o = 4; o < 32; o <<= 1) v += __shfl_xor_sync(0xffffffffu, v, o);
            if (lane < 4) red[(w & 3)*128 + wc + nf*8 + lane*2 + j] = v;
        }
    __syncthreads();
    if (t < 128) {
        float s = red[t] + red[128 + t] + red[256 + t] + red[384 + t];
        atomicAdd(&g_sum[LAYER*256 + o0 + t], s);
    }
    __syncthreads();
    // sumsq
    #pragma unroll
    for (int nf = 0; nf < 8; nf++)
        #pragma unroll
        for (int j = 0; j < 2; j++) {
            float v = csq[nf][j];
            #pragma unroll
            for (int o = 4; o < 32; o <<= 1) v += __shfl_xor_sync(0xffffffffu, v, o);
            if (lane < 4) red[(w & 3)*128 + wc + nf*8 + lane*2 + j] = v;
        }
    __syncthreads();
    if (t < 128) {
        float s = red[t] + red[128 + t] + red[256 + t] + red[384 + t];
        atomicAdd(&g_sqs[LAYER*256 + o0 + t], s);
    }

    if (LAYER == 2) {
        __syncthreads();
        // max: groups = rows [0,64) and [64,128) of the tile (warprows {0,1},{2,3})
        #pragma unroll
        for (int nf = 0; nf < 8; nf++)
            #pragma unroll
            for (int j = 0; j < 2; j++) {
                float v = cmx[nf][j];
                #pragma unroll
                for (int o = 4; o < 32; o <<= 1) v = fmaxf(v, __shfl_xor_sync(0xffffffffu, v, o));
                if (lane < 4) red[(w & 3)*128 + wc + nf*8 + lane*2 + j] = v;
            }
        __syncthreads();
        if (t < 256) {
            int g = t >> 7, col = t & 127;
            float v = fmaxf(red[(2*g)*128 + col], red[(2*g + 1)*128 + col]);
            g_mx[((size_t)(2*blockIdx.x + g))*256 + o0 + col] = v;
        }
        __syncthreads();
        // min
        #pragma unroll
        for (int nf = 0; nf < 8; nf++)
            #pragma unroll
            for (int j = 0; j < 2; j++) {
                float v = cmn[nf][j];
                #pragma unroll
                for (int o = 4; o < 32; o <<= 1) v = fminf(v, __shfl_xor_sync(0xffffffffu, v, o));
                if (lane < 4) red[(w & 3)*128 + wc + nf*8 + lane*2 + j] = v;
            }
        __syncthreads();
        if (t < 256) {
            int g = t >> 7, col = t & 127;
            float v = fminf(red[(2*g)*128 + col], red[(2*g + 1)*128 + col]);
            g_mn[((size_t)(2*blockIdx.x + g))*256 + o0 + col] = v;
        }
    }
}

// ---------------- BN finalize ------------------------------------------------
__global__ void finalize_kernel(const float* __restrict__ gamma,
                                const float* __restrict__ beta,
                                int layer, int O) {
    int t = threadIdx.x;
    if (t < O) {
        const float invM = 1.f / (float)MTOT;   // 2^-19, exact
        float mu  = g_sum[layer*256 + t] * invM;
        float var = g_sqs[layer*256 + t] * invM - mu*mu;
        if (var < 0.f) var = 0.f;
        float s = gamma[t] * rsqrtf(var + EPSV);
        g_scale[layer*256 + t] = s;
        g_shift[layer*256 + t] = fmaf(-mu, s, beta[t]);
    }
}

// ---------------- final: BN3 + relu on pooled extremum, transpose out --------
__global__ void final_out_kernel(float* __restrict__ out_feat) {
    __shared__ float tile[32][33];
    int bs0 = blockIdx.x * 32, c0 = blockIdx.y * 32;
    int tx = threadIdx.x, ty = threadIdx.y;   // 32 x 8
    float s  = g_scale[512 + c0 + tx];
    float shv = g_shift[512 + c0 + tx];
    #pragma unroll
    for (int j = 0; j < 32; j += 8) {
        int bs = bs0 + ty + j;
        float mx = g_mx[(size_t)bs*256 + c0 + tx];
        float mn = g_mn[(size_t)bs*256 + c0 + tx];
        float e = (s >= 0.f) ? mx : mn;
        tile[ty + j][tx] = fmaxf(0.f, fmaf(s, e, shv));
    }
    __syncthreads();
    int b = bs0 >> 10, sl = bs0 & 1023;
    #pragma unroll
    for (int j = 0; j < 32; j += 8)
        out_feat[((size_t)(b*256 + c0 + ty + j))*1024 + sl + tx] = tile[tx][ty + j];
}

// ---------------- launcher ---------------------------------------------------
extern "C" void kernel_launch(void* const* d_in, const int* in_sizes, int n_in,
                              void* d_out, int out_size) {
    const float* xyz = (const float*)d_in[0];
    const float* pts = (const float*)d_in[1];
    const int*   idx = (const int*)d_in[2];
    const float* w0  = (const float*)d_in[3];
    const float* g0  = (const float*)d_in[5];
    const float* be0 = (const float*)d_in[6];
    const float* w1  = (const float*)d_in[7];
    const float* g1  = (const float*)d_in[9];
    const float* be1 = (const float*)d_in[10];
    const float* w2  = (const float*)d_in[11];
    const float* g2  = (const float*)d_in[13];
    const float* be2 = (const float*)d_in[14];

    float* out      = (float*)d_out;
    float* out_xyz  = out;                       // [B,3,SPT]
    float* out_feat = out + (size_t)B_*3*SPT;    // [B,256,SPT]

    const int GSM = 32768 * 4;   // 128 KB frag smem

    cudaFuncSetAttribute(fps_kernel, cudaFuncAttributeMaxDynamicSharedMemorySize, FPS_SMEM);
    cudaFuncSetAttribute(gemm_tc<0>, cudaFuncAttributeMaxDynamicSharedMemorySize, GSM);
    cudaFuncSetAttribute(gemm_tc<1>, cudaFuncAttributeMaxDynamicSharedMemorySize, GSM);
    cudaFuncSetAttribute(gemm_tc<2>, cudaFuncAttributeMaxDynamicSharedMemorySize, GSM);

    zero_stats_kernel<<<1, 768>>>();
    transpose_kernel<<<dim3(NPT/32, DD/32, B_), dim3(32, 8)>>>(pts);
    fps_kernel<<<B_, 1024, FPS_SMEM>>>(xyz, idx, out_xyz);
    ballquery_kernel<<<(B_*SPT)/8, 256>>>(xyz, idx);
    gather_kernel<<<MTOT/16, 256>>>(xyz);

    gemm_tc<0><<<dim3(MTOT/128, 1), 256, GSM>>>(w0);
    finalize_kernel<<<1, 256>>>(g0, be0, 0, 128);
    gemm_tc<1><<<dim3(MTOT/128, 1), 256, GSM>>>(w1);
    finalize_kernel<<<1, 256>>>(g1, be1, 1, 128);
    gemm_tc<2><<<dim3(MTOT/128, 2), 256, GSM>>>(w2);
    finalize_kernel<<<1, 256>>>(g2, be2, 2, 256);

    final_out_kernel<<<dim3(NGRP/32, 256/32), dim3(32, 8)>>>(out_feat);
}

// round 4
// speedup vs baseline: 1.7647x; 1.4376x over previous
#include <cuda_runtime.h>
#include <math.h>

#define B_ 8
#define NPT 16384
#define SPT 1024
#define NS 64
#define DD 64
#define C0 67
#define C0P 72
#define MTOT (B_*SPT*NS)      // 524288
#define NGRP (MTOT/NS)        // 8192
#define RR2 0.09f
#define EPSV 1e-5f

typedef unsigned long long ull;

// ---------------- scratch (static device globals; no allocation) -------------
__device__ __align__(16) float g_ptsT[(size_t)B_*NPT*DD];       // 33.5 MB
__device__ float g_newxyz[B_*SPT*3];
__device__ int   g_fpsidx[B_*SPT];
__device__ int   g_newptr[B_*SPT];
__device__ int   g_gid[B_*SPT*NS];
__device__ __align__(16) float g_x0[(size_t)MTOT*C0P];          // 151 MB
__device__ __align__(16) float g_y1[(size_t)MTOT*128];          // 268 MB
__device__ __align__(16) float g_y2[(size_t)MTOT*128];          // 268 MB
__device__ __align__(16) float g_mx[(size_t)NGRP*256];          // 8 MB
__device__ __align__(16) float g_mn[(size_t)NGRP*256];          // 8 MB
__device__ float g_sum[3*256];
__device__ float g_sqs[3*256];
__device__ float g_scale[3*256];
__device__ float g_shift[3*256];
// pre-split weights (hi/lo tf32), layer0 already permuted+padded to 72
__device__ __align__(16) float g_w0h[128*C0P], g_w0l[128*C0P];
__device__ __align__(16) float g_w1h[128*128], g_w1l[128*128];
__device__ __align__(16) float g_w2h[256*128], g_w2l[256*128];

// ---------------- f32x2 packed helpers ---------------------------------------
#define ADD2(o, a, b) asm("add.rn.f32x2 %0, %1, %2;" : "=l"(o) : "l"(a), "l"(b))
#define MUL2(o, a, b) asm("mul.rn.f32x2 %0, %1, %2;" : "=l"(o) : "l"(a), "l"(b))
#define FMA2(o, a, b, c) asm("fma.rn.f32x2 %0, %1, %2, %3;" : "=l"(o) : "l"(a), "l"(b), "l"(c))

__device__ __forceinline__ ull bcast2(float v) {
    unsigned u = __float_as_uint(v);
    return ((ull)u << 32) | (ull)u;
}
__device__ __forceinline__ float lo2(ull m) { return __uint_as_float((unsigned)m); }
__device__ __forceinline__ float hi2(ull m) { return __uint_as_float((unsigned)(m >> 32)); }

__device__ __forceinline__ unsigned f2tf(float v) {
    unsigned r;
    asm("cvt.rna.tf32.f32 %0, %1;" : "=r"(r) : "f"(v));
    return r;
}

// ---------------- zero stats + split weights ---------------------------------
__global__ void prep_kernel(const float* __restrict__ w0,
                            const float* __restrict__ w1,
                            const float* __restrict__ w2) {
    int i = blockIdx.x * 256 + threadIdx.x;
    if (i < 768) { g_sum[i] = 0.f; g_sqs[i] = 0.f; }
    float v; float* dh; float* dl;
    if (i < 128*C0P) {
        int o = i / C0P, c = i - o*C0P;
        int csrc = (c < 64) ? (c + 3) : (c - 64);
        v = (c < C0) ? w0[o*C0 + csrc] : 0.f;
        dh = &g_w0h[i]; dl = &g_w0l[i];
    } else if (i < 128*C0P + 128*128) {
        int j = i - 128*C0P;
        v = w1[j]; dh = &g_w1h[j]; dl = &g_w1l[j];
    } else if (i < 128*C0P + 128*128 + 256*128) {
        int j = i - 128*C0P - 128*128;
        v = w2[j]; dh = &g_w2h[j]; dl = &g_w2l[j];
    } else return;
    float hf = __uint_as_float(f2tf(v));
    *dh = hf;
    *dl = __uint_as_float(f2tf(v - hf));
}

// ---------------- transpose points [B,64,N] -> [B,N,64] ----------------------
__global__ void transpose_kernel(const float* __restrict__ pts) {
    __shared__ float tile[32][33];
    int b = blockIdx.z;
    int n0 = blockIdx.x * 32, c0 = blockIdx.y * 32;
    int tx = threadIdx.x, ty = threadIdx.y;   // 32 x 8
    #pragma unroll
    for (int j = 0; j < 32; j += 8)
        tile[ty + j][tx] = pts[((size_t)b*DD + c0 + ty + j)*NPT + n0 + tx];
    __syncthreads();
    #pragma unroll
    for (int j = 0; j < 32; j += 8)
        g_ptsT[((size_t)b*NPT + n0 + ty + j)*DD + c0 + tx] = tile[tx][ty + j];
}

// ---------------- FPS: one CTA/batch, packed f32x2 math, x/y in regs ---------
#define FPS_SMEM ((3*NPT + 64) * 4)
__global__ void __launch_bounds__(512, 1)
fps_kernel(const float* __restrict__ xyz, const int* __restrict__ idx,
           float* __restrict__ out_xyz) {
    extern __shared__ float fsm[];
    float* sx = fsm;
    float* sy = sx + NPT;
    float* sz = sy + NPT;
    float* redv = sz + NPT;        // 32
    int*   redi = (int*)(redv + 32);
    __shared__ int s_far;

    const int b = blockIdx.x, t = threadIdx.x;
    const float* px = xyz + (size_t)b*3*NPT;
    const float* py = px + NPT;
    const float* pz = py + NPT;

    for (int n = t; n < NPT; n += 512) { sx[n]=px[n]; sy[n]=py[n]; sz[n]=pz[n]; }
    if (t == 0) s_far = 0;
    __syncthreads();

    // thread t owns 16 point-pairs: pair p = t + i*512 -> points 2p, 2p+1
    ull xp[16], yp[16];
    float dist[32];
    #pragma unroll
    for (int i = 0; i < 16; i++) {
        int p = t + (i << 9);
        xp[i] = *(const ull*)&sx[2*p];
        yp[i] = *(const ull*)&sy[2*p];
        dist[2*i] = 1e10f; dist[2*i+1] = 1e10f;
    }

    for (int s = 0; s < SPT; s++) {
        int far = s_far;
        float cx = sx[far], cy = sy[far], cz = sz[far];
        if (t == 0) {
            g_fpsidx[b*SPT + s] = far;
            g_newptr[b*SPT + s] = idx[b*NPT + far];
            g_newxyz[(b*SPT + s)*3 + 0] = cx;
            g_newxyz[(b*SPT + s)*3 + 1] = cy;
            g_newxyz[(b*SPT + s)*3 + 2] = cz;
            out_xyz[(b*3 + 0)*SPT + s] = cx;
            out_xyz[(b*3 + 1)*SPT + s] = cy;
            out_xyz[(b*3 + 2)*SPT + s] = cz;
        }
        if (s == SPT - 1) break;

        ull ncx = bcast2(-cx), ncy = bcast2(-cy), ncz = bcast2(-cz);
        float best = -1.f; int bi = 0;
        #pragma unroll
        for (int i = 0; i < 16; i++) {
            int p = t + (i << 9);
            ull z2 = *(const ull*)&sz[2*p];
            ull dx2, dy2, dz2, m;
            ADD2(dx2, xp[i], ncx);
            ADD2(dy2, yp[i], ncy);
            ADD2(dz2, z2,    ncz);
            MUL2(m, dx2, dx2);
            FMA2(m, dy2, dy2, m);
            FMA2(m, dz2, dz2, m);
            float d0 = fminf(dist[2*i],   lo2(m));
            float d1 = fminf(dist[2*i+1], hi2(m));
            dist[2*i] = d0; dist[2*i+1] = d1;
            if (d0 > best) { best = d0; bi = 2*p; }
            if (d1 > best) { best = d1; bi = 2*p + 1; }
        }
        // warp argmax (min-index tie break)
        #pragma unroll
        for (int o = 16; o > 0; o >>= 1) {
            float ov = __shfl_down_sync(0xffffffffu, best, o);
            int   oi = __shfl_down_sync(0xffffffffu, bi,   o);
            if (ov > best || (ov == best && oi < bi)) { best = ov; bi = oi; }
        }
        if ((t & 31) == 0) { redv[t >> 5] = best; redi[t >> 5] = bi; }
        __syncthreads();
        if (t < 32) {
            best = (t < 16) ? redv[t] : -2.f;
            bi   = (t < 16) ? redi[t] : 0;
            #pragma unroll
            for (int o = 8; o > 0; o >>= 1) {
                float ov = __shfl_down_sync(0xffffffffu, best, o);
                int   oi = __shfl_down_sync(0xffffffffu, bi,   o);
                if (ov > best || (ov == best && oi < bi)) { best = ov; bi = oi; }
            }
            if (t == 0) s_far = bi;
        }
        __syncthreads();
    }
}

// ---------------- ball query: one warp per (b,s), 128 pts per iter -----------
__global__ void __launch_bounds__(256)
ballquery_kernel(const float* __restrict__ xyz, const int* __restrict__ idx) {
    int warp = (blockIdx.x * blockDim.x + threadIdx.x) >> 5;
    int lane = threadIdx.x & 31;
    if (warp >= B_*SPT) return;
    int b = warp / SPT;
    float cx = g_newxyz[warp*3+0], cy = g_newxyz[warp*3+1], cz = g_newxyz[warp*3+2];
    int np = g_newptr[warp];
    float cn = cx*cx + cy*cy + cz*cz;
    const float* px = xyz + (size_t)b*3*NPT;
    const float* py = px + NPT;
    const float* pz = py + NPT;
    const int*   pid = idx + (size_t)b*NPT;
    int* gout = g_gid + (size_t)warp*NS;

    int cnt = 0, first = -1;
    for (int n0 = 0; n0 < NPT && cnt < NS; n0 += 128) {
        float xs[4], ys[4], zs[4]; int pds[4];
        #pragma unroll
        for (int sb = 0; sb < 4; sb++) {
            int n = n0 + sb*32 + lane;
            xs[sb] = px[n]; ys[sb] = py[n]; zs[sb] = pz[n]; pds[sb] = pid[n];
        }
        #pragma unroll
        for (int sb = 0; sb < 4; sb++) {
            int n = n0 + sb*32 + lane;
            float pn = xs[sb]*xs[sb] + ys[sb]*ys[sb] + zs[sb]*zs[sb];
            float sq = cn + pn - 2.f*(cx*xs[sb] + cy*ys[sb] + cz*zs[sb]);
            bool hit = !(sq > RR2) && (pds[sb] == np);
            unsigned m = __ballot_sync(0xffffffffu, hit);
            if (m) {
                if (first < 0) first = n0 + sb*32 + __ffs(m) - 1;
                int pos = cnt + __popc(m & ((1u << lane) - 1));
                if (hit && pos < NS) gout[pos] = n;
                cnt += __popc(m);
                if (cnt > NS) cnt = NS;
            }
        }
    }
    if (first < 0) { first = g_fpsidx[warp]; }   // cannot happen; safety
    if (cnt == 0) { if (lane == 0) gout[0] = first; cnt = 1; }
    for (int p = cnt + lane; p < NS; p += 32) gout[p] = first;
}

// ---------------- gather/concat -> X0 [M, 72] (pts[0..63], dxyz[64..66], 0) --
__global__ void __launch_bounds__(256)
gather_kernel(const float* __restrict__ xyz) {
    int g16  = threadIdx.x >> 4;
    int lane = threadIdx.x & 15;
    size_t m = (size_t)blockIdx.x * 16 + g16;
    int bs = (int)(m >> 6);
    int b  = bs >> 10;
    int g  = g_gid[m];
    float4 v = *(const float4*)&g_ptsT[((size_t)b*NPT + g)*DD + lane*4];
    float* dst = g_x0 + m*C0P;
    *(float4*)&dst[lane*4] = v;
    if (lane == 0) {
        const float* px = xyz + (size_t)b*3*NPT;
        float cx = g_newxyz[bs*3+0], cy = g_newxyz[bs*3+1], cz = g_newxyz[bs*3+2];
        float4 w = make_float4(px[g]-cx, px[NPT+g]-cy, px[2*NPT+g]-cz, 0.f);
        *(float4*)&dst[64] = w;
        *(float4*)&dst[68] = make_float4(0.f, 0.f, 0.f, 0.f);
    }
}

// ---------------- tf32 mma helpers -------------------------------------------
#define MMA8(d, a, b) asm volatile( \
    "mma.sync.aligned.m16n8k8.row.col.f32.tf32.tf32.f32 " \
    "{%0,%1,%2,%3},{%4,%5,%6,%7},{%8,%9},{%0,%1,%2,%3};\n" \
    : "+f"(d[0]), "+f"(d[1]), "+f"(d[2]), "+f"(d[3]) \
    : "r"(a[0]), "r"(a[1]), "r"(a[2]), "r"(a[3]), "r"(b[0]), "r"(b[1]))

// frag-layout smem indices (chunk-local k in 0..31)
__device__ __forceinline__ int a_fidx(int r, int c) {
    int kstep = c >> 3, c8 = c & 7, mb = r >> 4, r16 = r & 15;
    int ln = ((r16 & 7) << 2) | (c8 & 3);
    int sl = ((c8 >> 2) << 1) | (r16 >> 3);
    return ((kstep*8 + mb)*32 + ln)*4 + sl;
}
__device__ __forceinline__ int b_fidx(int n, int c) {
    int kstep = c >> 3, k8 = c & 7, nb = n >> 3;
    int ln = ((n & 7) << 2) | (k8 & 3);
    int sl = k8 >> 2;
    return ((kstep*16 + nb)*32 + ln)*2 + sl;
}

// ---------------- tf32x3 GEMM: Y = act(A) * W^T, fused stats (+pool L2) ------
// CTA tile 128x128, 8 warps (4 row x 2 col), warp tile 32x64, K-chunks of 32.
template<int LAYER>
__global__ void __launch_bounds__(256)
gemm_tc() {
    constexpr int KP = (LAYER == 0) ? C0P : 128;   // padded K

    const float* A = (LAYER == 0) ? g_x0 : ((LAYER == 1) ? g_y1 : g_y2);
    float*       Y = (LAYER == 0) ? g_y1 : g_y2;   // unused for LAYER==2
    const float* Wh = (LAYER == 0) ? g_w0h : ((LAYER == 1) ? g_w1h : g_w2h);
    const float* Wl = (LAYER == 0) ? g_w0l : ((LAYER == 1) ? g_w1l : g_w2l);
    const float* sc = g_scale + ((LAYER > 0) ? (LAYER - 1)*256 : 0);
    const float* sh = g_shift + ((LAYER > 0) ? (LAYER - 1)*256 : 0);

    extern __shared__ float sm[];
    float* Ah = sm;             // 4096 each
    float* Al = sm + 4096;
    float* Bh = sm + 8192;
    float* Bl = sm + 12288;

    const int t = threadIdx.x;
    const int lane = t & 31, w = t >> 5;
    const int wr = (w & 3) * 32, wc = (w >> 2) * 64;
    const size_t m0 = (size_t)blockIdx.x * 128;
    const int o0 = blockIdx.y * 128;

    float acc[2][8][4];
    #pragma unroll
    for (int mb = 0; mb < 2; mb++)
        #pragma unroll
        for (int nf = 0; nf < 8; nf++)
            #pragma unroll
            for (int c = 0; c < 4; c++) acc[mb][nf][c] = 0.f;

    for (int kc = 0; kc < KP; kc += 32) {
        const int rem = KP - kc;
        const int ks8 = (rem >= 32) ? 4 : (rem >> 3);
        const int cw = ks8 * 2;                      // float4 per row

        // ---- load A chunk, (BN+relu), split hi/lo, store frag layout ----
        for (int i = t; i < 128*cw; i += 256) {
            int r = i / cw, c4 = i - r*cw;
            float4 v = *(const float4*)&A[(m0 + r)*KP + kc + c4*4];
            if (LAYER > 0) {
                int ch = kc + c4*4;
                v.x = fmaxf(0.f, fmaf(sc[ch+0], v.x, sh[ch+0]));
                v.y = fmaxf(0.f, fmaf(sc[ch+1], v.y, sh[ch+1]));
                v.z = fmaxf(0.f, fmaf(sc[ch+2], v.z, sh[ch+2]));
                v.w = fmaxf(0.f, fmaf(sc[ch+3], v.w, sh[ch+3]));
            }
            float e[4] = {v.x, v.y, v.z, v.w};
            #pragma unroll
            for (int j = 0; j < 4; j++) {
                float hf = __uint_as_float(f2tf(e[j]));
                int fi = a_fidx(r, c4*4 + j);
                Ah[fi] = hf;
                Al[fi] = __uint_as_float(f2tf(e[j] - hf));
            }
        }
        // ---- load pre-split W chunk ----
        for (int i = t; i < 128*cw; i += 256) {
            int n = i / cw, c4 = i - n*cw;
            float4 vh = *(const float4*)&Wh[(o0 + n)*KP + kc + c4*4];
            float4 vl = *(const float4*)&Wl[(o0 + n)*KP + kc + c4*4];
            float eh[4] = {vh.x, vh.y, vh.z, vh.w};
            float el[4] = {vl.x, vl.y, vl.z, vl.w};
            #pragma unroll
            for (int j = 0; j < 4; j++) {
                int fi = b_fidx(n, c4*4 + j);
                Bh[fi] = eh[j];
                Bl[fi] = el[j];
            }
        }
        __syncthreads();

        // ---- mainloop ----
        for (int kstep = 0; kstep < ks8; kstep++) {
            unsigned ah[2][4], al[2][4];
            #pragma unroll
            for (int mb = 0; mb < 2; mb++) {
                int base = ((kstep*8 + (w & 3)*2 + mb)*32 + lane)*4;
                float4 vh = *(const float4*)&Ah[base];
                float4 vl = *(const float4*)&Al[base];
                ah[mb][0] = __float_as_uint(vh.x); ah[mb][1] = __float_as_uint(vh.y);
                ah[mb][2] = __float_as_uint(vh.z); ah[mb][3] = __float_as_uint(vh.w);
                al[mb][0] = __float_as_uint(vl.x); al[mb][1] = __float_as_uint(vl.y);
                al[mb][2] = __float_as_uint(vl.z); al[mb][3] = __float_as_uint(vl.w);
            }
            #pragma unroll
            for (int nf = 0; nf < 8; nf++) {
                int baseb = ((kstep*16 + (wc >> 3) + nf)*32 + lane)*2;
                float2 bhv = *(const float2*)&Bh[baseb];
                float2 blv = *(const float2*)&Bl[baseb];
                unsigned bh[2] = {__float_as_uint(bhv.x), __float_as_uint(bhv.y)};
                unsigned bl[2] = {__float_as_uint(blv.x), __float_as_uint(blv.y)};
                #pragma unroll
                for (int mb = 0; mb < 2; mb++) {
                    MMA8(acc[mb][nf], ah[mb], bh);
                    MMA8(acc[mb][nf], al[mb], bh);
                    MMA8(acc[mb][nf], ah[mb], bl);
                }
            }
        }
        __syncthreads();
    }

    // ---- epilogue: store Y (layers 0,1) ----
    if (LAYER < 2) {
        #pragma unroll
        for (int mb = 0; mb < 2; mb++)
            #pragma unroll
            for (int h = 0; h < 2; h++) {
                size_t row = m0 + wr + mb*16 + (lane >> 2) + h*8;
                float* yr = &Y[row*128 + wc + (lane & 3)*2];
                #pragma unroll
                for (int nf = 0; nf < 8; nf++)
                    *(float2*)&yr[nf*8] = make_float2(acc[mb][nf][h*2], acc[mb][nf][h*2+1]);
            }
    }

    // ---- per-column partial stats (sum, sumsq), and max/min for LAYER 2 ----
    float csum[8][2], csq[8][2];
    #pragma unroll
    for (int nf = 0; nf < 8; nf++)
        #pragma unroll
        for (int j = 0; j < 2; j++) { csum[nf][j] = 0.f; csq[nf][j] = 0.f; }
    float cmx[8][2], cmn[8][2];
    if (LAYER == 2) {
        #pragma unroll
        for (int nf = 0; nf < 8; nf++)
            #pragma unroll
            for (int j = 0; j < 2; j++) { cmx[nf][j] = -3.4e38f; cmn[nf][j] = 3.4e38f; }
    }
    #pragma unroll
    for (int mb = 0; mb < 2; mb++)
        #pragma unroll
        for (int nf = 0; nf < 8; nf++)
            #pragma unroll
            for (int c = 0; c < 4; c++) {
                int j = c & 1;
                float v = acc[mb][nf][c];
                csum[nf][j] += v;
                csq[nf][j] = fmaf(v, v, csq[nf][j]);
                if (LAYER == 2) {
                    cmx[nf][j] = fmaxf(cmx[nf][j], v);
                    cmn[nf][j] = fminf(cmn[nf][j], v);
                }
            }

    float* red = sm;   // [4][128] reuse
    // sum
    #pragma unroll
    for (int nf = 0; nf < 8; nf++)
        #pragma unroll
        for (int j = 0; j < 2; j++) {
            float v = csum[nf][j];
            #pragma unroll
            for (int o = 4; o < 32; o <<= 1) v += __shfl_xor_sync(0xffffffffu, v, o);
            if (lane < 4) red[(w & 3)*128 + wc + nf*8 + lane*2 + j] = v;
        }
    __syncthreads();
    if (t < 128) {
        float s = red[t] + red[128 + t] + red[256 + t] + red[384 + t];
        atomicAdd(&g_sum[LAYER*256 + o0 + t], s);
    }
    __syncthreads();
    // sumsq
    #pragma unroll
    for (int nf = 0; nf < 8; nf++)
        #pragma unroll
        for (int j = 0; j < 2; j++) {
            float v = csq[nf][j];
            #pragma unroll
            for (int o = 4; o < 32; o <<= 1) v += __shfl_xor_sync(0xffffffffu, v, o);
            if (lane < 4) red[(w & 3)*128 + wc + nf*8 + lane*2 + j] = v;
        }
    __syncthreads();
    if (t < 128) {
        float s = red[t] + red[128 + t] + red[256 + t] + red[384 + t];
        atomicAdd(&g_sqs[LAYER*256 + o0 + t], s);
    }

    if (LAYER == 2) {
        __syncthreads();
        // max: groups = rows [0,64) and [64,128) of the tile
        #pragma unroll
        for (int nf = 0; nf < 8; nf++)
            #pragma unroll
            for (int j = 0; j < 2; j++) {
                float v = cmx[nf][j];
                #pragma unroll
                for (int o = 4; o < 32; o <<= 1) v = fmaxf(v, __shfl_xor_sync(0xffffffffu, v, o));
                if (lane < 4) red[(w & 3)*128 + wc + nf*8 + lane*2 + j] = v;
            }
        __syncthreads();
        if (t < 256) {
            int g = t >> 7, col = t & 127;
            float v = fmaxf(red[(2*g)*128 + col], red[(2*g + 1)*128 + col]);
            g_mx[((size_t)(2*blockIdx.x + g))*256 + o0 + col] = v;
        }
        __syncthreads();
        // min
        #pragma unroll
        for (int nf = 0; nf < 8; nf++)
            #pragma unroll
            for (int j = 0; j < 2; j++) {
                float v = cmn[nf][j];
                #pragma unroll
                for (int o = 4; o < 32; o <<= 1) v = fminf(v, __shfl_xor_sync(0xffffffffu, v, o));
                if (lane < 4) red[(w & 3)*128 + wc + nf*8 + lane*2 + j] = v;
            }
        __syncthreads();
        if (t < 256) {
            int g = t >> 7, col = t & 127;
            float v = fminf(red[(2*g)*128 + col], red[(2*g + 1)*128 + col]);
            g_mn[((size_t)(2*blockIdx.x + g))*256 + o0 + col] = v;
        }
    }
}

// ---------------- BN finalize ------------------------------------------------
__global__ void finalize_kernel(const float* __restrict__ gamma,
                                const float* __restrict__ beta,
                                int layer, int O) {
    int t = threadIdx.x;
    if (t < O) {
        const float invM = 1.f / (float)MTOT;   // 2^-19, exact
        float mu  = g_sum[layer*256 + t] * invM;
        float var = g_sqs[layer*256 + t] * invM - mu*mu;
        if (var < 0.f) var = 0.f;
        float s = gamma[t] * rsqrtf(var + EPSV);
        g_scale[layer*256 + t] = s;
        g_shift[layer*256 + t] = fmaf(-mu, s, beta[t]);
    }
}

// ---------------- final: BN3 + relu on pooled extremum, transpose out --------
__global__ void final_out_kernel(float* __restrict__ out_feat) {
    __shared__ float tile[32][33];
    int bs0 = blockIdx.x * 32, c0 = blockIdx.y * 32;
    int tx = threadIdx.x, ty = threadIdx.y;   // 32 x 8
    float s  = g_scale[512 + c0 + tx];
    float shv = g_shift[512 + c0 + tx];
    #pragma unroll
    for (int j = 0; j < 32; j += 8) {
        int bs = bs0 + ty + j;
        float mx = g_mx[(size_t)bs*256 + c0 + tx];
        float mn = g_mn[(size_t)bs*256 + c0 + tx];
        float e = (s >= 0.f) ? mx : mn;
        tile[ty + j][tx] = fmaxf(0.f, fmaf(s, e, shv));
    }
    __syncthreads();
    int b = bs0 >> 10, sl = bs0 & 1023;
    #pragma unroll
    for (int j = 0; j < 32; j += 8)
        out_feat[((size_t)(b*256 + c0 + ty + j))*1024 + sl + tx] = tile[tx][ty + j];
}

// ---------------- launcher ---------------------------------------------------
extern "C" void kernel_launch(void* const* d_in, const int* in_sizes, int n_in,
                              void* d_out, int out_size) {
    const float* xyz = (const float*)d_in[0];
    const float* pts = (const float*)d_in[1];
    const int*   idx = (const int*)d_in[2];
    const float* w0  = (const float*)d_in[3];
    const float* g0  = (const float*)d_in[5];
    const float* be0 = (const float*)d_in[6];
    const float* w1  = (const float*)d_in[7];
    const float* g1  = (const float*)d_in[9];
    const float* be1 = (const float*)d_in[10];
    const float* w2  = (const float*)d_in[11];
    const float* g2  = (const float*)d_in[13];
    const float* be2 = (const float*)d_in[14];

    float* out      = (float*)d_out;
    float* out_xyz  = out;                       // [B,3,SPT]
    float* out_feat = out + (size_t)B_*3*SPT;    // [B,256,SPT]

    const int GSM = 16384 * 4;   // 64 KB frag smem

    cudaFuncSetAttribute(fps_kernel, cudaFuncAttributeMaxDynamicSharedMemorySize, FPS_SMEM);
    cudaFuncSetAttribute(gemm_tc<0>, cudaFuncAttributeMaxDynamicSharedMemorySize, GSM);
    cudaFuncSetAttribute(gemm_tc<1>, cudaFuncAttributeMaxDynamicSharedMemorySize, GSM);
    cudaFuncSetAttribute(gemm_tc<2>, cudaFuncAttributeMaxDynamicSharedMemorySize, GSM);

    prep_kernel<<<(128*C0P + 128*128 + 256*128 + 255)/256, 256>>>(w0, w1, w2);
    transpose_kernel<<<dim3(NPT/32, DD/32, B_), dim3(32, 8)>>>(pts);
    fps_kernel<<<B_, 512, FPS_SMEM>>>(xyz, idx, out_xyz);
    ballquery_kernel<<<(B_*SPT)/8, 256>>>(xyz, idx);
    gather_kernel<<<MTOT/16, 256>>>(xyz);

    gemm_tc<0><<<dim3(MTOT/128, 1), 256, GSM>>>();
    finalize_kernel<<<1, 256>>>(g0, be0, 0, 128);
    gemm_tc<1><<<dim3(MTOT/128, 1), 256, GSM>>>();
    finalize_kernel<<<1, 256>>>(g1, be1, 1, 128);
    gemm_tc<2><<<dim3(MTOT/128, 2), 256, GSM>>>();
    finalize_kernel<<<1, 256>>>(g2, be2, 2, 256);

    final_out_kernel<<<dim3(NGRP/32, 256/32), dim3(32, 8)>>>(out_feat);
}

// round 7
// speedup vs baseline: 2.2714x; 1.2871x over previous
#include <cuda_runtime.h>
#include <cuda_bf16.h>
#include <math.h>

#define B_ 8
#define NPT 16384
#define SPT 1024
#define NS 64
#define DD 64
#define C0 67
#define C0P 80
#define MTOT (B_*SPT*NS)      // 524288
#define NGRP (MTOT/NS)        // 8192
#define RR2 0.09f
#define EPSV 1e-5f

typedef unsigned long long ull;
typedef unsigned uint;

// ---------------- scratch (static device globals; no allocation) -------------
__device__ __align__(16) float g_ptsT[(size_t)B_*NPT*DD];       // 33.5 MB
__device__ __align__(16) float4 g_pk[(size_t)B_*NPT];           // 2 MB packed xyz+id
__device__ float g_newxyz[B_*SPT*3];
__device__ int   g_fpsidx[B_*SPT];
__device__ int   g_newptr[B_*SPT];
__device__ int   g_gid[B_*SPT*NS];
__device__ __align__(16) float g_x0[(size_t)MTOT*C0P];          // 168 MB
__device__ __align__(16) float g_y1[(size_t)MTOT*128];          // 268 MB
__device__ __align__(16) float g_y2[(size_t)MTOT*128];          // 268 MB
__device__ __align__(16) float g_mx[(size_t)NGRP*256];          // 8 MB
__device__ __align__(16) float g_mn[(size_t)NGRP*256];          // 8 MB
__device__ float g_sum[3*256];
__device__ float g_sqs[3*256];
__device__ float g_scale[3*256];
__device__ float g_shift[3*256];
// weights pre-split (bf16 hi/lo) and packed in m16n8k16 B-fragment layout
// layout: [otile][ksg][nb=16][lane=32][reg=2] packed u32 (2 bf16)
#define W0WORDS (5*1024)      // KP=80: 5 ksteps
#define W1WORDS (8*1024)      // KP=128
#define W2WORDS (2*8*1024)    // 2 otiles
__device__ __align__(16) uint g_wf0h[W0WORDS], g_wf0l[W0WORDS];
__device__ __align__(16) uint g_wf1h[W1WORDS], g_wf1l[W1WORDS];
__device__ __align__(16) uint g_wf2h[W2WORDS], g_wf2l[W2WORDS];

// ---------------- f32x2 packed helpers ---------------------------------------
#define ADD2(o, a, b) asm("add.rn.f32x2 %0, %1, %2;" : "=l"(o) : "l"(a), "l"(b))
#define MUL2(o, a, b) asm("mul.rn.f32x2 %0, %1, %2;" : "=l"(o) : "l"(a), "l"(b))
#define FMA2(o, a, b, c) asm("fma.rn.f32x2 %0, %1, %2, %3;" : "=l"(o) : "l"(a), "l"(b), "l"(c))

__device__ __forceinline__ ull bcast2(float v) {
    unsigned u = __float_as_uint(v);
    return ((ull)u << 32) | (ull)u;
}
__device__ __forceinline__ float lo2(ull m) { return __uint_as_float((unsigned)m); }
__device__ __forceinline__ float hi2(ull m) { return __uint_as_float((unsigned)(m >> 32)); }

// pack two floats to bf16x2 word: {lo half = a, hi half = b}
__device__ __forceinline__ uint pk_bf2(float a, float b) {
    uint r;
    asm("cvt.rn.bf16x2.f32 %0, %1, %2;" : "=r"(r) : "f"(b), "f"(a));
    return r;
}
// split pair (v0,v1) into hi word + lo word (residual)
__device__ __forceinline__ void split2(float v0, float v1, uint& wh, uint& wl) {
    wh = pk_bf2(v0, v1);
    __nv_bfloat162 h2 = *(__nv_bfloat162*)&wh;
    float h0 = __bfloat162float(h2.x), h1 = __bfloat162float(h2.y);
    wl = pk_bf2(v0 - h0, v1 - h1);
}

// ---------------- prep: zero stats, split+frag-pack weights, pack xyz --------
__global__ void prep_kernel(const float* __restrict__ w0,
                            const float* __restrict__ w1,
                            const float* __restrict__ w2,
                            const float* __restrict__ xyz,
                            const int* __restrict__ idx) {
    int i = blockIdx.x * 256 + threadIdx.x;
    if (i < 768) { g_sum[i] = 0.f; g_sqs[i] = 0.f; }
    // pack xyz+id (B*NPT = 131072 entries)
    if (i < B_*NPT) {
        int b = i >> 14, n = i & (NPT-1);
        const float* px = xyz + (size_t)b*3*NPT;
        g_pk[i] = make_float4(px[n], px[NPT+n], px[2*NPT+n], __int_as_float(idx[i]));
    }
    // weight fragments
    if (i >= W0WORDS + W1WORDS + W2WORDS) return;
    int layer, j, otile = 0;
    if (i < W0WORDS) { layer = 0; j = i; }
    else if (i < W0WORDS + W1WORDS) { layer = 1; j = i - W0WORDS; }
    else { layer = 2; j = i - W0WORDS - W1WORDS; otile = j >> 13; j &= 8191; }
    int reg = j & 1, lane = (j >> 1) & 31, nb = (j >> 6) & 15, ksg = j >> 10;
    int o  = otile*128 + nb*8 + (lane >> 2);
    int c0 = ksg*16 + reg*8 + (lane & 3)*2;
    float v0, v1;
    if (layer == 0) {
        int s0 = (c0   < 64) ? (c0   + 3) : (c0   - 64);
        int s1 = (c0+1 < 64) ? (c0+1 + 3) : (c0+1 - 64);
        v0 = (c0   < C0) ? w0[o*C0 + s0] : 0.f;
        v1 = (c0+1 < C0) ? w0[o*C0 + s1] : 0.f;
    } else if (layer == 1) {
        v0 = w1[o*128 + c0]; v1 = w1[o*128 + c0 + 1];
    } else {
        v0 = w2[o*128 + c0]; v1 = w2[o*128 + c0 + 1];
    }
    uint wh, wl;
    split2(v0, v1, wh, wl);
    if (layer == 0)      { g_wf0h[i] = wh; g_wf0l[i] = wl; }
    else if (layer == 1) { g_wf1h[j] = wh; g_wf1l[j] = wl; }
    else                 { int k = (otile << 13) | j; g_wf2h[k] = wh; g_wf2l[k] = wl; }
}

// ---------------- transpose points [B,64,N] -> [B,N,64] ----------------------
__global__ void transpose_kernel(const float* __restrict__ pts) {
    __shared__ float tile[32][33];
    int b = blockIdx.z;
    int n0 = blockIdx.x * 32, c0 = blockIdx.y * 32;
    int tx = threadIdx.x, ty = threadIdx.y;   // 32 x 8
    #pragma unroll
    for (int j = 0; j < 32; j += 8)
        tile[ty + j][tx] = pts[((size_t)b*DD + c0 + ty + j)*NPT + n0 + tx];
    __syncthreads();
    #pragma unroll
    for (int j = 0; j < 32; j += 8)
        g_ptsT[((size_t)b*NPT + n0 + ty + j)*DD + c0 + tx] = tile[tx][ty + j];
}

// ---------------- FPS: one CTA/batch, packed f32x2 math, x/y in regs ---------
#define FPS_SMEM ((3*NPT + 64) * 4)
__global__ void __launch_bounds__(512, 1)
fps_kernel(const float* __restrict__ xyz, const int* __restrict__ idx,
           float* __restrict__ out_xyz) {
    extern __shared__ float fsm[];
    float* sx = fsm;
    float* sy = sx + NPT;
    float* sz = sy + NPT;
    float* redv = sz + NPT;        // 32
    int*   redi = (int*)(redv + 32);
    __shared__ int s_far;

    const int b = blockIdx.x, t = threadIdx.x;
    const float* px = xyz + (size_t)b*3*NPT;
    const float* py = px + NPT;
    const float* pz = py + NPT;

    for (int n = t; n < NPT; n += 512) { sx[n]=px[n]; sy[n]=py[n]; sz[n]=pz[n]; }
    if (t == 0) s_far = 0;
    __syncthreads();

    ull xp[16], yp[16];
    float dist[32];
    #pragma unroll
    for (int i = 0; i < 16; i++) {
        int p = t + (i << 9);
        xp[i] = *(const ull*)&sx[2*p];
        yp[i] = *(const ull*)&sy[2*p];
        dist[2*i] = 1e10f; dist[2*i+1] = 1e10f;
    }

    for (int s = 0; s < SPT; s++) {
        int far = s_far;
        float cx = sx[far], cy = sy[far], cz = sz[far];
        if (t == 0) {
            g_fpsidx[b*SPT + s] = far;
            g_newptr[b*SPT + s] = idx[b*NPT + far];
            g_newxyz[(b*SPT + s)*3 + 0] = cx;
            g_newxyz[(b*SPT + s)*3 + 1] = cy;
            g_newxyz[(b*SPT + s)*3 + 2] = cz;
            out_xyz[(b*3 + 0)*SPT + s] = cx;
            out_xyz[(b*3 + 1)*SPT + s] = cy;
            out_xyz[(b*3 + 2)*SPT + s] = cz;
        }
        if (s == SPT - 1) break;

        ull ncx = bcast2(-cx), ncy = bcast2(-cy), ncz = bcast2(-cz);
        float best = -1.f; int bi = 0;
        #pragma unroll
        for (int i = 0; i < 16; i++) {
            int p = t + (i << 9);
            ull z2 = *(const ull*)&sz[2*p];
            ull dx2, dy2, dz2, m;
            ADD2(dx2, xp[i], ncx);
            ADD2(dy2, yp[i], ncy);
            ADD2(dz2, z2,    ncz);
            MUL2(m, dx2, dx2);
            FMA2(m, dy2, dy2, m);
            FMA2(m, dz2, dz2, m);
            float d0 = fminf(dist[2*i],   lo2(m));
            float d1 = fminf(dist[2*i+1], hi2(m));
            dist[2*i] = d0; dist[2*i+1] = d1;
            if (d0 > best) { best = d0; bi = 2*p; }
            if (d1 > best) { best = d1; bi = 2*p + 1; }
        }
        #pragma unroll
        for (int o = 16; o > 0; o >>= 1) {
            float ov = __shfl_down_sync(0xffffffffu, best, o);
            int   oi = __shfl_down_sync(0xffffffffu, bi,   o);
            if (ov > best || (ov == best && oi < bi)) { best = ov; bi = oi; }
        }
        if ((t & 31) == 0) { redv[t >> 5] = best; redi[t >> 5] = bi; }
        __syncthreads();
        if (t < 32) {
            best = (t < 16) ? redv[t] : -2.f;
            bi   = (t < 16) ? redi[t] : 0;
            #pragma unroll
            for (int o = 8; o > 0; o >>= 1) {
                float ov = __shfl_down_sync(0xffffffffu, best, o);
                int   oi = __shfl_down_sync(0xffffffffu, bi,   o);
                if (ov > best || (ov == best && oi < bi)) { best = ov; bi = oi; }
            }
            if (t == 0) s_far = bi;
        }
        __syncthreads();
    }
}

// ---------------- ball query: one warp per (b,s), packed float4 --------------
__global__ void __launch_bounds__(256)
ballquery_kernel() {
    int warp = (blockIdx.x * blockDim.x + threadIdx.x) >> 5;
    int lane = threadIdx.x & 31;
    if (warp >= B_*SPT) return;
    int b = warp / SPT;
    float cx = g_newxyz[warp*3+0], cy = g_newxyz[warp*3+1], cz = g_newxyz[warp*3+2];
    int np = g_newptr[warp];
    float cn = cx*cx + cy*cy + cz*cz;
    const float4* pk = g_pk + (size_t)b*NPT;
    int* gout = g_gid + (size_t)warp*NS;

    int cnt = 0, first = -1;
    for (int n0 = 0; n0 < NPT && cnt < NS; n0 += 128) {
        float4 vv[4];
        #pragma unroll
        for (int sb = 0; sb < 4; sb++) vv[sb] = pk[n0 + sb*32 + lane];
        #pragma unroll
        for (int sb = 0; sb < 4; sb++) {
            int n = n0 + sb*32 + lane;
            float x = vv[sb].x, y = vv[sb].y, z = vv[sb].z;
            float pn = x*x + y*y + z*z;
            float sq = cn + pn - 2.f*(cx*x + cy*y + cz*z);
            bool hit = !(sq > RR2) && (__float_as_int(vv[sb].w) == np);
            unsigned m = __ballot_sync(0xffffffffu, hit);
            if (m) {
                if (first < 0) first = n0 + sb*32 + __ffs(m) - 1;
                int pos = cnt + __popc(m & ((1u << lane) - 1));
                if (hit && pos < NS) gout[pos] = n;
                cnt += __popc(m);
                if (cnt > NS) cnt = NS;
            }
        }
    }
    if (first < 0) { first = g_fpsidx[warp]; }
    if (cnt == 0) { if (lane == 0) gout[0] = first; cnt = 1; }
    for (int p = cnt + lane; p < NS; p += 32) gout[p] = first;
}

// ---------------- gather/concat -> X0 [M, 80] --------------------------------
__global__ void __launch_bounds__(256)
gather_kernel(const float* __restrict__ xyz) {
    int g16  = threadIdx.x >> 4;
    int lane = threadIdx.x & 15;
    size_t m = (size_t)blockIdx.x * 16 + g16;
    int bs = (int)(m >> 6);
    int b  = bs >> 10;
    int g  = g_gid[m];
    float4 v = *(const float4*)&g_ptsT[((size_t)b*NPT + g)*DD + lane*4];
    float* dst = g_x0 + m*C0P;
    *(float4*)&dst[lane*4] = v;
    if (lane == 0) {
        const float* px = xyz + (size_t)b*3*NPT;
        float cx = g_newxyz[bs*3+0], cy = g_newxyz[bs*3+1], cz = g_newxyz[bs*3+2];
        *(float4*)&dst[64] = make_float4(px[g]-cx, px[NPT+g]-cy, px[2*NPT+g]-cz, 0.f);
        *(float4*)&dst[68] = make_float4(0.f,0.f,0.f,0.f);
        *(float4*)&dst[72] = make_float4(0.f,0.f,0.f,0.f);
        *(float4*)&dst[76] = make_float4(0.f,0.f,0.f,0.f);
    }
}

// ---------------- bf16 mma helpers -------------------------------------------
#define MMAB(d, a, b) asm volatile( \
    "mma.sync.aligned.m16n8k16.row.col.f32.bf16.bf16.f32 " \
    "{%0,%1,%2,%3},{%4,%5,%6,%7},{%8,%9},{%0,%1,%2,%3};\n" \
    : "+f"(d[0]), "+f"(d[1]), "+f"(d[2]), "+f"(d[3]) \
    : "r"(a[0]), "r"(a[1]), "r"(a[2]), "r"(a[3]), "r"(b[0]), "r"(b[1]))

// ---------------- one K-chunk (<=64) : load A (split), copy W, mma -----------
template<int KS16, int LAYER>
__device__ __forceinline__ void do_chunk(
    const float* __restrict__ A, size_t m0, int kc,
    const float* __restrict__ sc, const float* __restrict__ sh,
    const uint* __restrict__ Wfh, const uint* __restrict__ Wfl, int wfbase,
    uint* Ah, uint* Al, uint* Bh, uint* Bl,
    int t, int lane, int w, int wc, float acc[2][8][4])
{
    constexpr int KP = (LAYER == 0) ? C0P : 128;
    constexpr int CW = KS16 * 4;          // float4 per row this chunk

    // A: 128 rows x KS16*16 cols
    for (int i = t; i < 128*CW; i += 256) {
        int r = i / CW, c4 = i - r*CW;
        float4 v = *(const float4*)&A[(m0 + r)*KP + kc + c4*4];
        if (LAYER > 0) {
            int ch = kc + c4*4;
            v.x = fmaxf(0.f, fmaf(sc[ch+0], v.x, sh[ch+0]));
            v.y = fmaxf(0.f, fmaf(sc[ch+1], v.y, sh[ch+1]));
            v.z = fmaxf(0.f, fmaf(sc[ch+2], v.z, sh[ch+2]));
            v.w = fmaxf(0.f, fmaf(sc[ch+3], v.w, sh[ch+3]));
        }
        int r16 = r & 15, mb = r >> 4;
        int kk0 = (c4*4) & 15, kst = (c4*4) >> 4;
        int reg = (r16 >> 3) + ((kk0 >> 3) << 1);
        int l0  = ((r16 & 7) << 2) | ((kk0 >> 1) & 3);
        int i0  = ((kst*8 + mb)*32 + l0)*4 + reg;
        uint wh, wl;
        split2(v.x, v.y, wh, wl);
        Ah[i0] = wh; Al[i0] = wl;
        split2(v.z, v.w, wh, wl);
        Ah[i0 + 4] = wh; Al[i0 + 4] = wl;    // pair at kk0+2 -> lane+1
    }
    // B: straight copy of pre-packed fragments
    {
        const uint4* shp = (const uint4*)(Wfh + wfbase);
        const uint4* slp = (const uint4*)(Wfl + wfbase);
        for (int i = t; i < KS16*256; i += 256) {
            ((uint4*)Bh)[i] = shp[i];
            ((uint4*)Bl)[i] = slp[i];
        }
    }
    __syncthreads();

    #pragma unroll
    for (int kstep = 0; kstep < KS16; kstep++) {
        uint ah[2][4], al[2][4];
        #pragma unroll
        for (int mb = 0; mb < 2; mb++) {
            int base = ((kstep*8 + (w & 3)*2 + mb)*32 + lane)*4;
            uint4 vh = *(const uint4*)&Ah[base];
            uint4 vl = *(const uint4*)&Al[base];
            ah[mb][0]=vh.x; ah[mb][1]=vh.y; ah[mb][2]=vh.z; ah[mb][3]=vh.w;
            al[mb][0]=vl.x; al[mb][1]=vl.y; al[mb][2]=vl.z; al[mb][3]=vl.w;
        }
        #pragma unroll
        for (int nf = 0; nf < 8; nf++) {
            int baseb = ((kstep*16 + (wc >> 3) + nf)*32 + lane)*2;
            uint2 bhv = *(const uint2*)&Bh[baseb];
            uint2 blv = *(const uint2*)&Bl[baseb];
            uint bh[2] = {bhv.x, bhv.y};
            uint bl[2] = {blv.x, blv.y};
            #pragma unroll
            for (int mb = 0; mb < 2; mb++) {
                MMAB(acc[mb][nf], ah[mb], bh);
                MMAB(acc[mb][nf], al[mb], bh);
                MMAB(acc[mb][nf], ah[mb], bl);
            }
        }
    }
    __syncthreads();
}

// ---------------- bf16x3 GEMM: Y = act(A) * W^T, fused stats (+pool L2) ------
template<int LAYER>
__global__ void __launch_bounds__(256)
gemm_tc() {
    const float* A = (LAYER == 0) ? g_x0 : ((LAYER == 1) ? g_y1 : g_y2);
    float*       Y = (LAYER == 0) ? g_y1 : g_y2;
    const uint* Wfh = (LAYER == 0) ? g_wf0h : ((LAYER == 1) ? g_wf1h : g_wf2h);
    const uint* Wfl = (LAYER == 0) ? g_wf0l : ((LAYER == 1) ? g_wf1l : g_wf2l);
    const float* sc = g_scale + ((LAYER > 0) ? (LAYER - 1)*256 : 0);
    const float* sh = g_shift + ((LAYER > 0) ? (LAYER - 1)*256 : 0);

    extern __shared__ uint usm[];
    uint* Ah = usm;              // 4096 each
    uint* Al = usm + 4096;
    uint* Bh = usm + 8192;
    uint* Bl = usm + 12288;

    const int t = threadIdx.x;
    const int lane = t & 31, w = t >> 5;
    const int wr = (w & 3) * 32, wc = (w >> 2) * 64;
    const size_t m0 = (size_t)blockIdx.x * 128;
    const int o0 = blockIdx.y * 128;
    const int otile = blockIdx.y;

    float acc[2][8][4];
    #pragma unroll
    for (int mb = 0; mb < 2; mb++)
        #pragma unroll
        for (int nf = 0; nf < 8; nf++)
            #pragma unroll
            for (int c = 0; c < 4; c++) acc[mb][nf][c] = 0.f;

    int wb0 = (LAYER == 2) ? (otile*8)*1024 : 0;
    do_chunk<4, LAYER>(A, m0, 0, sc, sh, Wfh, Wfl, wb0, Ah, Al, Bh, Bl, t, lane, w, wc, acc);
    if (LAYER == 0)
        do_chunk<1, LAYER>(A, m0, 64, sc, sh, Wfh, Wfl, 4*1024, Ah, Al, Bh, Bl, t, lane, w, wc, acc);
    else
        do_chunk<4, LAYER>(A, m0, 64, sc, sh, Wfh, Wfl, wb0 + 4*1024, Ah, Al, Bh, Bl, t, lane, w, wc, acc);

    // ---- epilogue: store Y (layers 0,1) ----
    if (LAYER < 2) {
        #pragma unroll
        for (int mb = 0; mb < 2; mb++)
            #pragma unroll
            for (int h = 0; h < 2; h++) {
                size_t row = m0 + wr + mb*16 + (lane >> 2) + h*8;
                float* yr = &Y[row*128 + wc + (lane & 3)*2];
                #pragma unroll
                for (int nf = 0; nf < 8; nf++)
                    *(float2*)&yr[nf*8] = make_float2(acc[mb][nf][h*2], acc[mb][nf][h*2+1]);
            }
    }

    // ---- per-column partial stats, and max/min for LAYER 2 ----
    float csum[8][2], csq[8][2];
    #pragma unroll
    for (int nf = 0; nf < 8; nf++)
        #pragma unroll
        for (int j = 0; j < 2; j++) { csum[nf][j] = 0.f; csq[nf][j] = 0.f; }
    float cmx[8][2], cmn[8][2];
    if (LAYER == 2) {
        #pragma unroll
        for (int nf = 0; nf < 8; nf++)
            #pragma unroll
            for (int j = 0; j < 2; j++) { cmx[nf][j] = -3.4e38f; cmn[nf][j] = 3.4e38f; }
    }
    #pragma unroll
    for (int mb = 0; mb < 2; mb++)
        #pragma unroll
        for (int nf = 0; nf < 8; nf++)
            #pragma unroll
            for (int c = 0; c < 4; c++) {
                int j = c & 1;
                float v = acc[mb][nf][c];
                csum[nf][j] += v;
                csq[nf][j] = fmaf(v, v, csq[nf][j]);
                if (LAYER == 2) {
                    cmx[nf][j] = fmaxf(cmx[nf][j], v);
                    cmn[nf][j] = fminf(cmn[nf][j], v);
                }
            }

    float* red = (float*)usm;   // [4][128]
    #pragma unroll
    for (int nf = 0; nf < 8; nf++)
        #pragma unroll
        for (int j = 0; j < 2; j++) {
            float v = csum[nf][j];
            #pragma unroll
            for (int o = 4; o < 32; o <<= 1) v += __shfl_xor_sync(0xffffffffu, v, o);
            if (lane < 4) red[(w & 3)*128 + wc + nf*8 + lane*2 + j] = v;
        }
    __syncthreads();
    if (t < 128) {
        float s = red[t] + red[128 + t] + red[256 + t] + red[384 + t];
        atomicAdd(&g_sum[LAYER*256 + o0 + t], s);
    }
    __syncthreads();
    #pragma unroll
    for (int nf = 0; nf < 8; nf++)
        #pragma unroll
        for (int j = 0; j < 2; j++) {
            float v = csq[nf][j];
            #pragma unroll
            for (int o = 4; o < 32; o <<= 1) v += __shfl_xor_sync(0xffffffffu, v, o);
            if (lane < 4) red[(w & 3)*128 + wc + nf*8 + lane*2 + j] = v;
        }
    __syncthreads();
    if (t < 128) {
        float s = red[t] + red[128 + t] + red[256 + t] + red[384 + t];
        atomicAdd(&g_sqs[LAYER*256 + o0 + t], s);
    }

    if (LAYER == 2) {
        __syncthreads();
        #pragma unroll
        for (int nf = 0; nf < 8; nf++)
            #pragma unroll
            for (int j = 0; j < 2; j++) {
                float v = cmx[nf][j];
                #pragma unroll
                for (int o = 4; o < 32; o <<= 1) v = fmaxf(v, __shfl_xor_sync(0xffffffffu, v, o));
                if (lane < 4) red[(w & 3)*128 + wc + nf*8 + lane*2 + j] = v;
            }
        __syncthreads();
        if (t < 256) {
            int g = t >> 7, col = t & 127;
            float v = fmaxf(red[(2*g)*128 + col], red[(2*g + 1)*128 + col]);
            g_mx[((size_t)(2*blockIdx.x + g))*256 + o0 + col] = v;
        }
        __syncthreads();
        #pragma unroll
        for (int nf = 0; nf < 8; nf++)
            #pragma unroll
            for (int j = 0; j < 2; j++) {
                float v = cmn[nf][j];
                #pragma unroll
                for (int o = 4; o < 32; o <<= 1) v = fminf(v, __shfl_xor_sync(0xffffffffu, v, o));
                if (lane < 4) red[(w & 3)*128 + wc + nf*8 + lane*2 + j] = v;
            }
        __syncthreads();
        if (t < 256) {
            int g = t >> 7, col = t & 127;
            float v = fminf(red[(2*g)*128 + col], red[(2*g + 1)*128 + col]);
            g_mn[((size_t)(2*blockIdx.x + g))*256 + o0 + col] = v;
        }
    }
}

// ---------------- BN finalize ------------------------------------------------
__global__ void finalize_kernel(const float* __restrict__ gamma,
                                const float* __restrict__ beta,
                                int layer, int O) {
    int t = threadIdx.x;
    if (t < O) {
        const float invM = 1.f / (float)MTOT;
        float mu  = g_sum[layer*256 + t] * invM;
        float var = g_sqs[layer*256 + t] * invM - mu*mu;
        if (var < 0.f) var = 0.f;
        float s = gamma[t] * rsqrtf(var + EPSV);
        g_scale[layer*256 + t] = s;
        g_shift[layer*256 + t] = fmaf(-mu, s, beta[t]);
    }
}

// ---------------- final: BN3 + relu on pooled extremum, transpose out --------
__global__ void final_out_kernel(float* __restrict__ out_feat) {
    __shared__ float tile[32][33];
    int bs0 = blockIdx.x * 32, c0 = blockIdx.y * 32;
    int tx = threadIdx.x, ty = threadIdx.y;   // 32 x 8
    float s  = g_scale[512 + c0 + tx];
    float shv = g_shift[512 + c0 + tx];
    #pragma unroll
    for (int j = 0; j < 32; j += 8) {
        int bs = bs0 + ty + j;
        float mx = g_mx[(size_t)bs*256 + c0 + tx];
        float mn = g_mn[(size_t)bs*256 + c0 + tx];
        float e = (s >= 0.f) ? mx : mn;
        tile[ty + j][tx] = fmaxf(0.f, fmaf(s, e, shv));
    }
    __syncthreads();
    int b = bs0 >> 10, sl = bs0 & 1023;
    #pragma unroll
    for (int j = 0; j < 32; j += 8)
        out_feat[((size_t)(b*256 + c0 + ty + j))*1024 + sl + tx] = tile[tx][ty + j];
}

// ---------------- launcher ---------------------------------------------------
extern "C" void kernel_launch(void* const* d_in, const int* in_sizes, int n_in,
                              void* d_out, int out_size) {
    const float* xyz = (const float*)d_in[0];
    const float* pts = (const float*)d_in[1];
    const int*   idx = (const int*)d_in[2];
    const float* w0  = (const float*)d_in[3];
    const float* g0  = (const float*)d_in[5];
    const float* be0 = (const float*)d_in[6];
    const float* w1  = (const float*)d_in[7];
    const float* g1  = (const float*)d_in[9];
    const float* be1 = (const float*)d_in[10];
    const float* w2  = (const float*)d_in[11];
    const float* g2  = (const float*)d_in[13];
    const float* be2 = (const float*)d_in[14];

    float* out      = (float*)d_out;
    float* out_xyz  = out;                       // [B,3,SPT]
    float* out_feat = out + (size_t)B_*3*SPT;    // [B,256,SPT]

    const int GSM = 16384 * 4;   // 64 KB

    cudaFuncSetAttribute(fps_kernel, cudaFuncAttributeMaxDynamicSharedMemorySize, FPS_SMEM);
    cudaFuncSetAttribute(gemm_tc<0>, cudaFuncAttributeMaxDynamicSharedMemorySize, GSM);
    cudaFuncSetAttribute(gemm_tc<1>, cudaFuncAttributeMaxDynamicSharedMemorySize, GSM);
    cudaFuncSetAttribute(gemm_tc<2>, cudaFuncAttributeMaxDynamicSharedMemorySize, GSM);

    prep_kernel<<<(B_*NPT + 255)/256, 256>>>(w0, w1, w2, xyz, idx);
    transpose_kernel<<<dim3(NPT/32, DD/32, B_), dim3(32, 8)>>>(pts);
    fps_kernel<<<B_, 512, FPS_SMEM>>>(xyz, idx, out_xyz);
    ballquery_kernel<<<(B_*SPT)/8, 256>>>();
    gather_kernel<<<MTOT/16, 256>>>(xyz);

    gemm_tc<0><<<dim3(MTOT/128, 1), 256, GSM>>>();
    finalize_kernel<<<1, 256>>>(g0, be0, 0, 128);
    gemm_tc<1><<<dim3(MTOT/128, 1), 256, GSM>>>();
    finalize_kernel<<<1, 256>>>(g1, be1, 1, 128);
    gemm_tc<2><<<dim3(MTOT/128, 2), 256, GSM>>>();
    finalize_kernel<<<1, 256>>>(g2, be2, 2, 256);

    final_out_kernel<<<dim3(NGRP/32, 256/32), dim3(32, 8)>>>(out_feat);
}

// round 8
// speedup vs baseline: 2.4257x; 1.0680x over previous
#include <cuda_runtime.h>
#include <cuda_bf16.h>
#include <math.h>

#define B_ 8
#define NPT 16384
#define SPT 1024
#define NS 64
#define DD 64
#define C0 67
#define C0P 80
#define MTOT (B_*SPT*NS)      // 524288
#define NGRP (MTOT/NS)        // 8192
#define RR2 0.09f
#define EPSV 1e-5f

typedef unsigned long long ull;
typedef unsigned uint;

// ---------------- scratch (static device globals; no allocation) -------------
__device__ __align__(16) float g_ptsT[(size_t)B_*NPT*DD];       // 33.5 MB
__device__ __align__(16) float4 g_pk[(size_t)B_*NPT];           // 2 MB packed xyz+id
__device__ float g_newxyz[B_*SPT*3];
__device__ int   g_fpsidx[B_*SPT];
__device__ int   g_newptr[B_*SPT];
__device__ int   g_gid[B_*SPT*NS];
__device__ __align__(16) float g_x0[(size_t)MTOT*C0P];          // 168 MB
__device__ __align__(16) float g_y1[(size_t)MTOT*128];          // 268 MB
__device__ __align__(16) float g_y2[(size_t)MTOT*128];          // 268 MB
__device__ __align__(16) float g_mx[(size_t)NGRP*256];          // 8 MB
__device__ __align__(16) float g_mn[(size_t)NGRP*256];          // 8 MB
__device__ float g_sum[3*256];
__device__ float g_sqs[3*256];
__device__ float g_scale[3*256];
__device__ float g_shift[3*256];
// weights pre-split (bf16 hi/lo) and packed in m16n8k16 B-fragment layout
// layout: [otile][ksg][nb=16][lane=32][reg=2] packed u32 (2 bf16)
#define W0WORDS (5*1024)      // KP=80: 5 ksteps
#define W1WORDS (8*1024)      // KP=128
#define W2WORDS (2*8*1024)    // 2 otiles
__device__ __align__(16) uint g_wf0h[W0WORDS], g_wf0l[W0WORDS];
__device__ __align__(16) uint g_wf1h[W1WORDS], g_wf1l[W1WORDS];
__device__ __align__(16) uint g_wf2h[W2WORDS], g_wf2l[W2WORDS];

// ---------------- f32x2 packed helpers ---------------------------------------
#define ADD2(o, a, b) asm("add.rn.f32x2 %0, %1, %2;" : "=l"(o) : "l"(a), "l"(b))
#define MUL2(o, a, b) asm("mul.rn.f32x2 %0, %1, %2;" : "=l"(o) : "l"(a), "l"(b))
#define FMA2(o, a, b, c) asm("fma.rn.f32x2 %0, %1, %2, %3;" : "=l"(o) : "l"(a), "l"(b), "l"(c))

__device__ __forceinline__ ull bcast2(float v) {
    unsigned u = __float_as_uint(v);
    return ((ull)u << 32) | (ull)u;
}
__device__ __forceinline__ float lo2(ull m) { return __uint_as_float((unsigned)m); }
__device__ __forceinline__ float hi2(ull m) { return __uint_as_float((unsigned)(m >> 32)); }

// pack two floats to bf16x2 word: {lo half = a, hi half = b}
__device__ __forceinline__ uint pk_bf2(float a, float b) {
    uint r;
    asm("cvt.rn.bf16x2.f32 %0, %1, %2;" : "=r"(r) : "f"(b), "f"(a));
    return r;
}
// split pair (v0,v1) into hi word + lo word (residual)
__device__ __forceinline__ void split2(float v0, float v1, uint& wh, uint& wl) {
    wh = pk_bf2(v0, v1);
    __nv_bfloat162 h2 = *(__nv_bfloat162*)&wh;
    float h0 = __bfloat162float(h2.x), h1 = __bfloat162float(h2.y);
    wl = pk_bf2(v0 - h0, v1 - h1);
}

// ---------------- prep: zero stats, split+frag-pack weights, pack xyz --------
__global__ void prep_kernel(const float* __restrict__ w0,
                            const float* __restrict__ w1,
                            const float* __restrict__ w2,
                            const float* __restrict__ xyz,
                            const int* __restrict__ idx) {
    int i = blockIdx.x * 256 + threadIdx.x;
    if (i < 768) { g_sum[i] = 0.f; g_sqs[i] = 0.f; }
    // pack xyz+id (B*NPT = 131072 entries)
    if (i < B_*NPT) {
        int b = i >> 14, n = i & (NPT-1);
        const float* px = xyz + (size_t)b*3*NPT;
        g_pk[i] = make_float4(px[n], px[NPT+n], px[2*NPT+n], __int_as_float(idx[i]));
    }
    // weight fragments
    if (i >= W0WORDS + W1WORDS + W2WORDS) return;
    int layer, j, otile = 0;
    if (i < W0WORDS) { layer = 0; j = i; }
    else if (i < W0WORDS + W1WORDS) { layer = 1; j = i - W0WORDS; }
    else { layer = 2; j = i - W0WORDS - W1WORDS; otile = j >> 13; j &= 8191; }
    int reg = j & 1, lane = (j >> 1) & 31, nb = (j >> 6) & 15, ksg = j >> 10;
    int o  = otile*128 + nb*8 + (lane >> 2);
    int c0 = ksg*16 + reg*8 + (lane & 3)*2;
    float v0, v1;
    if (layer == 0) {
        int s0 = (c0   < 64) ? (c0   + 3) : (c0   - 64);
        int s1 = (c0+1 < 64) ? (c0+1 + 3) : (c0+1 - 64);
        v0 = (c0   < C0) ? w0[o*C0 + s0] : 0.f;
        v1 = (c0+1 < C0) ? w0[o*C0 + s1] : 0.f;
    } else if (layer == 1) {
        v0 = w1[o*128 + c0]; v1 = w1[o*128 + c0 + 1];
    } else {
        v0 = w2[o*128 + c0]; v1 = w2[o*128 + c0 + 1];
    }
    uint wh, wl;
    split2(v0, v1, wh, wl);
    if (layer == 0)      { g_wf0h[i] = wh; g_wf0l[i] = wl; }
    else if (layer == 1) { g_wf1h[j] = wh; g_wf1l[j] = wl; }
    else                 { int k = (otile << 13) | j; g_wf2h[k] = wh; g_wf2l[k] = wl; }
}

// ---------------- transpose points [B,64,N] -> [B,N,64] ----------------------
__global__ void transpose_kernel(const float* __restrict__ pts) {
    __shared__ float tile[32][33];
    int b = blockIdx.z;
    int n0 = blockIdx.x * 32, c0 = blockIdx.y * 32;
    int tx = threadIdx.x, ty = threadIdx.y;   // 32 x 8
    #pragma unroll
    for (int j = 0; j < 32; j += 8)
        tile[ty + j][tx] = pts[((size_t)b*DD + c0 + ty + j)*NPT + n0 + tx];
    __syncthreads();
    #pragma unroll
    for (int j = 0; j < 32; j += 8)
        g_ptsT[((size_t)b*NPT + n0 + ty + j)*DD + c0 + tx] = tile[tx][ty + j];
}

// ---------------- FPS: one CTA/batch, f32x2 math, deferred argmax index ------
#define FPS_SMEM ((3*NPT + 64) * 4)
__global__ void __launch_bounds__(512, 1)
fps_kernel(const float* __restrict__ xyz, const int* __restrict__ idx,
           float* __restrict__ out_xyz) {
    extern __shared__ float fsm[];
    float* sx = fsm;
    float* sy = sx + NPT;
    float* sz = sy + NPT;
    float* redv = sz + NPT;        // 16 used
    __shared__ int   s_idx[2];
    __shared__ float s_maxv;

    const int b = blockIdx.x, t = threadIdx.x;
    const float* px = xyz + (size_t)b*3*NPT;
    const float* py = px + NPT;
    const float* pz = py + NPT;

    for (int n = t; n < NPT; n += 512) { sx[n]=px[n]; sy[n]=py[n]; sz[n]=pz[n]; }
    if (t == 0) s_idx[0] = 0;
    __syncthreads();

    // thread t owns 16 point-pairs: pair p = t + i*512 -> points 2p, 2p+1
    ull xp[16], yp[16];
    float dist[32];
    #pragma unroll
    for (int i = 0; i < 16; i++) {
        int p = t + (i << 9);
        xp[i] = *(const ull*)&sx[2*p];
        yp[i] = *(const ull*)&sy[2*p];
        dist[2*i] = 1e10f; dist[2*i+1] = 1e10f;
    }

    for (int s = 0; s < SPT; s++) {
        int far = s_idx[s & 1];
        float cx = sx[far], cy = sy[far], cz = sz[far];
        if (t == 0) {
            g_fpsidx[b*SPT + s] = far;
            g_newptr[b*SPT + s] = idx[b*NPT + far];
            g_newxyz[(b*SPT + s)*3 + 0] = cx;
            g_newxyz[(b*SPT + s)*3 + 1] = cy;
            g_newxyz[(b*SPT + s)*3 + 2] = cz;
            out_xyz[(b*3 + 0)*SPT + s] = cx;
            out_xyz[(b*3 + 1)*SPT + s] = cy;
            out_xyz[(b*3 + 2)*SPT + s] = cz;
        }
        if (s == SPT - 1) break;

        ull ncx = bcast2(-cx), ncy = bcast2(-cy), ncz = bcast2(-cz);
        float best = -1.f;
        #pragma unroll
        for (int i = 0; i < 16; i++) {
            int p = t + (i << 9);
            ull z2 = *(const ull*)&sz[2*p];
            ull dx2, dy2, dz2, m;
            ADD2(dx2, xp[i], ncx);
            ADD2(dy2, yp[i], ncy);
            ADD2(dz2, z2,    ncz);
            MUL2(m, dx2, dx2);
            FMA2(m, dy2, dy2, m);
            FMA2(m, dz2, dz2, m);
            float d0 = fminf(dist[2*i],   lo2(m));
            float d1 = fminf(dist[2*i+1], hi2(m));
            dist[2*i] = d0; dist[2*i+1] = d1;
            best = fmaxf(best, d0);
            best = fmaxf(best, d1);
        }
        // value-only max reduction
        float wmax = best;
        #pragma unroll
        for (int o = 16; o > 0; o >>= 1)
            wmax = fmaxf(wmax, __shfl_xor_sync(0xffffffffu, wmax, o));
        if ((t & 31) == 0) redv[t >> 5] = wmax;
        __syncthreads();
        if (t < 32) {
            float v = (t < 16) ? redv[t] : -2.f;
            #pragma unroll
            for (int o = 8; o > 0; o >>= 1)
                v = fmaxf(v, __shfl_xor_sync(0xffffffffu, v, o));
            if (t == 0) { s_maxv = v; s_idx[(s + 1) & 1] = 0x7fffffff; }
        }
        __syncthreads();
        // deferred index recovery: only owner thread(s) rescan registers
        float vmax = s_maxv;
        if (best == vmax) {
            int found = 0x7fffffff;
            #pragma unroll
            for (int i = 0; i < 16; i++) {
                int p2 = 2*(t + (i << 9));
                if (dist[2*i]   == vmax) found = min(found, p2);
                if (dist[2*i+1] == vmax) found = min(found, p2 + 1);
            }
            atomicMin(&s_idx[(s + 1) & 1], found);
        }
        __syncthreads();
    }
}

// ---------------- ball query: one warp per (b,s), packed float4 --------------
__global__ void __launch_bounds__(256)
ballquery_kernel() {
    int warp = (blockIdx.x * blockDim.x + threadIdx.x) >> 5;
    int lane = threadIdx.x & 31;
    if (warp >= B_*SPT) return;
    int b = warp / SPT;
    float cx = g_newxyz[warp*3+0], cy = g_newxyz[warp*3+1], cz = g_newxyz[warp*3+2];
    int np = g_newptr[warp];
    float cn = cx*cx + cy*cy + cz*cz;
    const float4* pk = g_pk + (size_t)b*NPT;
    int* gout = g_gid + (size_t)warp*NS;

    int cnt = 0, first = -1;
    for (int n0 = 0; n0 < NPT && cnt < NS; n0 += 128) {
        float4 vv[4];
        #pragma unroll
        for (int sb = 0; sb < 4; sb++) vv[sb] = pk[n0 + sb*32 + lane];
        #pragma unroll
        for (int sb = 0; sb < 4; sb++) {
            int n = n0 + sb*32 + lane;
            float x = vv[sb].x, y = vv[sb].y, z = vv[sb].z;
            float pn = x*x + y*y + z*z;
            float sq = cn + pn - 2.f*(cx*x + cy*y + cz*z);
            bool hit = !(sq > RR2) && (__float_as_int(vv[sb].w) == np);
            unsigned m = __ballot_sync(0xffffffffu, hit);
            if (m) {
                if (first < 0) first = n0 + sb*32 + __ffs(m) - 1;
                int pos = cnt + __popc(m & ((1u << lane) - 1));
                if (hit && pos < NS) gout[pos] = n;
                cnt += __popc(m);
                if (cnt > NS) cnt = NS;
            }
        }
    }
    if (first < 0) { first = g_fpsidx[warp]; }
    if (cnt == 0) { if (lane == 0) gout[0] = first; cnt = 1; }
    for (int p = cnt + lane; p < NS; p += 32) gout[p] = first;
}

// ---------------- gather/concat -> X0 [M, 80] --------------------------------
__global__ void __launch_bounds__(256)
gather_kernel(const float* __restrict__ xyz) {
    int g16  = threadIdx.x >> 4;
    int lane = threadIdx.x & 15;
    size_t m = (size_t)blockIdx.x * 16 + g16;
    int bs = (int)(m >> 6);
    int b  = bs >> 10;
    int g  = g_gid[m];
    float4 v = *(const float4*)&g_ptsT[((size_t)b*NPT + g)*DD + lane*4];
    float* dst = g_x0 + m*C0P;
    *(float4*)&dst[lane*4] = v;
    if (lane == 0) {
        const float* px = xyz + (size_t)b*3*NPT;
        float cx = g_newxyz[bs*3+0], cy = g_newxyz[bs*3+1], cz = g_newxyz[bs*3+2];
        *(float4*)&dst[64] = make_float4(px[g]-cx, px[NPT+g]-cy, px[2*NPT+g]-cz, 0.f);
        *(float4*)&dst[68] = make_float4(0.f,0.f,0.f,0.f);
        *(float4*)&dst[72] = make_float4(0.f,0.f,0.f,0.f);
        *(float4*)&dst[76] = make_float4(0.f,0.f,0.f,0.f);
    }
}

// ---------------- bf16 mma helpers -------------------------------------------
#define MMAB(d, a, b) asm volatile( \
    "mma.sync.aligned.m16n8k16.row.col.f32.bf16.bf16.f32 " \
    "{%0,%1,%2,%3},{%4,%5,%6,%7},{%8,%9},{%0,%1,%2,%3};\n" \
    : "+f"(d[0]), "+f"(d[1]), "+f"(d[2]), "+f"(d[3]) \
    : "r"(a[0]), "r"(a[1]), "r"(a[2]), "r"(a[3]), "r"(b[0]), "r"(b[1]))

// ---------------- one K-chunk (<=64) : load A (split), copy W, mma -----------
template<int KS16, int LAYER>
__device__ __forceinline__ void do_chunk(
    const float* __restrict__ A, size_t m0, int kc,
    const float* __restrict__ sc, const float* __restrict__ sh,
    const uint* __restrict__ Wfh, const uint* __restrict__ Wfl, int wfbase,
    uint* Ah, uint* Al, uint* Bh, uint* Bl,
    int t, int lane, int w, int wc, float acc[2][8][4])
{
    constexpr int KP = (LAYER == 0) ? C0P : 128;
    constexpr int CW = KS16 * 4;          // float4 per row this chunk

    // A: 128 rows x KS16*16 cols
    for (int i = t; i < 128*CW; i += 256) {
        int r = i / CW, c4 = i - r*CW;
        float4 v = *(const float4*)&A[(m0 + r)*KP + kc + c4*4];
        if (LAYER > 0) {
            int ch = kc + c4*4;
            v.x = fmaxf(0.f, fmaf(sc[ch+0], v.x, sh[ch+0]));
            v.y = fmaxf(0.f, fmaf(sc[ch+1], v.y, sh[ch+1]));
            v.z = fmaxf(0.f, fmaf(sc[ch+2], v.z, sh[ch+2]));
            v.w = fmaxf(0.f, fmaf(sc[ch+3], v.w, sh[ch+3]));
        }
        int r16 = r & 15, mb = r >> 4;
        int kk0 = (c4*4) & 15, kst = (c4*4) >> 4;
        int reg = (r16 >> 3) + ((kk0 >> 3) << 1);
        int l0  = ((r16 & 7) << 2) | ((kk0 >> 1) & 3);
        int i0  = ((kst*8 + mb)*32 + l0)*4 + reg;
        uint wh, wl;
        split2(v.x, v.y, wh, wl);
        Ah[i0] = wh; Al[i0] = wl;
        split2(v.z, v.w, wh, wl);
        Ah[i0 + 4] = wh; Al[i0 + 4] = wl;    // pair at kk0+2 -> lane+1
    }
    // B: straight copy of pre-packed fragments
    {
        const uint4* shp = (const uint4*)(Wfh + wfbase);
        const uint4* slp = (const uint4*)(Wfl + wfbase);
        for (int i = t; i < KS16*256; i += 256) {
            ((uint4*)Bh)[i] = shp[i];
            ((uint4*)Bl)[i] = slp[i];
        }
    }
    __syncthreads();

    #pragma unroll
    for (int kstep = 0; kstep < KS16; kstep++) {
        uint ah[2][4], al[2][4];
        #pragma unroll
        for (int mb = 0; mb < 2; mb++) {
            int base = ((kstep*8 + (w & 3)*2 + mb)*32 + lane)*4;
            uint4 vh = *(const uint4*)&Ah[base];
            uint4 vl = *(const uint4*)&Al[base];
            ah[mb][0]=vh.x; ah[mb][1]=vh.y; ah[mb][2]=vh.z; ah[mb][3]=vh.w;
            al[mb][0]=vl.x; al[mb][1]=vl.y; al[mb][2]=vl.z; al[mb][3]=vl.w;
        }
        #pragma unroll
        for (int nf = 0; nf < 8; nf++) {
            int baseb = ((kstep*16 + (wc >> 3) + nf)*32 + lane)*2;
            uint2 bhv = *(const uint2*)&Bh[baseb];
            uint2 blv = *(const uint2*)&Bl[baseb];
            uint bh[2] = {bhv.x, bhv.y};
            uint bl[2] = {blv.x, blv.y};
            #pragma unroll
            for (int mb = 0; mb < 2; mb++) {
                MMAB(acc[mb][nf], ah[mb], bh);
                MMAB(acc[mb][nf], al[mb], bh);
                MMAB(acc[mb][nf], ah[mb], bl);
            }
        }
    }
    __syncthreads();
}

// ---------------- bf16x3 GEMM: Y = act(A) * W^T, fused stats (+pool L2) ------
template<int LAYER>
__global__ void __launch_bounds__(256, 2)
gemm_tc() {
    const float* A = (LAYER == 0) ? g_x0 : ((LAYER == 1) ? g_y1 : g_y2);
    float*       Y = (LAYER == 0) ? g_y1 : g_y2;
    const uint* Wfh = (LAYER == 0) ? g_wf0h : ((LAYER == 1) ? g_wf1h : g_wf2h);
    const uint* Wfl = (LAYER == 0) ? g_wf0l : ((LAYER == 1) ? g_wf1l : g_wf2l);
    const float* sc = g_scale + ((LAYER > 0) ? (LAYER - 1)*256 : 0);
    const float* sh = g_shift + ((LAYER > 0) ? (LAYER - 1)*256 : 0);

    extern __shared__ uint usm[];
    uint* Ah = usm;              // 4096 each
    uint* Al = usm + 4096;
    uint* Bh = usm + 8192;
    uint* Bl = usm + 12288;

    const int t = threadIdx.x;
    const int lane = t & 31, w = t >> 5;
    const int wr = (w & 3) * 32, wc = (w >> 2) * 64;
    const size_t m0 = (size_t)blockIdx.x * 128;
    const int o0 = blockIdx.y * 128;
    const int otile = blockIdx.y;

    float acc[2][8][4];
    #pragma unroll
    for (int mb = 0; mb < 2; mb++)
        #pragma unroll
        for (int nf = 0; nf < 8; nf++)
            #pragma unroll
            for (int c = 0; c < 4; c++) acc[mb][nf][c] = 0.f;

    int wb0 = (LAYER == 2) ? (otile*8)*1024 : 0;
    do_chunk<4, LAYER>(A, m0, 0, sc, sh, Wfh, Wfl, wb0, Ah, Al, Bh, Bl, t, lane, w, wc, acc);
    if (LAYER == 0)
        do_chunk<1, LAYER>(A, m0, 64, sc, sh, Wfh, Wfl, 4*1024, Ah, Al, Bh, Bl, t, lane, w, wc, acc);
    else
        do_chunk<4, LAYER>(A, m0, 64, sc, sh, Wfh, Wfl, wb0 + 4*1024, Ah, Al, Bh, Bl, t, lane, w, wc, acc);

    // ---- epilogue: store Y (layers 0,1) ----
    if (LAYER < 2) {
        #pragma unroll
        for (int mb = 0; mb < 2; mb++)
            #pragma unroll
            for (int h = 0; h < 2; h++) {
                size_t row = m0 + wr + mb*16 + (lane >> 2) + h*8;
                float* yr = &Y[row*128 + wc + (lane & 3)*2];
                #pragma unroll
                for (int nf = 0; nf < 8; nf++)
                    *(float2*)&yr[nf*8] = make_float2(acc[mb][nf][h*2], acc[mb][nf][h*2+1]);
            }
    }

    // ---- per-column partial stats, and max/min for LAYER 2 ----
    float csum[8][2], csq[8][2];
    #pragma unroll
    for (int nf = 0; nf < 8; nf++)
        #pragma unroll
        for (int j = 0; j < 2; j++) { csum[nf][j] = 0.f; csq[nf][j] = 0.f; }
    float cmx[8][2], cmn[8][2];
    if (LAYER == 2) {
        #pragma unroll
        for (int nf = 0; nf < 8; nf++)
            #pragma unroll
            for (int j = 0; j < 2; j++) { cmx[nf][j] = -3.4e38f; cmn[nf][j] = 3.4e38f; }
    }
    #pragma unroll
    for (int mb = 0; mb < 2; mb++)
        #pragma unroll
        for (int nf = 0; nf < 8; nf++)
            #pragma unroll
            for (int c = 0; c < 4; c++) {
                int j = c & 1;
                float v = acc[mb][nf][c];
                csum[nf][j] += v;
                csq[nf][j] = fmaf(v, v, csq[nf][j]);
                if (LAYER == 2) {
                    cmx[nf][j] = fmaxf(cmx[nf][j], v);
                    cmn[nf][j] = fminf(cmn[nf][j], v);
                }
            }

    float* red = (float*)usm;   // [4][128]
    #pragma unroll
    for (int nf = 0; nf < 8; nf++)
        #pragma unroll
        for (int j = 0; j < 2; j++) {
            float v = csum[nf][j];
            #pragma unroll
            for (int o = 4; o < 32; o <<= 1) v += __shfl_xor_sync(0xffffffffu, v, o);
            if (lane < 4) red[(w & 3)*128 + wc + nf*8 + lane*2 + j] = v;
        }
    __syncthreads();
    if (t < 128) {
        float s = red[t] + red[128 + t] + red[256 + t] + red[384 + t];
        atomicAdd(&g_sum[LAYER*256 + o0 + t], s);
    }
    __syncthreads();
    #pragma unroll
    for (int nf = 0; nf < 8; nf++)
        #pragma unroll
        for (int j = 0; j < 2; j++) {
            float v = csq[nf][j];
            #pragma unroll
            for (int o = 4; o < 32; o <<= 1) v += __shfl_xor_sync(0xffffffffu, v, o);
            if (lane < 4) red[(w & 3)*128 + wc + nf*8 + lane*2 + j] = v;
        }
    __syncthreads();
    if (t < 128) {
        float s = red[t] + red[128 + t] + red[256 + t] + red[384 + t];
        atomicAdd(&g_sqs[LAYER*256 + o0 + t], s);
    }

    if (LAYER == 2) {
        __syncthreads();
        #pragma unroll
        for (int nf = 0; nf < 8; nf++)
            #pragma unroll
            for (int j = 0; j < 2; j++) {
                float v = cmx[nf][j];
                #pragma unroll
                for (int o = 4; o < 32; o <<= 1) v = fmaxf(v, __shfl_xor_sync(0xffffffffu, v, o));
                if (lane < 4) red[(w & 3)*128 + wc + nf*8 + lane*2 + j] = v;
            }
        __syncthreads();
        if (t < 256) {
            int g = t >> 7, col = t & 127;
            float v = fmaxf(red[(2*g)*128 + col], red[(2*g + 1)*128 + col]);
            g_mx[((size_t)(2*blockIdx.x + g))*256 + o0 + col] = v;
        }
        __syncthreads();
        #pragma unroll
        for (int nf = 0; nf < 8; nf++)
            #pragma unroll
            for (int j = 0; j < 2; j++) {
                float v = cmn[nf][j];
                #pragma unroll
                for (int o = 4; o < 32; o <<= 1) v = fminf(v, __shfl_xor_sync(0xffffffffu, v, o));
                if (lane < 4) red[(w & 3)*128 + wc + nf*8 + lane*2 + j] = v;
            }
        __syncthreads();
        if (t < 256) {
            int g = t >> 7, col = t & 127;
            float v = fminf(red[(2*g)*128 + col], red[(2*g + 1)*128 + col]);
            g_mn[((size_t)(2*blockIdx.x + g))*256 + o0 + col] = v;
        }
    }
}

// ---------------- BN finalize ------------------------------------------------
__global__ void finalize_kernel(const float* __restrict__ gamma,
                                const float* __restrict__ beta,
                                int layer, int O) {
    int t = threadIdx.x;
    if (t < O) {
        const float invM = 1.f / (float)MTOT;
        float mu  = g_sum[layer*256 + t] * invM;
        float var = g_sqs[layer*256 + t] * invM - mu*mu;
        if (var < 0.f) var = 0.f;
        float s = gamma[t] * rsqrtf(var + EPSV);
        g_scale[layer*256 + t] = s;
        g_shift[layer*256 + t] = fmaf(-mu, s, beta[t]);
    }
}

// ---------------- final: BN3 + relu on pooled extremum, transpose out --------
__global__ void final_out_kernel(float* __restrict__ out_feat) {
    __shared__ float tile[32][33];
    int bs0 = blockIdx.x * 32, c0 = blockIdx.y * 32;
    int tx = threadIdx.x, ty = threadIdx.y;   // 32 x 8
    float s  = g_scale[512 + c0 + tx];
    float shv = g_shift[512 + c0 + tx];
    #pragma unroll
    for (int j = 0; j < 32; j += 8) {
        int bs = bs0 + ty + j;
        float mx = g_mx[(size_t)bs*256 + c0 + tx];
        float mn = g_mn[(size_t)bs*256 + c0 + tx];
        float e = (s >= 0.f) ? mx : mn;
        tile[ty + j][tx] = fmaxf(0.f, fmaf(s, e, shv));
    }
    __syncthreads();
    int b = bs0 >> 10, sl = bs0 & 1023;
    #pragma unroll
    for (int j = 0; j < 32; j += 8)
        out_feat[((size_t)(b*256 + c0 + ty + j))*1024 + sl + tx] = tile[tx][ty + j];
}

// ---------------- launcher ---------------------------------------------------
extern "C" void kernel_launch(void* const* d_in, const int* in_sizes, int n_in,
                              void* d_out, int out_size) {
    const float* xyz = (const float*)d_in[0];
    const float* pts = (const float*)d_in[1];
    const int*   idx = (const int*)d_in[2];
    const float* w0  = (const float*)d_in[3];
    const float* g0  = (const float*)d_in[5];
    const float* be0 = (const float*)d_in[6];
    const float* w1  = (const float*)d_in[7];
    const float* g1  = (const float*)d_in[9];
    const float* be1 = (const float*)d_in[10];
    const float* w2  = (const float*)d_in[11];
    const float* g2  = (const float*)d_in[13];
    const float* be2 = (const float*)d_in[14];

    float* out      = (float*)d_out;
    float* out_xyz  = out;                       // [B,3,SPT]
    float* out_feat = out + (size_t)B_*3*SPT;    // [B,256,SPT]

    const int GSM = 16384 * 4;   // 64 KB

    cudaFuncSetAttribute(fps_kernel, cudaFuncAttributeMaxDynamicSharedMemorySize, FPS_SMEM);
    cudaFuncSetAttribute(gemm_tc<0>, cudaFuncAttributeMaxDynamicSharedMemorySize, GSM);
    cudaFuncSetAttribute(gemm_tc<1>, cudaFuncAttributeMaxDynamicSharedMemorySize, GSM);
    cudaFuncSetAttribute(gemm_tc<2>, cudaFuncAttributeMaxDynamicSharedMemorySize, GSM);

    prep_kernel<<<(B_*NPT + 255)/256, 256>>>(w0, w1, w2, xyz, idx);
    transpose_kernel<<<dim3(NPT/32, DD/32, B_), dim3(32, 8)>>>(pts);
    fps_kernel<<<B_, 512, FPS_SMEM>>>(xyz, idx, out_xyz);
    ballquery_kernel<<<(B_*SPT)/8, 256>>>();
    gather_kernel<<<MTOT/16, 256>>>(xyz);

    gemm_tc<0><<<dim3(MTOT/128, 1), 256, GSM>>>();
    finalize_kernel<<<1, 256>>>(g0, be0, 0, 128);
    gemm_tc<1><<<dim3(MTOT/128, 1), 256, GSM>>>();
    finalize_kernel<<<1, 256>>>(g1, be1, 1, 128);
    gemm_tc<2><<<dim3(MTOT/128, 2), 256, GSM>>>();
    finalize_kernel<<<1, 256>>>(g2, be2, 2, 256);

    final_out_kernel<<<dim3(NGRP/32, 256/32), dim3(32, 8)>>>(out_feat);
}

// round 9
// speedup vs baseline: 2.5512x; 1.0517x over previous
#include <cuda_runtime.h>
#include <cuda_bf16.h>
#include <math.h>

#define B_ 8
#define NPT 16384
#define SPT 1024
#define NS 64
#define DD 64
#define C0 67
#define C0P 80
#define MTOT (B_*SPT*NS)      // 524288
#define NGRP (MTOT/NS)        // 8192
#define RR2 0.09f
#define EPSV 1e-5f

typedef unsigned long long ull;
typedef unsigned uint;

// ---------------- scratch (static device globals; no allocation) -------------
__device__ __align__(16) float g_ptsT[(size_t)B_*NPT*DD];       // 33.5 MB
__device__ __align__(16) float4 g_pk[(size_t)B_*NPT];           // 2 MB packed xyz+id
__device__ float g_newxyz[B_*SPT*3];
__device__ int   g_fpsidx[B_*SPT];
__device__ int   g_newptr[B_*SPT];
__device__ int   g_gid[B_*SPT*NS];
__device__ __align__(16) float g_y1[(size_t)MTOT*128];          // 268 MB
__device__ __align__(16) float g_y2[(size_t)MTOT*128];          // 268 MB
__device__ __align__(16) float g_mx[(size_t)NGRP*256];          // 8 MB
__device__ __align__(16) float g_mn[(size_t)NGRP*256];          // 8 MB
__device__ float g_sum[3*256];
__device__ float g_sqs[3*256];
__device__ float g_scale[3*256];
__device__ float g_shift[3*256];
// weights pre-split (bf16 hi/lo) and packed in m16n8k16 B-fragment layout
#define W0WORDS (5*1024)      // KP=80: 5 ksteps
#define W1WORDS (8*1024)      // KP=128
#define W2WORDS (2*8*1024)    // 2 otiles
__device__ __align__(16) uint g_wf0h[W0WORDS], g_wf0l[W0WORDS];
__device__ __align__(16) uint g_wf1h[W1WORDS], g_wf1l[W1WORDS];
__device__ __align__(16) uint g_wf2h[W2WORDS], g_wf2l[W2WORDS];

// ---------------- f32x2 packed helpers ---------------------------------------
#define ADD2(o, a, b) asm("add.rn.f32x2 %0, %1, %2;" : "=l"(o) : "l"(a), "l"(b))
#define MUL2(o, a, b) asm("mul.rn.f32x2 %0, %1, %2;" : "=l"(o) : "l"(a), "l"(b))
#define FMA2(o, a, b, c) asm("fma.rn.f32x2 %0, %1, %2, %3;" : "=l"(o) : "l"(a), "l"(b), "l"(c))

__device__ __forceinline__ ull bcast2(float v) {
    unsigned u = __float_as_uint(v);
    return ((ull)u << 32) | (ull)u;
}
__device__ __forceinline__ float lo2(ull m) { return __uint_as_float((unsigned)m); }
__device__ __forceinline__ float hi2(ull m) { return __uint_as_float((unsigned)(m >> 32)); }

// pack two floats to bf16x2 word: {lo half = a, hi half = b}
__device__ __forceinline__ uint pk_bf2(float a, float b) {
    uint r;
    asm("cvt.rn.bf16x2.f32 %0, %1, %2;" : "=r"(r) : "f"(b), "f"(a));
    return r;
}
// split pair (v0,v1) into hi word + lo word (residual)
__device__ __forceinline__ void split2(float v0, float v1, uint& wh, uint& wl) {
    wh = pk_bf2(v0, v1);
    __nv_bfloat162 h2 = *(__nv_bfloat162*)&wh;
    float h0 = __bfloat162float(h2.x), h1 = __bfloat162float(h2.y);
    wl = pk_bf2(v0 - h0, v1 - h1);
}

// store float4 (row r, chunk-local col base kk0 = c4*4) into A frag smem
__device__ __forceinline__ void frag_store4(uint* Ah, uint* Al, int r, int c4, float4 v) {
    int r16 = r & 15, mb = r >> 4;
    int kk0 = (c4*4) & 15, kst = (c4*4) >> 4;
    int reg = (r16 >> 3) + ((kk0 >> 3) << 1);
    int l0  = ((r16 & 7) << 2) | ((kk0 >> 1) & 3);
    int i0  = ((kst*8 + mb)*32 + l0)*4 + reg;
    uint wh, wl;
    split2(v.x, v.y, wh, wl);
    Ah[i0] = wh; Al[i0] = wl;
    split2(v.z, v.w, wh, wl);
    Ah[i0 + 4] = wh; Al[i0 + 4] = wl;
}

// ---------------- prep: zero stats, split+frag-pack weights, pack xyz --------
__global__ void prep_kernel(const float* __restrict__ w0,
                            const float* __restrict__ w1,
                            const float* __restrict__ w2,
                            const float* __restrict__ xyz,
                            const int* __restrict__ idx) {
    int i = blockIdx.x * 256 + threadIdx.x;
    if (i < 768) { g_sum[i] = 0.f; g_sqs[i] = 0.f; }
    if (i < B_*NPT) {
        int b = i >> 14, n = i & (NPT-1);
        const float* px = xyz + (size_t)b*3*NPT;
        g_pk[i] = make_float4(px[n], px[NPT+n], px[2*NPT+n], __int_as_float(idx[i]));
    }
    if (i >= W0WORDS + W1WORDS + W2WORDS) return;
    int layer, j, otile = 0;
    if (i < W0WORDS) { layer = 0; j = i; }
    else if (i < W0WORDS + W1WORDS) { layer = 1; j = i - W0WORDS; }
    else { layer = 2; j = i - W0WORDS - W1WORDS; otile = j >> 13; j &= 8191; }
    int reg = j & 1, lane = (j >> 1) & 31, nb = (j >> 6) & 15, ksg = j >> 10;
    int o  = otile*128 + nb*8 + (lane >> 2);
    int c0 = ksg*16 + reg*8 + (lane & 3)*2;
    float v0, v1;
    if (layer == 0) {
        int s0 = (c0   < 64) ? (c0   + 3) : (c0   - 64);
        int s1 = (c0+1 < 64) ? (c0+1 + 3) : (c0+1 - 64);
        v0 = (c0   < C0) ? w0[o*C0 + s0] : 0.f;
        v1 = (c0+1 < C0) ? w0[o*C0 + s1] : 0.f;
    } else if (layer == 1) {
        v0 = w1[o*128 + c0]; v1 = w1[o*128 + c0 + 1];
    } else {
        v0 = w2[o*128 + c0]; v1 = w2[o*128 + c0 + 1];
    }
    uint wh, wl;
    split2(v0, v1, wh, wl);
    if (layer == 0)      { g_wf0h[i] = wh; g_wf0l[i] = wl; }
    else if (layer == 1) { g_wf1h[j] = wh; g_wf1l[j] = wl; }
    else                 { int k = (otile << 13) | j; g_wf2h[k] = wh; g_wf2l[k] = wl; }
}

// ---------------- transpose points [B,64,N] -> [B,N,64] ----------------------
__global__ void transpose_kernel(const float* __restrict__ pts) {
    __shared__ float tile[32][33];
    int b = blockIdx.z;
    int n0 = blockIdx.x * 32, c0 = blockIdx.y * 32;
    int tx = threadIdx.x, ty = threadIdx.y;   // 32 x 8
    #pragma unroll
    for (int j = 0; j < 32; j += 8)
        tile[ty + j][tx] = pts[((size_t)b*DD + c0 + ty + j)*NPT + n0 + tx];
    __syncthreads();
    #pragma unroll
    for (int j = 0; j < 32; j += 8)
        g_ptsT[((size_t)b*NPT + n0 + ty + j)*DD + c0 + tx] = tile[tx][ty + j];
}

// ---------------- FPS: one CTA/batch, f32x2 math, 2 syncs/step ---------------
#define FPS_SMEM ((3*NPT + 64) * 4)
__global__ void __launch_bounds__(512, 1)
fps_kernel(const float* __restrict__ xyz, const int* __restrict__ idx,
           float* __restrict__ out_xyz) {
    extern __shared__ float fsm[];
    float* sx = fsm;
    float* sy = sx + NPT;
    float* sz = sy + NPT;
    float* redv = sz + NPT;        // 16 used
    __shared__ int s_idx[2];

    const int b = blockIdx.x, t = threadIdx.x;
    const float* px = xyz + (size_t)b*3*NPT;
    const float* py = px + NPT;
    const float* pz = py + NPT;

    for (int n = t; n < NPT; n += 512) { sx[n]=px[n]; sy[n]=py[n]; sz[n]=pz[n]; }
    if (t == 0) s_idx[0] = 0;
    __syncthreads();

    ull xp[16], yp[16];
    float dist[32];
    #pragma unroll
    for (int i = 0; i < 16; i++) {
        int p = t + (i << 9);
        xp[i] = *(const ull*)&sx[2*p];
        yp[i] = *(const ull*)&sy[2*p];
        dist[2*i] = 1e10f; dist[2*i+1] = 1e10f;
    }

    const int lane = t & 31;
    for (int s = 0; s < SPT; s++) {
        int far = s_idx[s & 1];
        float cx = sx[far], cy = sy[far], cz = sz[far];
        if (t == 0) {
            g_fpsidx[b*SPT + s] = far;
            g_newptr[b*SPT + s] = idx[b*NPT + far];
            g_newxyz[(b*SPT + s)*3 + 0] = cx;
            g_newxyz[(b*SPT + s)*3 + 1] = cy;
            g_newxyz[(b*SPT + s)*3 + 2] = cz;
            out_xyz[(b*3 + 0)*SPT + s] = cx;
            out_xyz[(b*3 + 1)*SPT + s] = cy;
            out_xyz[(b*3 + 2)*SPT + s] = cz;
            s_idx[(s + 1) & 1] = 0x7fffffff;   // reset next slot (diff slot, safe)
        }
        if (s == SPT - 1) break;

        ull ncx = bcast2(-cx), ncy = bcast2(-cy), ncz = bcast2(-cz);
        float best = -1.f;
        #pragma unroll
        for (int i = 0; i < 16; i++) {
            int p = t + (i << 9);
            ull z2 = *(const ull*)&sz[2*p];
            ull dx2, dy2, dz2, m;
            ADD2(dx2, xp[i], ncx);
            ADD2(dy2, yp[i], ncy);
            ADD2(dz2, z2,    ncz);
            MUL2(m, dx2, dx2);
            FMA2(m, dy2, dy2, m);
            FMA2(m, dz2, dz2, m);
            float d0 = fminf(dist[2*i],   lo2(m));
            float d1 = fminf(dist[2*i+1], hi2(m));
            dist[2*i] = d0; dist[2*i+1] = d1;
            best = fmaxf(best, d0);
            best = fmaxf(best, d1);
        }
        // warp max
        float wmax = best;
        #pragma unroll
        for (int o = 16; o > 0; o >>= 1)
            wmax = fmaxf(wmax, __shfl_xor_sync(0xffffffffu, wmax, o));
        if (lane == 0) redv[t >> 5] = wmax;
        __syncthreads();
        // every warp redundantly reduces the 16 partials -> all know vmax
        float vmax = redv[lane & 15];
        #pragma unroll
        for (int o = 8; o > 0; o >>= 1)
            vmax = fmaxf(vmax, __shfl_xor_sync(0xffffffffu, vmax, o));
        // deferred index recovery
        if (best == vmax) {
            int found = 0x7fffffff;
            #pragma unroll
            for (int i = 0; i < 16; i++) {
                int p2 = 2*(t + (i << 9));
                if (dist[2*i]   == vmax) found = min(found, p2);
                if (dist[2*i+1] == vmax) found = min(found, p2 + 1);
            }
            atomicMin(&s_idx[(s + 1) & 1], found);
        }
        __syncthreads();
    }
}

// ---------------- ball query: one warp per (b,s), packed float4 --------------
__global__ void __launch_bounds__(256)
ballquery_kernel() {
    int warp = (blockIdx.x * blockDim.x + threadIdx.x) >> 5;
    int lane = threadIdx.x & 31;
    if (warp >= B_*SPT) return;
    int b = warp / SPT;
    float cx = g_newxyz[warp*3+0], cy = g_newxyz[warp*3+1], cz = g_newxyz[warp*3+2];
    int np = g_newptr[warp];
    float cn = cx*cx + cy*cy + cz*cz;
    const float4* pk = g_pk + (size_t)b*NPT;
    int* gout = g_gid + (size_t)warp*NS;

    int cnt = 0, first = -1;
    for (int n0 = 0; n0 < NPT && cnt < NS; n0 += 128) {
        float4 vv[4];
        #pragma unroll
        for (int sb = 0; sb < 4; sb++) vv[sb] = pk[n0 + sb*32 + lane];
        #pragma unroll
        for (int sb = 0; sb < 4; sb++) {
            int n = n0 + sb*32 + lane;
            float x = vv[sb].x, y = vv[sb].y, z = vv[sb].z;
            float pn = x*x + y*y + z*z;
            float sq = cn + pn - 2.f*(cx*x + cy*y + cz*z);
            bool hit = !(sq > RR2) && (__float_as_int(vv[sb].w) == np);
            unsigned m = __ballot_sync(0xffffffffu, hit);
            if (m) {
                if (first < 0) first = n0 + sb*32 + __ffs(m) - 1;
                int pos = cnt + __popc(m & ((1u << lane) - 1));
                if (hit && pos < NS) gout[pos] = n;
                cnt += __popc(m);
                if (cnt > NS) cnt = NS;
            }
        }
    }
    if (first < 0) { first = g_fpsidx[warp]; }
    if (cnt == 0) { if (lane == 0) gout[0] = first; cnt = 1; }
    for (int p = cnt + lane; p < NS; p += 32) gout[p] = first;
}

// ---------------- bf16 mma helpers -------------------------------------------
#define MMAB(d, a, b) asm volatile( \
    "mma.sync.aligned.m16n8k16.row.col.f32.bf16.bf16.f32 " \
    "{%0,%1,%2,%3},{%4,%5,%6,%7},{%8,%9},{%0,%1,%2,%3};\n" \
    : "+f"(d[0]), "+f"(d[1]), "+f"(d[2]), "+f"(d[3]) \
    : "r"(a[0]), "r"(a[1]), "r"(a[2]), "r"(a[3]), "r"(b[0]), "r"(b[1]))

// ---------------- one K-chunk : load A (split / gather for L0), copy W, mma --
template<int KS16, int LAYER>
__device__ __forceinline__ void do_chunk(
    const float* __restrict__ A, const float* __restrict__ xyz, size_t m0, int kc,
    const float* __restrict__ sc, const float* __restrict__ sh,
    const uint* __restrict__ Wfh, const uint* __restrict__ Wfl, int wfbase,
    uint* Ah, uint* Al, uint* Bh, uint* Bl,
    int t, int lane, int w, int wc, float acc[2][8][4])
{
    constexpr int KP = 128;               // layers 1,2 row stride
    constexpr int CW = KS16 * 4;          // float4 per row this chunk

    if (LAYER == 0) {
        const int bb = (int)(m0 >> 16);
        if (KS16 == 4) {
            // cols 0..63: gather ptsT rows via gid
            for (int i = t; i < 128*16; i += 256) {
                int r = i >> 4, c4 = i & 15;
                int g = g_gid[m0 + r];
                float4 v = *(const float4*)&g_ptsT[((size_t)bb*NPT + g)*DD + c4*4];
                frag_store4(Ah, Al, r, c4, v);
            }
        } else {
            // cols 64..79: dxyz + zero pad
            const float* px = xyz + (size_t)bb*3*NPT;
            for (int i = t; i < 128*4; i += 256) {
                int r = i >> 2, c4 = i & 3;
                float4 v = make_float4(0.f, 0.f, 0.f, 0.f);
                if (c4 == 0) {
                    int g = g_gid[m0 + r];
                    int bs = (int)((m0 + r) >> 6);
                    v = make_float4(px[g]        - g_newxyz[bs*3+0],
                                    px[NPT+g]    - g_newxyz[bs*3+1],
                                    px[2*NPT+g]  - g_newxyz[bs*3+2], 0.f);
                }
                frag_store4(Ah, Al, r, c4, v);
            }
        }
    } else {
        for (int i = t; i < 128*CW; i += 256) {
            int r = i / CW, c4 = i - r*CW;
            float4 v = *(const float4*)&A[(m0 + r)*KP + kc + c4*4];
            int ch = kc + c4*4;
            v.x = fmaxf(0.f, fmaf(sc[ch+0], v.x, sh[ch+0]));
            v.y = fmaxf(0.f, fmaf(sc[ch+1], v.y, sh[ch+1]));
            v.z = fmaxf(0.f, fmaf(sc[ch+2], v.z, sh[ch+2]));
            v.w = fmaxf(0.f, fmaf(sc[ch+3], v.w, sh[ch+3]));
            frag_store4(Ah, Al, r, c4, v);
        }
    }
    // B: straight copy of pre-packed fragments
    {
        const uint4* shp = (const uint4*)(Wfh + wfbase);
        const uint4* slp = (const uint4*)(Wfl + wfbase);
        for (int i = t; i < KS16*256; i += 256) {
            ((uint4*)Bh)[i] = shp[i];
            ((uint4*)Bl)[i] = slp[i];
        }
    }
    __syncthreads();

    #pragma unroll
    for (int kstep = 0; kstep < KS16; kstep++) {
        uint ah[2][4], al[2][4];
        #pragma unroll
        for (int mb = 0; mb < 2; mb++) {
            int base = ((kstep*8 + (w & 3)*2 + mb)*32 + lane)*4;
            uint4 vh = *(const uint4*)&Ah[base];
            uint4 vl = *(const uint4*)&Al[base];
            ah[mb][0]=vh.x; ah[mb][1]=vh.y; ah[mb][2]=vh.z; ah[mb][3]=vh.w;
            al[mb][0]=vl.x; al[mb][1]=vl.y; al[mb][2]=vl.z; al[mb][3]=vl.w;
        }
        #pragma unroll
        for (int nf = 0; nf < 8; nf++) {
            int baseb = ((kstep*16 + (wc >> 3) + nf)*32 + lane)*2;
            uint2 bhv = *(const uint2*)&Bh[baseb];
            uint2 blv = *(const uint2*)&Bl[baseb];
            uint bh[2] = {bhv.x, bhv.y};
            uint bl[2] = {blv.x, blv.y};
            #pragma unroll
            for (int mb = 0; mb < 2; mb++) {
                MMAB(acc[mb][nf], ah[mb], bh);
                MMAB(acc[mb][nf], al[mb], bh);
                MMAB(acc[mb][nf], ah[mb], bl);
            }
        }
    }
    __syncthreads();
}

// ---------------- bf16x3 GEMM: Y = act(A) * W^T, fused stats (+pool L2) ------
template<int LAYER>
__global__ void __launch_bounds__(256, 2)
gemm_tc(const float* __restrict__ xyz) {
    const float* A = (LAYER == 1) ? g_y1 : g_y2;   // unused for LAYER==0
    float*       Y = (LAYER == 0) ? g_y1 : g_y2;
    const uint* Wfh = (LAYER == 0) ? g_wf0h : ((LAYER == 1) ? g_wf1h : g_wf2h);
    const uint* Wfl = (LAYER == 0) ? g_wf0l : ((LAYER == 1) ? g_wf1l : g_wf2l);
    const float* sc = g_scale + ((LAYER > 0) ? (LAYER - 1)*256 : 0);
    const float* sh = g_shift + ((LAYER > 0) ? (LAYER - 1)*256 : 0);

    extern __shared__ uint usm[];
    uint* Ah = usm;              // 4096 each
    uint* Al = usm + 4096;
    uint* Bh = usm + 8192;
    uint* Bl = usm + 12288;

    const int t = threadIdx.x;
    const int lane = t & 31, w = t >> 5;
    const int wr = (w & 3) * 32, wc = (w >> 2) * 64;
    const size_t m0 = (size_t)blockIdx.x * 128;
    const int o0 = blockIdx.y * 128;
    const int otile = blockIdx.y;

    float acc[2][8][4];
    #pragma unroll
    for (int mb = 0; mb < 2; mb++)
        #pragma unroll
        for (int nf = 0; nf < 8; nf++)
            #pragma unroll
            for (int c = 0; c < 4; c++) acc[mb][nf][c] = 0.f;

    int wb0 = (LAYER == 2) ? (otile*8)*1024 : 0;
    do_chunk<4, LAYER>(A, xyz, m0, 0, sc, sh, Wfh, Wfl, wb0, Ah, Al, Bh, Bl, t, lane, w, wc, acc);
    if (LAYER == 0)
        do_chunk<1, LAYER>(A, xyz, m0, 64, sc, sh, Wfh, Wfl, 4*1024, Ah, Al, Bh, Bl, t, lane, w, wc, acc);
    else
        do_chunk<4, LAYER>(A, xyz, m0, 64, sc, sh, Wfh, Wfl, wb0 + 4*1024, Ah, Al, Bh, Bl, t, lane, w, wc, acc);

    // ---- epilogue: store Y (layers 0,1) ----
    if (LAYER < 2) {
        #pragma unroll
        for (int mb = 0; mb < 2; mb++)
            #pragma unroll
            for (int h = 0; h < 2; h++) {
                size_t row = m0 + wr + mb*16 + (lane >> 2) + h*8;
                float* yr = &Y[row*128 + wc + (lane & 3)*2];
                #pragma unroll
                for (int nf = 0; nf < 8; nf++)
                    *(float2*)&yr[nf*8] = make_float2(acc[mb][nf][h*2], acc[mb][nf][h*2+1]);
            }
    }

    // ---- per-column partial stats, and max/min for LAYER 2 ----
    float csum[8][2], csq[8][2];
    #pragma unroll
    for (int nf = 0; nf < 8; nf++)
        #pragma unroll
        for (int j = 0; j < 2; j++) { csum[nf][j] = 0.f; csq[nf][j] = 0.f; }
    float cmx[8][2], cmn[8][2];
    if (LAYER == 2) {
        #pragma unroll
        for (int nf = 0; nf < 8; nf++)
            #pragma unroll
            for (int j = 0; j < 2; j++) { cmx[nf][j] = -3.4e38f; cmn[nf][j] = 3.4e38f; }
    }
    #pragma unroll
    for (int mb = 0; mb < 2; mb++)
        #pragma unroll
        for (int nf = 0; nf < 8; nf++)
            #pragma unroll
            for (int c = 0; c < 4; c++) {
                int j = c & 1;
                float v = acc[mb][nf][c];
                csum[nf][j] += v;
                csq[nf][j] = fmaf(v, v, csq[nf][j]);
                if (LAYER == 2) {
                    cmx[nf][j] = fmaxf(cmx[nf][j], v);
                    cmn[nf][j] = fminf(cmn[nf][j], v);
                }
            }

    float* red = (float*)usm;   // [4][128]
    #pragma unroll
    for (int nf = 0; nf < 8; nf++)
        #pragma unroll
        for (int j = 0; j < 2; j++) {
            float v = csum[nf][j];
            #pragma unroll
            for (int o = 4; o < 32; o <<= 1) v += __shfl_xor_sync(0xffffffffu, v, o);
            if (lane < 4) red[(w & 3)*128 + wc + nf*8 + lane*2 + j] = v;
        }
    __syncthreads();
    if (t < 128) {
        float s = red[t] + red[128 + t] + red[256 + t] + red[384 + t];
        atomicAdd(&g_sum[LAYER*256 + o0 + t], s);
    }
    __syncthreads();
    #pragma unroll
    for (int nf = 0; nf < 8; nf++)
        #pragma unroll
        for (int j = 0; j < 2; j++) {
            float v = csq[nf][j];
            #pragma unroll
            for (int o = 4; o < 32; o <<= 1) v += __shfl_xor_sync(0xffffffffu, v, o);
            if (lane < 4) red[(w & 3)*128 + wc + nf*8 + lane*2 + j] = v;
        }
    __syncthreads();
    if (t < 128) {
        float s = red[t] + red[128 + t] + red[256 + t] + red[384 + t];
        atomicAdd(&g_sqs[LAYER*256 + o0 + t], s);
    }

    if (LAYER == 2) {
        __syncthreads();
        #pragma unroll
        for (int nf = 0; nf < 8; nf++)
            #pragma unroll
            for (int j = 0; j < 2; j++) {
                float v = cmx[nf][j];
                #pragma unroll
                for (int o = 4; o < 32; o <<= 1) v = fmaxf(v, __shfl_xor_sync(0xffffffffu, v, o));
                if (lane < 4) red[(w & 3)*128 + wc + nf*8 + lane*2 + j] = v;
            }
        __syncthreads();
        if (t < 256) {
            int g = t >> 7, col = t & 127;
            float v = fmaxf(red[(2*g)*128 + col], red[(2*g + 1)*128 + col]);
            g_mx[((size_t)(2*blockIdx.x + g))*256 + o0 + col] = v;
        }
        __syncthreads();
        #pragma unroll
        for (int nf = 0; nf < 8; nf++)
            #pragma unroll
            for (int j = 0; j < 2; j++) {
                float v = cmn[nf][j];
                #pragma unroll
                for (int o = 4; o < 32; o <<= 1) v = fminf(v, __shfl_xor_sync(0xffffffffu, v, o));
                if (lane < 4) red[(w & 3)*128 + wc + nf*8 + lane*2 + j] = v;
            }
        __syncthreads();
        if (t < 256) {
            int g = t >> 7, col = t & 127;
            float v = fminf(red[(2*g)*128 + col], red[(2*g + 1)*128 + col]);
            g_mn[((size_t)(2*blockIdx.x + g))*256 + o0 + col] = v;
        }
    }
}

// ---------------- BN finalize ------------------------------------------------
__global__ void finalize_kernel(const float* __restrict__ gamma,
                                const float* __restrict__ beta,
                                int layer, int O) {
    int t = threadIdx.x;
    if (t < O) {
        const float invM = 1.f / (float)MTOT;
        float mu  = g_sum[layer*256 + t] * invM;
        float var = g_sqs[layer*256 + t] * invM - mu*mu;
        if (var < 0.f) var = 0.f;
        float s = gamma[t] * rsqrtf(var + EPSV);
        g_scale[layer*256 + t] = s;
        g_shift[layer*256 + t] = fmaf(-mu, s, beta[t]);
    }
}

// ---------------- final: BN3 + relu on pooled extremum, transpose out --------
__global__ void final_out_kernel(float* __restrict__ out_feat) {
    __shared__ float tile[32][33];
    int bs0 = blockIdx.x * 32, c0 = blockIdx.y * 32;
    int tx = threadIdx.x, ty = threadIdx.y;   // 32 x 8
    float s  = g_scale[512 + c0 + tx];
    float shv = g_shift[512 + c0 + tx];
    #pragma unroll
    for (int j = 0; j < 32; j += 8) {
        int bs = bs0 + ty + j;
        float mx = g_mx[(size_t)bs*256 + c0 + tx];
        float mn = g_mn[(size_t)bs*256 + c0 + tx];
        float e = (s >= 0.f) ? mx : mn;
        tile[ty + j][tx] = fmaxf(0.f, fmaf(s, e, shv));
    }
    __syncthreads();
    int b = bs0 >> 10, sl = bs0 & 1023;
    #pragma unroll
    for (int j = 0; j < 32; j += 8)
        out_feat[((size_t)(b*256 + c0 + ty + j))*1024 + sl + tx] = tile[tx][ty + j];
}

// ---------------- launcher ---------------------------------------------------
extern "C" void kernel_launch(void* const* d_in, const int* in_sizes, int n_in,
                              void* d_out, int out_size) {
    const float* xyz = (const float*)d_in[0];
    const float* pts = (const float*)d_in[1];
    const int*   idx = (const int*)d_in[2];
    const float* w0  = (const float*)d_in[3];
    const float* g0  = (const float*)d_in[5];
    const float* be0 = (const float*)d_in[6];
    const float* w1  = (const float*)d_in[7];
    const float* g1  = (const float*)d_in[9];
    const float* be1 = (const float*)d_in[10];
    const float* w2  = (const float*)d_in[11];
    const float* g2  = (const float*)d_in[13];
    const float* be2 = (const float*)d_in[14];

    float* out      = (float*)d_out;
    float* out_xyz  = out;                       // [B,3,SPT]
    float* out_feat = out + (size_t)B_*3*SPT;    // [B,256,SPT]

    const int GSM = 16384 * 4;   // 64 KB

    cudaFuncSetAttribute(fps_kernel, cudaFuncAttributeMaxDynamicSharedMemorySize, FPS_SMEM);
    cudaFuncSetAttribute(gemm_tc<0>, cudaFuncAttributeMaxDynamicSharedMemorySize, GSM);
    cudaFuncSetAttribute(gemm_tc<1>, cudaFuncAttributeMaxDynamicSharedMemorySize, GSM);
    cudaFuncSetAttribute(gemm_tc<2>, cudaFuncAttributeMaxDynamicSharedMemorySize, GSM);

    prep_kernel<<<(B_*NPT + 255)/256, 256>>>(w0, w1, w2, xyz, idx);
    transpose_kernel<<<dim3(NPT/32, DD/32, B_), dim3(32, 8)>>>(pts);
    fps_kernel<<<B_, 512, FPS_SMEM>>>(xyz, idx, out_xyz);
    ballquery_kernel<<<(B_*SPT)/8, 256>>>();

    gemm_tc<0><<<dim3(MTOT/128, 1), 256, GSM>>>(xyz);
    finalize_kernel<<<1, 256>>>(g0, be0, 0, 128);
    gemm_tc<1><<<dim3(MTOT/128, 1), 256, GSM>>>(xyz);
    finalize_kernel<<<1, 256>>>(g1, be1, 1, 128);
    gemm_tc<2><<<dim3(MTOT/128, 2), 256, GSM>>>(xyz);
    finalize_kernel<<<1, 256>>>(g2, be2, 2, 256);

    final_out_kernel<<<dim3(NGRP/32, 256/32), dim3(32, 8)>>>(out_feat);
}

// round 11
// speedup vs baseline: 2.5738x; 1.0089x over previous
#include <cuda_runtime.h>
#include <cuda_bf16.h>
#include <math.h>

#define B_ 8
#define NPT 16384
#define SPT 1024
#define NS 64
#define DD 64
#define C0 67
#define MTOT (B_*SPT*NS)      // 524288
#define NGRP (MTOT/NS)        // 8192
#define RR2 0.09f
#define EPSV 1e-5f

typedef unsigned long long ull;
typedef unsigned uint;

// ---------------- scratch (static device globals; no allocation) -------------
__device__ __align__(16) float g_ptsT[(size_t)B_*NPT*DD];       // 33.5 MB
__device__ __align__(16) float4 g_pk[(size_t)B_*NPT];           // 2 MB packed xyz+id
__device__ float g_newxyz[B_*SPT*3];
__device__ int   g_fpsidx[B_*SPT];
__device__ int   g_newptr[B_*SPT];
__device__ int   g_gid[B_*SPT*NS];
__device__ __align__(16) float g_y1[(size_t)MTOT*128];          // 268 MB
__device__ __align__(16) float g_y2[(size_t)MTOT*128];          // 268 MB
__device__ __align__(16) float g_mx[(size_t)NGRP*256];          // 8 MB
__device__ __align__(16) float g_mn[(size_t)NGRP*256];          // 8 MB
__device__ float g_sum[3*256];
__device__ float g_sqs[3*256];
__device__ float g_scale[3*256];
__device__ float g_shift[3*256];
// weights pre-split (bf16 hi/lo) packed in m16n8k16 B-fragment layout
#define W0WORDS (5*1024)      // KP=80: 5 ksteps
#define W1WORDS (8*1024)      // KP=128
#define W2WORDS (2*8*1024)    // 2 otiles
#define TOTALW (W0WORDS + W1WORDS + W2WORDS)
__device__ __align__(16) uint g_wf0h[W0WORDS], g_wf0l[W0WORDS];
__device__ __align__(16) uint g_wf1h[W1WORDS], g_wf1l[W1WORDS];
__device__ __align__(16) uint g_wf2h[W2WORDS], g_wf2l[W2WORDS];

// ---------------- f32x2 packed helpers ---------------------------------------
#define ADD2(o, a, b) asm("add.rn.f32x2 %0, %1, %2;" : "=l"(o) : "l"(a), "l"(b))
#define MUL2(o, a, b) asm("mul.rn.f32x2 %0, %1, %2;" : "=l"(o) : "l"(a), "l"(b))
#define FMA2(o, a, b, c) asm("fma.rn.f32x2 %0, %1, %2, %3;" : "=l"(o) : "l"(a), "l"(b), "l"(c))

__device__ __forceinline__ ull bcast2(float v) {
    unsigned u = __float_as_uint(v);
    return ((ull)u << 32) | (ull)u;
}
__device__ __forceinline__ float lo2(ull m) { return __uint_as_float((unsigned)m); }
__device__ __forceinline__ float hi2(ull m) { return __uint_as_float((unsigned)(m >> 32)); }

__device__ __forceinline__ uint pk_bf2(float a, float b) {
    uint r;
    asm("cvt.rn.bf16x2.f32 %0, %1, %2;" : "=r"(r) : "f"(b), "f"(a));
    return r;
}
__device__ __forceinline__ void split2(float v0, float v1, uint& wh, uint& wl) {
    wh = pk_bf2(v0, v1);
    __nv_bfloat162 h2 = *(__nv_bfloat162*)&wh;
    float h0 = __bfloat162float(h2.x), h1 = __bfloat162float(h2.y);
    wl = pk_bf2(v0 - h0, v1 - h1);
}

// store float4 (row r, chunk-local col base = c4*4) into A frag smem
__device__ __forceinline__ void frag_store4(uint* Ah, uint* Al, int r, int c4, float4 v) {
    int r16 = r & 15, mb = r >> 4;
    int kk0 = (c4*4) & 15, kst = (c4*4) >> 4;
    int reg = (r16 >> 3) + ((kk0 >> 3) << 1);
    int l0  = ((r16 & 7) << 2) | ((kk0 >> 1) & 3);
    int i0  = ((kst*8 + mb)*32 + l0)*4 + reg;
    uint wh, wl;
    split2(v.x, v.y, wh, wl);
    Ah[i0] = wh; Al[i0] = wl;
    split2(v.z, v.w, wh, wl);
    Ah[i0 + 4] = wh; Al[i0 + 4] = wl;
}

// ---------------- FRONT: fps (blocks 0..7) + prep/transpose (blocks 8+) ------
#define FPS_SMEM ((3*NPT + 64) * 4)
#define NTRB 4096   // transpose blocks (2 tiles each -> 8192 tiles)
__global__ void __launch_bounds__(512, 1)
front_kernel(const float* __restrict__ xyz, const int* __restrict__ idx,
             const float* __restrict__ pts,
             const float* __restrict__ w0, const float* __restrict__ w1,
             const float* __restrict__ w2,
             float* __restrict__ out_xyz) {
    extern __shared__ float fsm[];
    const int t = threadIdx.x;

    if (blockIdx.x >= 8) {
        // ===================== prep + transpose role =====================
        int bid = blockIdx.x - 8;
        int gi = bid*512 + t;
        // zero stats
        if (gi < 768) { g_sum[gi] = 0.f; g_sqs[gi] = 0.f; }
        // pack xyz+id
        if (gi < B_*NPT) {
            int b = gi >> 14, n = gi & (NPT-1);
            const float* px = xyz + (size_t)b*3*NPT;
            g_pk[gi] = make_float4(px[n], px[NPT+n], px[2*NPT+n], __int_as_float(idx[gi]));
        }
        // weight fragments
        if (gi < TOTALW) {
            int layer, j, otile = 0;
            if (gi < W0WORDS) { layer = 0; j = gi; }
            else if (gi < W0WORDS + W1WORDS) { layer = 1; j = gi - W0WORDS; }
            else { layer = 2; j = gi - W0WORDS - W1WORDS; otile = j >> 13; j &= 8191; }
            int reg = j & 1, ln = (j >> 1) & 31, nb = (j >> 6) & 15, ksg = j >> 10;
            int o  = otile*128 + nb*8 + (ln >> 2);
            int c0 = ksg*16 + reg*8 + (ln & 3)*2;
            float v0, v1;
            if (layer == 0) {
                int s0 = (c0   < 64) ? (c0   + 3) : (c0   - 64);
                int s1 = (c0+1 < 64) ? (c0+1 + 3) : (c0+1 - 64);
                v0 = (c0   < C0) ? w0[o*C0 + s0] : 0.f;
                v1 = (c0+1 < C0) ? w0[o*C0 + s1] : 0.f;
            } else if (layer == 1) {
                v0 = w1[o*128 + c0]; v1 = w1[o*128 + c0 + 1];
            } else {
                v0 = w2[o*128 + c0]; v1 = w2[o*128 + c0 + 1];
            }
            uint wh, wl;
            split2(v0, v1, wh, wl);
            if (layer == 0)      { g_wf0h[j] = wh; g_wf0l[j] = wl; }
            else if (layer == 1) { g_wf1h[j] = wh; g_wf1l[j] = wl; }
            else { int k2 = (otile << 13) | j; g_wf2h[k2] = wh; g_wf2l[k2] = wl; }
        }
        // transpose: 2 tiles per block
        int tile_id = bid*2 + (t >> 8);
        int sub = t & 255, tx = sub & 31, ty = sub >> 5;   // 32 x 8
        int bx = tile_id & 511, byz = tile_id >> 9;
        int by = byz & 1, bz = byz >> 1;
        int n0 = bx * 32, c0 = by * 32;
        float* tb = fsm + (t >> 8) * 1088;    // 32x33 + pad
        #pragma unroll
        for (int j = 0; j < 32; j += 8)
            tb[(ty + j)*33 + tx] = pts[((size_t)bz*DD + c0 + ty + j)*NPT + n0 + tx];
        __syncthreads();
        #pragma unroll
        for (int j = 0; j < 32; j += 8)
            g_ptsT[((size_t)bz*NPT + n0 + ty + j)*DD + c0 + tx] = tb[tx*33 + ty + j];
        return;
    }

    // ===================== FPS role (blocks 0..7) =====================
    float* sx = fsm;
    float* sy = sx + NPT;
    float* sz = sy + NPT;
    float* redv = sz + NPT;        // 16 used
    __shared__ int s_idx[2];

    const int b = blockIdx.x;
    const float* px = xyz + (size_t)b*3*NPT;
    const float* py = px + NPT;
    const float* pz = py + NPT;

    for (int n = t; n < NPT; n += 512) { sx[n]=px[n]; sy[n]=py[n]; sz[n]=pz[n]; }
    if (t == 0) s_idx[0] = 0;
    __syncthreads();

    ull xp[16], yp[16];
    float dist[32];
    #pragma unroll
    for (int i = 0; i < 16; i++) {
        int p = t + (i << 9);
        xp[i] = *(const ull*)&sx[2*p];
        yp[i] = *(const ull*)&sy[2*p];
        dist[2*i] = 1e10f; dist[2*i+1] = 1e10f;
    }

    const int lane = t & 31;
    for (int s = 0; s < SPT; s++) {
        int far = s_idx[s & 1];
        float cx = sx[far], cy = sy[far], cz = sz[far];
        if (t == 0) {
            g_fpsidx[b*SPT + s] = far;
            g_newptr[b*SPT + s] = idx[b*NPT + far];
            g_newxyz[(b*SPT + s)*3 + 0] = cx;
            g_newxyz[(b*SPT + s)*3 + 1] = cy;
            g_newxyz[(b*SPT + s)*3 + 2] = cz;
            out_xyz[(b*3 + 0)*SPT + s] = cx;
            out_xyz[(b*3 + 1)*SPT + s] = cy;
            out_xyz[(b*3 + 2)*SPT + s] = cz;
            s_idx[(s + 1) & 1] = 0x7fffffff;
        }
        if (s == SPT - 1) break;

        ull ncx = bcast2(-cx), ncy = bcast2(-cy), ncz = bcast2(-cz);
        float best = -1.f;
        #pragma unroll
        for (int i = 0; i < 16; i++) {
            int p = t + (i << 9);
            ull z2 = *(const ull*)&sz[2*p];
            ull dx2, dy2, dz2, m;
            ADD2(dx2, xp[i], ncx);
            ADD2(dy2, yp[i], ncy);
            ADD2(dz2, z2,    ncz);
            MUL2(m, dx2, dx2);
            FMA2(m, dy2, dy2, m);
            FMA2(m, dz2, dz2, m);
            float d0 = fminf(dist[2*i],   lo2(m));
            float d1 = fminf(dist[2*i+1], hi2(m));
            dist[2*i] = d0; dist[2*i+1] = d1;
            best = fmaxf(best, d0);
            best = fmaxf(best, d1);
        }
        float wmax = best;
        #pragma unroll
        for (int o = 16; o > 0; o >>= 1)
            wmax = fmaxf(wmax, __shfl_xor_sync(0xffffffffu, wmax, o));
        if (lane == 0) redv[t >> 5] = wmax;
        __syncthreads();
        float vmax = redv[lane & 15];
        #pragma unroll
        for (int o = 8; o > 0; o >>= 1)
            vmax = fmaxf(vmax, __shfl_xor_sync(0xffffffffu, vmax, o));
        if (best == vmax) {
            int found = 0x7fffffff;
            #pragma unroll
            for (int i = 0; i < 16; i++) {
                int p2 = 2*(t + (i << 9));
                if (dist[2*i]   == vmax) found = min(found, p2);
                if (dist[2*i+1] == vmax) found = min(found, p2 + 1);
            }
            atomicMin(&s_idx[(s + 1) & 1], found);
        }
        __syncthreads();
    }
}

// ---------------- ball query: one warp per (b,s), packed float4 --------------
__global__ void __launch_bounds__(256)
ballquery_kernel() {
    int warp = (blockIdx.x * blockDim.x + threadIdx.x) >> 5;
    int lane = threadIdx.x & 31;
    if (warp >= B_*SPT) return;
    int b = warp / SPT;
    float cx = g_newxyz[warp*3+0], cy = g_newxyz[warp*3+1], cz = g_newxyz[warp*3+2];
    int np = g_newptr[warp];
    float cn = cx*cx + cy*cy + cz*cz;
    const float4* pk = g_pk + (size_t)b*NPT;
    int* gout = g_gid + (size_t)warp*NS;

    int cnt = 0, first = -1;
    for (int n0 = 0; n0 < NPT && cnt < NS; n0 += 128) {
        float4 vv[4];
        #pragma unroll
        for (int sb = 0; sb < 4; sb++) vv[sb] = pk[n0 + sb*32 + lane];
        #pragma unroll
        for (int sb = 0; sb < 4; sb++) {
            int n = n0 + sb*32 + lane;
            float x = vv[sb].x, y = vv[sb].y, z = vv[sb].z;
            float pn = x*x + y*y + z*z;
            float sq = cn + pn - 2.f*(cx*x + cy*y + cz*z);
            bool hit = !(sq > RR2) && (__float_as_int(vv[sb].w) == np);
            unsigned m = __ballot_sync(0xffffffffu, hit);
            if (m) {
                if (first < 0) first = n0 + sb*32 + __ffs(m) - 1;
                int pos = cnt + __popc(m & ((1u << lane) - 1));
                if (hit && pos < NS) gout[pos] = n;
                cnt += __popc(m);
                if (cnt > NS) cnt = NS;
            }
        }
    }
    if (first < 0) { first = g_fpsidx[warp]; }
    if (cnt == 0) { if (lane == 0) gout[0] = first; cnt = 1; }
    for (int p = cnt + lane; p < NS; p += 32) gout[p] = first;
}

// ---------------- bf16 mma helpers -------------------------------------------
#define MMAB(d, a, b) asm volatile( \
    "mma.sync.aligned.m16n8k16.row.col.f32.bf16.bf16.f32 " \
    "{%0,%1,%2,%3},{%4,%5,%6,%7},{%8,%9},{%0,%1,%2,%3};\n" \
    : "+f"(d[0]), "+f"(d[1]), "+f"(d[2]), "+f"(d[3]) \
    : "r"(a[0]), "r"(a[1]), "r"(a[2]), "r"(a[3]), "r"(b[0]), "r"(b[1]))

// ---------------- one K-chunk : load A (split / gather for L0), copy W, mma --
template<int KS16, int LAYER>
__device__ __forceinline__ void do_chunk(
    const float* __restrict__ A, const float* __restrict__ xyz, size_t m0, int kc,
    const float* __restrict__ sc, const float* __restrict__ sh,
    const uint* __restrict__ Wfh, const uint* __restrict__ Wfl, int wfbase,
    uint* Ah, uint* Al, uint* Bh, uint* Bl,
    int t, int lane, int w, int wc, float acc[2][8][4])
{
    constexpr int KP = 128;               // layers 1,2 row stride
    constexpr int CW = KS16 * 4;          // float4 per row this chunk

    if (LAYER == 0) {
        const int bb = (int)(m0 >> 16);
        if (KS16 == 4) {
            for (int i = t; i < 128*16; i += 256) {
                int r = i >> 4, c4 = i & 15;
                int g = g_gid[m0 + r];
                float4 v = *(const float4*)&g_ptsT[((size_t)bb*NPT + g)*DD + c4*4];
                frag_store4(Ah, Al, r, c4, v);
            }
        } else {
            const float* px = xyz + (size_t)bb*3*NPT;
            for (int i = t; i < 128*4; i += 256) {
                int r = i >> 2, c4 = i & 3;
                float4 v = make_float4(0.f, 0.f, 0.f, 0.f);
                if (c4 == 0) {
                    int g = g_gid[m0 + r];
                    int bs = (int)((m0 + r) >> 6);
                    v = make_float4(px[g]        - g_newxyz[bs*3+0],
                                    px[NPT+g]    - g_newxyz[bs*3+1],
                                    px[2*NPT+g]  - g_newxyz[bs*3+2], 0.f);
                }
                frag_store4(Ah, Al, r, c4, v);
            }
        }
    } else {
        for (int i = t; i < 128*CW; i += 256) {
            int r = i / CW, c4 = i - r*CW;
            float4 v = *(const float4*)&A[(m0 + r)*KP + kc + c4*4];
            int ch = kc + c4*4;
            v.x = fmaxf(0.f, fmaf(sc[ch+0], v.x, sh[ch+0]));
            v.y = fmaxf(0.f, fmaf(sc[ch+1], v.y, sh[ch+1]));
            v.z = fmaxf(0.f, fmaf(sc[ch+2], v.z, sh[ch+2]));
            v.w = fmaxf(0.f, fmaf(sc[ch+3], v.w, sh[ch+3]));
            frag_store4(Ah, Al, r, c4, v);
        }
    }
    {
        const uint4* shp = (const uint4*)(Wfh + wfbase);
        const uint4* slp = (const uint4*)(Wfl + wfbase);
        for (int i = t; i < KS16*256; i += 256) {
            ((uint4*)Bh)[i] = shp[i];
            ((uint4*)Bl)[i] = slp[i];
        }
    }
    __syncthreads();

    #pragma unroll
    for (int kstep = 0; kstep < KS16; kstep++) {
        uint ah[2][4], al[2][4];
        #pragma unroll
        for (int mb = 0; mb < 2; mb++) {
            int base = ((kstep*8 + (w & 3)*2 + mb)*32 + lane)*4;
            uint4 vh = *(const uint4*)&Ah[base];
            uint4 vl = *(const uint4*)&Al[base];
            ah[mb][0]=vh.x; ah[mb][1]=vh.y; ah[mb][2]=vh.z; ah[mb][3]=vh.w;
            al[mb][0]=vl.x; al[mb][1]=vl.y; al[mb][2]=vl.z; al[mb][3]=vl.w;
        }
        #pragma unroll
        for (int nf = 0; nf < 8; nf++) {
            int baseb = ((kstep*16 + (wc >> 3) + nf)*32 + lane)*2;
            uint2 bhv = *(const uint2*)&Bh[baseb];
            uint2 blv = *(const uint2*)&Bl[baseb];
            uint bh[2] = {bhv.x, bhv.y};
            uint bl[2] = {blv.x, blv.y};
            #pragma unroll
            for (int mb = 0; mb < 2; mb++) {
                MMAB(acc[mb][nf], ah[mb], bh);
                MMAB(acc[mb][nf], al[mb], bh);
                MMAB(acc[mb][nf], ah[mb], bl);
            }
        }
    }
    __syncthreads();
}

// ---------------- bf16x3 GEMM: Y = act(A) * W^T, fused stats (+pool L2) ------
template<int LAYER>
__global__ void __launch_bounds__(256, 2)
gemm_tc(const float* __restrict__ xyz) {
    const float* A = (LAYER == 1) ? g_y1 : g_y2;   // unused for LAYER==0
    float*       Y = (LAYER == 0) ? g_y1 : g_y2;
    const uint* Wfh = (LAYER == 0) ? g_wf0h : ((LAYER == 1) ? g_wf1h : g_wf2h);
    const uint* Wfl = (LAYER == 0) ? g_wf0l : ((LAYER == 1) ? g_wf1l : g_wf2l);
    const float* sc = g_scale + ((LAYER > 0) ? (LAYER - 1)*256 : 0);
    const float* sh = g_shift + ((LAYER > 0) ? (LAYER - 1)*256 : 0);

    extern __shared__ uint usm[];
    uint* Ah = usm;              // 4096 each
    uint* Al = usm + 4096;
    uint* Bh = usm + 8192;
    uint* Bl = usm + 12288;

    const int t = threadIdx.x;
    const int lane = t & 31, w = t >> 5;
    const int wr = (w & 3) * 32, wc = (w >> 2) * 64;
    const size_t m0 = (size_t)blockIdx.x * 128;
    const int o0 = blockIdx.y * 128;
    const int otile = blockIdx.y;

    float acc[2][8][4];
    #pragma unroll
    for (int mb = 0; mb < 2; mb++)
        #pragma unroll
        for (int nf = 0; nf < 8; nf++)
            #pragma unroll
            for (int c = 0; c < 4; c++) acc[mb][nf][c] = 0.f;

    int wb0 = (LAYER == 2) ? (otile*8)*1024 : 0;
    do_chunk<4, LAYER>(A, xyz, m0, 0, sc, sh, Wfh, Wfl, wb0, Ah, Al, Bh, Bl, t, lane, w, wc, acc);
    if (LAYER == 0)
        do_chunk<1, LAYER>(A, xyz, m0, 64, sc, sh, Wfh, Wfl, 4*1024, Ah, Al, Bh, Bl, t, lane, w, wc, acc);
    else
        do_chunk<4, LAYER>(A, xyz, m0, 64, sc, sh, Wfh, Wfl, wb0 + 4*1024, Ah, Al, Bh, Bl, t, lane, w, wc, acc);

    // ---- epilogue: store Y (layers 0,1) ----
    if (LAYER < 2) {
        #pragma unroll
        for (int mb = 0; mb < 2; mb++)
            #pragma unroll
            for (int h = 0; h < 2; h++) {
                size_t row = m0 + wr + mb*16 + (lane >> 2) + h*8;
                float* yr = &Y[row*128 + wc + (lane & 3)*2];
                #pragma unroll
                for (int nf = 0; nf < 8; nf++)
                    *(float2*)&yr[nf*8] = make_float2(acc[mb][nf][h*2], acc[mb][nf][h*2+1]);
            }
    }

    // ---- per-column partial stats, and max/min for LAYER 2 ----
    float csum[8][2], csq[8][2];
    #pragma unroll
    for (int nf = 0; nf < 8; nf++)
        #pragma unroll
        for (int j = 0; j < 2; j++) { csum[nf][j] = 0.f; csq[nf][j] = 0.f; }
    float cmx[8][2], cmn[8][2];
    if (LAYER == 2) {
        #pragma unroll
        for (int nf = 0; nf < 8; nf++)
            #pragma unroll
            for (int j = 0; j < 2; j++) { cmx[nf][j] = -3.4e38f; cmn[nf][j] = 3.4e38f; }
    }
    #pragma unroll
    for (int mb = 0; mb < 2; mb++)
        #pragma unroll
        for (int nf = 0; nf < 8; nf++)
            #pragma unroll
            for (int c = 0; c < 4; c++) {
                int j = c & 1;
                float v = acc[mb][nf][c];
                csum[nf][j] += v;
                csq[nf][j] = fmaf(v, v, csq[nf][j]);
                if (LAYER == 2) {
                    cmx[nf][j] = fmaxf(cmx[nf][j], v);
                    cmn[nf][j] = fminf(cmn[nf][j], v);
                }
            }

    float* red = (float*)usm;   // [4][128]
    #pragma unroll
    for (int nf = 0; nf < 8; nf++)
        #pragma unroll
        for (int j = 0; j < 2; j++) {
            float v = csum[nf][j];
            #pragma unroll
            for (int o = 4; o < 32; o <<= 1) v += __shfl_xor_sync(0xffffffffu, v, o);
            if (lane < 4) red[(w & 3)*128 + wc + nf*8 + lane*2 + j] = v;
        }
    __syncthreads();
    if (t < 128) {
        float s = red[t] + red[128 + t] + red[256 + t] + red[384 + t];
        atomicAdd(&g_sum[LAYER*256 + o0 + t], s);
    }
    __syncthreads();
    #pragma unroll
    for (int nf = 0; nf < 8; nf++)
        #pragma unroll
        for (int j = 0; j < 2; j++) {
            float v = csq[nf][j];
            #pragma unroll
            for (int o = 4; o < 32; o <<= 1) v += __shfl_xor_sync(0xffffffffu, v, o);
            if (lane < 4) red[(w & 3)*128 + wc + nf*8 + lane*2 + j] = v;
        }
    __syncthreads();
    if (t < 128) {
        float s = red[t] + red[128 + t] + red[256 + t] + red[384 + t];
        atomicAdd(&g_sqs[LAYER*256 + o0 + t], s);
    }

    if (LAYER == 2) {
        __syncthreads();
        #pragma unroll
        for (int nf = 0; nf < 8; nf++)
            #pragma unroll
            for (int j = 0; j < 2; j++) {
                float v = cmx[nf][j];
                #pragma unroll
                for (int o = 4; o < 32; o <<= 1) v = fmaxf(v, __shfl_xor_sync(0xffffffffu, v, o));
                if (lane < 4) red[(w & 3)*128 + wc + nf*8 + lane*2 + j] = v;
            }
        __syncthreads();
        if (t < 256) {
            int g = t >> 7, col = t & 127;
            float v = fmaxf(red[(2*g)*128 + col], red[(2*g + 1)*128 + col]);
            g_mx[((size_t)(2*blockIdx.x + g))*256 + o0 + col] = v;
        }
        __syncthreads();
        #pragma unroll
        for (int nf = 0; nf < 8; nf++)
            #pragma unroll
            for (int j = 0; j < 2; j++) {
                float v = cmn[nf][j];
                #pragma unroll
                for (int o = 4; o < 32; o <<= 1) v = fminf(v, __shfl_xor_sync(0xffffffffu, v, o));
                if (lane < 4) red[(w & 3)*128 + wc + nf*8 + lane*2 + j] = v;
            }
        __syncthreads();
        if (t < 256) {
            int g = t >> 7, col = t & 127;
            float v = fminf(red[(2*g)*128 + col], red[(2*g + 1)*128 + col]);
            g_mn[((size_t)(2*blockIdx.x + g))*256 + o0 + col] = v;
        }
    }
}

// ---------------- BN finalize ------------------------------------------------
__global__ void finalize_kernel(const float* __restrict__ gamma,
                                const float* __restrict__ beta,
                                int layer, int O) {
    int t = threadIdx.x;
    if (t < O) {
        const float invM = 1.f / (float)MTOT;
        float mu  = g_sum[layer*256 + t] * invM;
        float var = g_sqs[layer*256 + t] * invM - mu*mu;
        if (var < 0.f) var = 0.f;
        float s = gamma[t] * rsqrtf(var + EPSV);
        g_scale[layer*256 + t] = s;
        g_shift[layer*256 + t] = fmaf(-mu, s, beta[t]);
    }
}

// ---------------- final: BN3 + relu on pooled extremum, transpose out --------
__global__ void final_out_kernel(float* __restrict__ out_feat) {
    __shared__ float tile[32][33];
    int bs0 = blockIdx.x * 32, c0 = blockIdx.y * 32;
    int tx = threadIdx.x, ty = threadIdx.y;   // 32 x 8
    float s  = g_scale[512 + c0 + tx];
    float shv = g_shift[512 + c0 + tx];
    #pragma unroll
    for (int j = 0; j < 32; j += 8) {
        int bs = bs0 + ty + j;
        float mx = g_mx[(size_t)bs*256 + c0 + tx];
        float mn = g_mn[(size_t)bs*256 + c0 + tx];
        float e = (s >= 0.f) ? mx : mn;
        tile[ty + j][tx] = fmaxf(0.f, fmaf(s, e, shv));
    }
    __syncthreads();
    int b = bs0 >> 10, sl = bs0 & 1023;
    #pragma unroll
    for (int j = 0; j < 32; j += 8)
        out_feat[((size_t)(b*256 + c0 + ty + j))*1024 + sl + tx] = tile[tx][ty + j];
}

// ---------------- launcher ---------------------------------------------------
extern "C" void kernel_launch(void* const* d_in, const int* in_sizes, int n_in,
                              void* d_out, int out_size) {
    const float* xyz = (const float*)d_in[0];
    const float* pts = (const float*)d_in[1];
    const int*   idx = (const int*)d_in[2];
    const float* w0  = (const float*)d_in[3];
    const float* g0  = (const float*)d_in[5];
    const float* be0 = (const float*)d_in[6];
    const float* w1  = (const float*)d_in[7];
    const float* g1  = (const float*)d_in[9];
    const float* be1 = (const float*)d_in[10];
    const float* w2  = (const float*)d_in[11];
    const float* g2  = (const float*)d_in[13];
    const float* be2 = (const float*)d_in[14];

    float* out      = (float*)d_out;
    float* out_xyz  = out;                       // [B,3,SPT]
    float* out_feat = out + (size_t)B_*3*SPT;    // [B,256,SPT]

    const int GSM = 16384 * 4;   // 64 KB

    cudaFuncSetAttribute(front_kernel, cudaFuncAttributeMaxDynamicSharedMemorySize, FPS_SMEM);
    cudaFuncSetAttribute(gemm_tc<0>, cudaFuncAttributeMaxDynamicSharedMemorySize, GSM);
    cudaFuncSetAttribute(gemm_tc<1>, cudaFuncAttributeMaxDynamicSharedMemorySize, GSM);
    cudaFuncSetAttribute(gemm_tc<2>, cudaFuncAttributeMaxDynamicSharedMemorySize, GSM);

    front_kernel<<<8 + NTRB, 512, FPS_SMEM>>>(xyz, idx, pts, w0, w1, w2, out_xyz);
    ballquery_kernel<<<(B_*SPT)/8, 256>>>();

    gemm_tc<0><<<dim3(MTOT/128, 1), 256, GSM>>>(xyz);
    finalize_kernel<<<1, 256>>>(g0, be0, 0, 128);
    gemm_tc<1><<<dim3(MTOT/128, 1), 256, GSM>>>(xyz);
    finalize_kernel<<<1, 256>>>(g1, be1, 1, 128);
    gemm_tc<2><<<dim3(MTOT/128, 2), 256, GSM>>>(xyz);
    finalize_kernel<<<1, 256>>>(g2, be2, 2, 256);

    final_out_kernel<<<dim3(NGRP/32, 256/32), dim3(32, 8)>>>(out_feat);
}

// round 12
// speedup vs baseline: 2.5834x; 1.0037x over previous
#include <cuda_runtime.h>
#include <cuda_bf16.h>
#include <math.h>

#define B_ 8
#define NPT 16384
#define SPT 1024
#define NS 64
#define DD 64
#define C0 67
#define MTOT (B_*SPT*NS)      // 524288
#define NGRP (MTOT/NS)        // 8192
#define RR2 0.09f
#define EPSV 1e-5f

typedef unsigned long long ull;
typedef unsigned uint;

// ---------------- scratch (static device globals; no allocation) -------------
__device__ __align__(16) float g_ptsT[(size_t)B_*NPT*DD];       // 33.5 MB
__device__ __align__(16) float4 g_pk[(size_t)B_*NPT];           // 2 MB packed xyz+id
__device__ float g_newxyz[B_*SPT*3];
__device__ int   g_fpsidx[B_*SPT];
__device__ int   g_newptr[B_*SPT];
__device__ int   g_gid[B_*SPT*NS];
__device__ __align__(16) float g_y1[(size_t)MTOT*128];          // 268 MB
__device__ __align__(16) float g_y2[(size_t)MTOT*128];          // 268 MB
__device__ __align__(16) float g_mx[(size_t)NGRP*256];          // 8 MB
__device__ __align__(16) float g_mn[(size_t)NGRP*256];          // 8 MB
__device__ float g_sum[3*256];
__device__ float g_sqs[3*256];
// weights pre-split (bf16 hi/lo) packed in m16n8k16 B-fragment layout
#define W0WORDS (5*1024)      // KP=80: 5 ksteps
#define W1WORDS (8*1024)      // KP=128
#define W2WORDS (2*8*1024)    // 2 otiles
#define TOTALW (W0WORDS + W1WORDS + W2WORDS)
__device__ __align__(16) uint g_wf0h[W0WORDS], g_wf0l[W0WORDS];
__device__ __align__(16) uint g_wf1h[W1WORDS], g_wf1l[W1WORDS];
__device__ __align__(16) uint g_wf2h[W2WORDS], g_wf2l[W2WORDS];

// ---------------- f32x2 packed helpers ---------------------------------------
#define ADD2(o, a, b) asm("add.rn.f32x2 %0, %1, %2;" : "=l"(o) : "l"(a), "l"(b))
#define MUL2(o, a, b) asm("mul.rn.f32x2 %0, %1, %2;" : "=l"(o) : "l"(a), "l"(b))
#define FMA2(o, a, b, c) asm("fma.rn.f32x2 %0, %1, %2, %3;" : "=l"(o) : "l"(a), "l"(b), "l"(c))

__device__ __forceinline__ ull bcast2(float v) {
    unsigned u = __float_as_uint(v);
    return ((ull)u << 32) | (ull)u;
}
__device__ __forceinline__ float lo2(ull m) { return __uint_as_float((unsigned)m); }
__device__ __forceinline__ float hi2(ull m) { return __uint_as_float((unsigned)(m >> 32)); }

__device__ __forceinline__ uint pk_bf2(float a, float b) {
    uint r;
    asm("cvt.rn.bf16x2.f32 %0, %1, %2;" : "=r"(r) : "f"(b), "f"(a));
    return r;
}
__device__ __forceinline__ void split2(float v0, float v1, uint& wh, uint& wl) {
    wh = pk_bf2(v0, v1);
    __nv_bfloat162 h2 = *(__nv_bfloat162*)&wh;
    float h0 = __bfloat162float(h2.x), h1 = __bfloat162float(h2.y);
    wl = pk_bf2(v0 - h0, v1 - h1);
}

// BN finalize formula (shared by gemm preamble + final_out); bit-identical
__device__ __forceinline__ void bn_coef(int layer, int c,
                                        const float* __restrict__ gamma,
                                        const float* __restrict__ beta,
                                        float& s, float& sh) {
    const float invM = 1.f / (float)MTOT;
    float mu  = g_sum[layer*256 + c] * invM;
    float var = g_sqs[layer*256 + c] * invM - mu*mu;
    if (var < 0.f) var = 0.f;
    s  = gamma[c] * rsqrtf(var + EPSV);
    sh = fmaf(-mu, s, beta[c]);
}

// store float4 (row r, chunk-local col base = c4*4) into A frag smem
__device__ __forceinline__ void frag_store4(uint* Ah, uint* Al, int r, int c4, float4 v) {
    int r16 = r & 15, mb = r >> 4;
    int kk0 = (c4*4) & 15, kst = (c4*4) >> 4;
    int reg = (r16 >> 3) + ((kk0 >> 3) << 1);
    int l0  = ((r16 & 7) << 2) | ((kk0 >> 1) & 3);
    int i0  = ((kst*8 + mb)*32 + l0)*4 + reg;
    uint wh, wl;
    split2(v.x, v.y, wh, wl);
    Ah[i0] = wh; Al[i0] = wl;
    split2(v.z, v.w, wh, wl);
    Ah[i0 + 4] = wh; Al[i0 + 4] = wl;
}

// ---------------- FRONT: fps (blocks 0..7) + prep/transpose (blocks 8+) ------
#define FPS_SMEM ((3*NPT + 64) * 4)
#define NTRB 4096   // transpose blocks (2 tiles each -> 8192 tiles)
__global__ void __launch_bounds__(512, 1)
front_kernel(const float* __restrict__ xyz, const int* __restrict__ idx,
             const float* __restrict__ pts,
             const float* __restrict__ w0, const float* __restrict__ w1,
             const float* __restrict__ w2,
             float* __restrict__ out_xyz) {
    extern __shared__ float fsm[];
    const int t = threadIdx.x;

    if (blockIdx.x >= 8) {
        // ===================== prep + transpose role =====================
        int bid = blockIdx.x - 8;
        int gi = bid*512 + t;
        if (gi < 768) { g_sum[gi] = 0.f; g_sqs[gi] = 0.f; }
        if (gi < B_*NPT) {
            int b = gi >> 14, n = gi & (NPT-1);
            const float* px = xyz + (size_t)b*3*NPT;
            g_pk[gi] = make_float4(px[n], px[NPT+n], px[2*NPT+n], __int_as_float(idx[gi]));
        }
        if (gi < TOTALW) {
            int layer, j, otile = 0;
            if (gi < W0WORDS) { layer = 0; j = gi; }
            else if (gi < W0WORDS + W1WORDS) { layer = 1; j = gi - W0WORDS; }
            else { layer = 2; j = gi - W0WORDS - W1WORDS; otile = j >> 13; j &= 8191; }
            int reg = j & 1, ln = (j >> 1) & 31, nb = (j >> 6) & 15, ksg = j >> 10;
            int o  = otile*128 + nb*8 + (ln >> 2);
            int c0 = ksg*16 + reg*8 + (ln & 3)*2;
            float v0, v1;
            if (layer == 0) {
                int s0 = (c0   < 64) ? (c0   + 3) : (c0   - 64);
                int s1 = (c0+1 < 64) ? (c0+1 + 3) : (c0+1 - 64);
                v0 = (c0   < C0) ? w0[o*C0 + s0] : 0.f;
                v1 = (c0+1 < C0) ? w0[o*C0 + s1] : 0.f;
            } else if (layer == 1) {
                v0 = w1[o*128 + c0]; v1 = w1[o*128 + c0 + 1];
            } else {
                v0 = w2[o*128 + c0]; v1 = w2[o*128 + c0 + 1];
            }
            uint wh, wl;
            split2(v0, v1, wh, wl);
            if (layer == 0)      { g_wf0h[j] = wh; g_wf0l[j] = wl; }
            else if (layer == 1) { g_wf1h[j] = wh; g_wf1l[j] = wl; }
            else { int k2 = (otile << 13) | j; g_wf2h[k2] = wh; g_wf2l[k2] = wl; }
        }
        int tile_id = bid*2 + (t >> 8);
        int sub = t & 255, tx = sub & 31, ty = sub >> 5;   // 32 x 8
        int bx = tile_id & 511, byz = tile_id >> 9;
        int by = byz & 1, bz = byz >> 1;
        int n0 = bx * 32, c0 = by * 32;
        float* tb = fsm + (t >> 8) * 1088;    // 32x33 + pad
        #pragma unroll
        for (int j = 0; j < 32; j += 8)
            tb[(ty + j)*33 + tx] = pts[((size_t)bz*DD + c0 + ty + j)*NPT + n0 + tx];
        __syncthreads();
        #pragma unroll
        for (int j = 0; j < 32; j += 8)
            g_ptsT[((size_t)bz*NPT + n0 + ty + j)*DD + c0 + tx] = tb[tx*33 + ty + j];
        return;
    }

    // ===================== FPS role (blocks 0..7) =====================
    float* sx = fsm;
    float* sy = sx + NPT;
    float* sz = sy + NPT;
    float* redv = sz + NPT;        // 16 used
    __shared__ int s_idx[2];

    const int b = blockIdx.x;
    const float* px = xyz + (size_t)b*3*NPT;
    const float* py = px + NPT;
    const float* pz = py + NPT;

    for (int n = t; n < NPT; n += 512) { sx[n]=px[n]; sy[n]=py[n]; sz[n]=pz[n]; }
    if (t == 0) s_idx[0] = 0;
    __syncthreads();

    ull xp[16], yp[16];
    float dist[32];
    #pragma unroll
    for (int i = 0; i < 16; i++) {
        int p = t + (i << 9);
        xp[i] = *(const ull*)&sx[2*p];
        yp[i] = *(const ull*)&sy[2*p];
        dist[2*i] = 1e10f; dist[2*i+1] = 1e10f;
    }

    const int lane = t & 31;
    for (int s = 0; s < SPT; s++) {
        int far = s_idx[s & 1];
        float cx = sx[far], cy = sy[far], cz = sz[far];
        if (t == 0) {
            g_fpsidx[b*SPT + s] = far;
            g_newptr[b*SPT + s] = idx[b*NPT + far];
            g_newxyz[(b*SPT + s)*3 + 0] = cx;
            g_newxyz[(b*SPT + s)*3 + 1] = cy;
            g_newxyz[(b*SPT + s)*3 + 2] = cz;
            out_xyz[(b*3 + 0)*SPT + s] = cx;
            out_xyz[(b*3 + 1)*SPT + s] = cy;
            out_xyz[(b*3 + 2)*SPT + s] = cz;
            s_idx[(s + 1) & 1] = 0x7fffffff;
        }
        if (s == SPT - 1) break;

        ull ncx = bcast2(-cx), ncy = bcast2(-cy), ncz = bcast2(-cz);
        float best = -1.f;
        #pragma unroll
        for (int i = 0; i < 16; i++) {
            int p = t + (i << 9);
            ull z2 = *(const ull*)&sz[2*p];
            ull dx2, dy2, dz2, m;
            ADD2(dx2, xp[i], ncx);
            ADD2(dy2, yp[i], ncy);
            ADD2(dz2, z2,    ncz);
            MUL2(m, dx2, dx2);
            FMA2(m, dy2, dy2, m);
            FMA2(m, dz2, dz2, m);
            float d0 = fminf(dist[2*i],   lo2(m));
            float d1 = fminf(dist[2*i+1], hi2(m));
            dist[2*i] = d0; dist[2*i+1] = d1;
            best = fmaxf(best, d0);
            best = fmaxf(best, d1);
        }
        float wmax = best;
        #pragma unroll
        for (int o = 16; o > 0; o >>= 1)
            wmax = fmaxf(wmax, __shfl_xor_sync(0xffffffffu, wmax, o));
        if (lane == 0) redv[t >> 5] = wmax;
        __syncthreads();
        float vmax = redv[lane & 15];
        #pragma unroll
        for (int o = 8; o > 0; o >>= 1)
            vmax = fmaxf(vmax, __shfl_xor_sync(0xffffffffu, vmax, o));
        if (best == vmax) {
            int found = 0x7fffffff;
            #pragma unroll
            for (int i = 0; i < 16; i++) {
                int p2 = 2*(t + (i << 9));
                if (dist[2*i]   == vmax) found = min(found, p2);
                if (dist[2*i+1] == vmax) found = min(found, p2 + 1);
            }
            atomicMin(&s_idx[(s + 1) & 1], found);
        }
        __syncthreads();
    }
}

// ---------------- ball query: one warp per (b,s), packed float4 --------------
__global__ void __launch_bounds__(256)
ballquery_kernel() {
    int warp = (blockIdx.x * blockDim.x + threadIdx.x) >> 5;
    int lane = threadIdx.x & 31;
    if (warp >= B_*SPT) return;
    int b = warp / SPT;
    float cx = g_newxyz[warp*3+0], cy = g_newxyz[warp*3+1], cz = g_newxyz[warp*3+2];
    int np = g_newptr[warp];
    float cn = cx*cx + cy*cy + cz*cz;
    const float4* pk = g_pk + (size_t)b*NPT;
    int* gout = g_gid + (size_t)warp*NS;

    int cnt = 0, first = -1;
    for (int n0 = 0; n0 < NPT && cnt < NS; n0 += 128) {
        float4 vv[4];
        #pragma unroll
        for (int sb = 0; sb < 4; sb++) vv[sb] = pk[n0 + sb*32 + lane];
        #pragma unroll
        for (int sb = 0; sb < 4; sb++) {
            int n = n0 + sb*32 + lane;
            float x = vv[sb].x, y = vv[sb].y, z = vv[sb].z;
            float pn = x*x + y*y + z*z;
            float sq = cn + pn - 2.f*(cx*x + cy*y + cz*z);
            bool hit = !(sq > RR2) && (__float_as_int(vv[sb].w) == np);
            unsigned m = __ballot_sync(0xffffffffu, hit);
            if (m) {
                if (first < 0) first = n0 + sb*32 + __ffs(m) - 1;
                int pos = cnt + __popc(m & ((1u << lane) - 1));
                if (hit && pos < NS) gout[pos] = n;
                cnt += __popc(m);
                if (cnt > NS) cnt = NS;
            }
        }
    }
    if (first < 0) { first = g_fpsidx[warp]; }
    if (cnt == 0) { if (lane == 0) gout[0] = first; cnt = 1; }
    for (int p = cnt + lane; p < NS; p += 32) gout[p] = first;
}

// ---------------- bf16 mma helpers -------------------------------------------
#define MMAB(d, a, b) asm volatile( \
    "mma.sync.aligned.m16n8k16.row.col.f32.bf16.bf16.f32 " \
    "{%0,%1,%2,%3},{%4,%5,%6,%7},{%8,%9},{%0,%1,%2,%3};\n" \
    : "+f"(d[0]), "+f"(d[1]), "+f"(d[2]), "+f"(d[3]) \
    : "r"(a[0]), "r"(a[1]), "r"(a[2]), "r"(a[3]), "r"(b[0]), "r"(b[1]))

// ---------------- one K-chunk : load A (split / gather for L0), copy W, mma --
template<int KS16, int LAYER>
__device__ __forceinline__ void do_chunk(
    const float* __restrict__ A, const float* __restrict__ xyz, size_t m0, int kc,
    const float* sc, const float* sh,
    const uint* __restrict__ Wfh, const uint* __restrict__ Wfl, int wfbase,
    uint* Ah, uint* Al, uint* Bh, uint* Bl,
    int t, int lane, int w, int wc, float acc[2][8][4])
{
    constexpr int KP = 128;               // layers 1,2 row stride
    constexpr int CW = KS16 * 4;          // float4 per row this chunk

    if (LAYER == 0) {
        const int bb = (int)(m0 >> 16);
        if (KS16 == 4) {
            for (int i = t; i < 128*16; i += 256) {
                int r = i >> 4, c4 = i & 15;
                int g = g_gid[m0 + r];
                float4 v = *(const float4*)&g_ptsT[((size_t)bb*NPT + g)*DD + c4*4];
                frag_store4(Ah, Al, r, c4, v);
            }
        } else {
            const float* px = xyz + (size_t)bb*3*NPT;
            for (int i = t; i < 128*4; i += 256) {
                int r = i >> 2, c4 = i & 3;
                float4 v = make_float4(0.f, 0.f, 0.f, 0.f);
                if (c4 == 0) {
                    int g = g_gid[m0 + r];
                    int bs = (int)((m0 + r) >> 6);
                    v = make_float4(px[g]        - g_newxyz[bs*3+0],
                                    px[NPT+g]    - g_newxyz[bs*3+1],
                                    px[2*NPT+g]  - g_newxyz[bs*3+2], 0.f);
                }
                frag_store4(Ah, Al, r, c4, v);
            }
        }
    } else {
        for (int i = t; i < 128*CW; i += 256) {
            int r = i / CW, c4 = i - r*CW;
            float4 v = *(const float4*)&A[(m0 + r)*KP + kc + c4*4];
            int ch = kc + c4*4;
            v.x = fmaxf(0.f, fmaf(sc[ch+0], v.x, sh[ch+0]));
            v.y = fmaxf(0.f, fmaf(sc[ch+1], v.y, sh[ch+1]));
            v.z = fmaxf(0.f, fmaf(sc[ch+2], v.z, sh[ch+2]));
            v.w = fmaxf(0.f, fmaf(sc[ch+3], v.w, sh[ch+3]));
            frag_store4(Ah, Al, r, c4, v);
        }
    }
    {
        const uint4* shp = (const uint4*)(Wfh + wfbase);
        const uint4* slp = (const uint4*)(Wfl + wfbase);
        for (int i = t; i < KS16*256; i += 256) {
            ((uint4*)Bh)[i] = shp[i];
            ((uint4*)Bl)[i] = slp[i];
        }
    }
    __syncthreads();

    #pragma unroll
    for (int kstep = 0; kstep < KS16; kstep++) {
        uint ah[2][4], al[2][4];
        #pragma unroll
        for (int mb = 0; mb < 2; mb++) {
            int base = ((kstep*8 + (w & 3)*2 + mb)*32 + lane)*4;
            uint4 vh = *(const uint4*)&Ah[base];
            uint4 vl = *(const uint4*)&Al[base];
            ah[mb][0]=vh.x; ah[mb][1]=vh.y; ah[mb][2]=vh.z; ah[mb][3]=vh.w;
            al[mb][0]=vl.x; al[mb][1]=vl.y; al[mb][2]=vl.z; al[mb][3]=vl.w;
        }
        #pragma unroll
        for (int nf = 0; nf < 8; nf++) {
            int baseb = ((kstep*16 + (wc >> 3) + nf)*32 + lane)*2;
            uint2 bhv = *(const uint2*)&Bh[baseb];
            uint2 blv = *(const uint2*)&Bl[baseb];
            uint bh[2] = {bhv.x, bhv.y};
            uint bl[2] = {blv.x, blv.y};
            #pragma unroll
            for (int mb = 0; mb < 2; mb++) {
                MMAB(acc[mb][nf], ah[mb], bh);
                MMAB(acc[mb][nf], al[mb], bh);
                MMAB(acc[mb][nf], ah[mb], bl);
            }
        }
    }
    __syncthreads();
}

// ---------------- bf16x3 GEMM: Y = act(A) * W^T, fused BN-coef + stats -------
#define GSM (16640 * 4)   // 64KB tiles + 1KB scale/shift
template<int LAYER>
__global__ void __launch_bounds__(256, 2)
gemm_tc(const float* __restrict__ xyz,
        const float* __restrict__ gprev, const float* __restrict__ beprev,
        int otile) {
    const float* A = (LAYER == 1) ? g_y1 : g_y2;   // unused for LAYER==0
    float*       Y = (LAYER == 0) ? g_y1 : g_y2;
    const uint* Wfh = (LAYER == 0) ? g_wf0h : ((LAYER == 1) ? g_wf1h : g_wf2h);
    const uint* Wfl = (LAYER == 0) ? g_wf0l : ((LAYER == 1) ? g_wf1l : g_wf2l);

    extern __shared__ uint usm[];
    uint* Ah = usm;              // 4096 each
    uint* Al = usm + 4096;
    uint* Bh = usm + 8192;
    uint* Bl = usm + 12288;
    float* scs = (float*)(usm + 16384);   // 128
    float* shs = (float*)(usm + 16512);   // 128

    const int t = threadIdx.x;
    const int lane = t & 31, w = t >> 5;
    const int wr = (w & 3) * 32, wc = (w >> 2) * 64;
    const size_t m0 = (size_t)blockIdx.x * 128;
    const int o0 = otile * 128;

    // in-kernel BN finalize for previous layer (layers 1,2)
    if (LAYER > 0 && t < 128) {
        float s, sh;
        bn_coef(LAYER - 1, t, gprev, beprev, s, sh);
        scs[t] = s; shs[t] = sh;
    }
    __syncthreads();

    float acc[2][8][4];
    #pragma unroll
    for (int mb = 0; mb < 2; mb++)
        #pragma unroll
        for (int nf = 0; nf < 8; nf++)
            #pragma unroll
            for (int c = 0; c < 4; c++) acc[mb][nf][c] = 0.f;

    int wb0 = (LAYER == 2) ? (otile*8)*1024 : 0;
    do_chunk<4, LAYER>(A, xyz, m0, 0, scs, shs, Wfh, Wfl, wb0, Ah, Al, Bh, Bl, t, lane, w, wc, acc);
    if (LAYER == 0)
        do_chunk<1, LAYER>(A, xyz, m0, 64, scs, shs, Wfh, Wfl, 4*1024, Ah, Al, Bh, Bl, t, lane, w, wc, acc);
    else
        do_chunk<4, LAYER>(A, xyz, m0, 64, scs, shs, Wfh, Wfl, wb0 + 4*1024, Ah, Al, Bh, Bl, t, lane, w, wc, acc);

    // ---- epilogue: store Y (layers 0,1) ----
    if (LAYER < 2) {
        #pragma unroll
        for (int mb = 0; mb < 2; mb++)
            #pragma unroll
            for (int h = 0; h < 2; h++) {
                size_t row = m0 + wr + mb*16 + (lane >> 2) + h*8;
                float* yr = &Y[row*128 + wc + (lane & 3)*2];
                #pragma unroll
                for (int nf = 0; nf < 8; nf++)
                    *(float2*)&yr[nf*8] = make_float2(acc[mb][nf][h*2], acc[mb][nf][h*2+1]);
            }
    }

    // ---- per-column partial stats, and max/min for LAYER 2 ----
    float csum[8][2], csq[8][2];
    #pragma unroll
    for (int nf = 0; nf < 8; nf++)
        #pragma unroll
        for (int j = 0; j < 2; j++) { csum[nf][j] = 0.f; csq[nf][j] = 0.f; }
    float cmx[8][2], cmn[8][2];
    if (LAYER == 2) {
        #pragma unroll
        for (int nf = 0; nf < 8; nf++)
            #pragma unroll
            for (int j = 0; j < 2; j++) { cmx[nf][j] = -3.4e38f; cmn[nf][j] = 3.4e38f; }
    }
    #pragma unroll
    for (int mb = 0; mb < 2; mb++)
        #pragma unroll
        for (int nf = 0; nf < 8; nf++)
            #pragma unroll
            for (int c = 0; c < 4; c++) {
                int j = c & 1;
                float v = acc[mb][nf][c];
                csum[nf][j] += v;
                csq[nf][j] = fmaf(v, v, csq[nf][j]);
                if (LAYER == 2) {
                    cmx[nf][j] = fmaxf(cmx[nf][j], v);
                    cmn[nf][j] = fminf(cmn[nf][j], v);
                }
            }

    float* red = (float*)usm;   // [4][128]
    #pragma unroll
    for (int nf = 0; nf < 8; nf++)
        #pragma unroll
        for (int j = 0; j < 2; j++) {
            float v = csum[nf][j];
            #pragma unroll
            for (int o = 4; o < 32; o <<= 1) v += __shfl_xor_sync(0xffffffffu, v, o);
            if (lane < 4) red[(w & 3)*128 + wc + nf*8 + lane*2 + j] = v;
        }
    __syncthreads();
    if (t < 128) {
        float s = red[t] + red[128 + t] + red[256 + t] + red[384 + t];
        atomicAdd(&g_sum[LAYER*256 + o0 + t], s);
    }
    __syncthreads();
    #pragma unroll
    for (int nf = 0; nf < 8; nf++)
        #pragma unroll
        for (int j = 0; j < 2; j++) {
            float v = csq[nf][j];
            #pragma unroll
            for (int o = 4; o < 32; o <<= 1) v += __shfl_xor_sync(0xffffffffu, v, o);
            if (lane < 4) red[(w & 3)*128 + wc + nf*8 + lane*2 + j] = v;
        }
    __syncthreads();
    if (t < 128) {
        float s = red[t] + red[128 + t] + red[256 + t] + red[384 + t];
        atomicAdd(&g_sqs[LAYER*256 + o0 + t], s);
    }

    if (LAYER == 2) {
        __syncthreads();
        #pragma unroll
        for (int nf = 0; nf < 8; nf++)
            #pragma unroll
            for (int j = 0; j < 2; j++) {
                float v = cmx[nf][j];
                #pragma unroll
                for (int o = 4; o < 32; o <<= 1) v = fmaxf(v, __shfl_xor_sync(0xffffffffu, v, o));
                if (lane < 4) red[(w & 3)*128 + wc + nf*8 + lane*2 + j] = v;
            }
        __syncthreads();
        if (t < 256) {
            int g = t >> 7, col = t & 127;
            float v = fmaxf(red[(2*g)*128 + col], red[(2*g + 1)*128 + col]);
            g_mx[((size_t)(2*blockIdx.x + g))*256 + o0 + col] = v;
        }
        __syncthreads();
        #pragma unroll
        for (int nf = 0; nf < 8; nf++)
            #pragma unroll
            for (int j = 0; j < 2; j++) {
                float v = cmn[nf][j];
                #pragma unroll
                for (int o = 4; o < 32; o <<= 1) v = fminf(v, __shfl_xor_sync(0xffffffffu, v, o));
                if (lane < 4) red[(w & 3)*128 + wc + nf*8 + lane*2 + j] = v;
            }
        __syncthreads();
        if (t < 256) {
            int g = t >> 7, col = t & 127;
            float v = fminf(red[(2*g)*128 + col], red[(2*g + 1)*128 + col]);
            g_mn[((size_t)(2*blockIdx.x + g))*256 + o0 + col] = v;
        }
    }
}

// ---------------- final: BN3 (in-kernel coef) + relu on extremum, transpose --
__global__ void final_out_kernel(const float* __restrict__ g2,
                                 const float* __restrict__ be2,
                                 float* __restrict__ out_feat) {
    __shared__ float tile[32][33];
    int bs0 = blockIdx.x * 32, c0 = blockIdx.y * 32;
    int tx = threadIdx.x, ty = threadIdx.y;   // 32 x 8
    float s, shv;
    bn_coef(2, c0 + tx, g2, be2, s, shv);
    #pragma unroll
    for (int j = 0; j < 32; j += 8) {
        int bs = bs0 + ty + j;
        float mx = g_mx[(size_t)bs*256 + c0 + tx];
        float mn = g_mn[(size_t)bs*256 + c0 + tx];
        float e = (s >= 0.f) ? mx : mn;
        tile[ty + j][tx] = fmaxf(0.f, fmaf(s, e, shv));
    }
    __syncthreads();
    int b = bs0 >> 10, sl = bs0 & 1023;
    #pragma unroll
    for (int j = 0; j < 32; j += 8)
        out_feat[((size_t)(b*256 + c0 + ty + j))*1024 + sl + tx] = tile[tx][ty + j];
}

// ---------------- launcher ---------------------------------------------------
extern "C" void kernel_launch(void* const* d_in, const int* in_sizes, int n_in,
                              void* d_out, int out_size) {
    const float* xyz = (const float*)d_in[0];
    const float* pts = (const float*)d_in[1];
    const int*   idx = (const int*)d_in[2];
    const float* w0  = (const float*)d_in[3];
    const float* g0  = (const float*)d_in[5];
    const float* be0 = (const float*)d_in[6];
    const float* w1  = (const float*)d_in[7];
    const float* g1  = (const float*)d_in[9];
    const float* be1 = (const float*)d_in[10];
    const float* w2  = (const float*)d_in[11];
    const float* g2  = (const float*)d_in[13];
    const float* be2 = (const float*)d_in[14];

    float* out      = (float*)d_out;
    float* out_xyz  = out;                       // [B,3,SPT]
    float* out_feat = out + (size_t)B_*3*SPT;    // [B,256,SPT]

    cudaFuncSetAttribute(front_kernel, cudaFuncAttributeMaxDynamicSharedMemorySize, FPS_SMEM);
    cudaFuncSetAttribute(gemm_tc<0>, cudaFuncAttributeMaxDynamicSharedMemorySize, GSM);
    cudaFuncSetAttribute(gemm_tc<1>, cudaFuncAttributeMaxDynamicSharedMemorySize, GSM);
    cudaFuncSetAttribute(gemm_tc<2>, cudaFuncAttributeMaxDynamicSharedMemorySize, GSM);

    front_kernel<<<8 + NTRB, 512, FPS_SMEM>>>(xyz, idx, pts, w0, w1, w2, out_xyz);
    ballquery_kernel<<<(B_*SPT)/8, 256>>>();

    gemm_tc<0><<<MTOT/128, 256, GSM>>>(xyz, (const float*)0, (const float*)0, 0);
    gemm_tc<1><<<MTOT/128, 256, GSM>>>(xyz, g0, be0, 0);
    gemm_tc<2><<<MTOT/128, 256, GSM>>>(xyz, g1, be1, 0);
    gemm_tc<2><<<MTOT/128, 256, GSM>>>(xyz, g1, be1, 1);   // launch #6 -> ncu capture

    final_out_kernel<<<dim3(NGRP/32, 256/32), dim3(32, 8)>>>(g2, be2, out_feat);
}

// round 13
// speedup vs baseline: 2.5932x; 1.0038x over previous
#include <cuda_runtime.h>
#include <cuda_bf16.h>
#include <math.h>

#define B_ 8
#define NPT 16384
#define SPT 1024
#define NS 64
#define DD 64
#define C0 67
#define MTOT (B_*SPT*NS)      // 524288
#define NGRP (MTOT/NS)        // 8192
#define RR2 0.09f
#define EPSV 1e-5f

typedef unsigned long long ull;
typedef unsigned uint;

// ---------------- scratch (static device globals; no allocation) -------------
__device__ __align__(16) float g_ptsT[(size_t)B_*NPT*DD];       // 33.5 MB
__device__ __align__(16) float4 g_pk[(size_t)B_*NPT];           // 2 MB packed xyz+id
__device__ float g_newxyz[B_*SPT*3];
__device__ int   g_fpsidx[B_*SPT];
__device__ int   g_newptr[B_*SPT];
__device__ int   g_gid[B_*SPT*NS];
__device__ __align__(16) float g_y1[(size_t)MTOT*128];          // 268 MB
__device__ __align__(16) float g_y2[(size_t)MTOT*128];          // 268 MB
__device__ __align__(16) float g_mx[(size_t)NGRP*256];          // 8 MB
__device__ __align__(16) float g_mn[(size_t)NGRP*256];          // 8 MB
__device__ float g_sum[3*256];
__device__ float g_sqs[3*256];
// weights pre-split (bf16 hi/lo) packed in m16n8k16 B-fragment layout
#define W0WORDS (5*1024)      // KP=80: 5 ksteps
#define W1WORDS (8*1024)      // KP=128
#define W2WORDS (2*8*1024)    // 2 otiles
#define TOTALW (W0WORDS + W1WORDS + W2WORDS)
__device__ __align__(16) uint g_wf0h[W0WORDS], g_wf0l[W0WORDS];
__device__ __align__(16) uint g_wf1h[W1WORDS], g_wf1l[W1WORDS];
__device__ __align__(16) uint g_wf2h[W2WORDS], g_wf2l[W2WORDS];

// ---------------- f32x2 packed helpers ---------------------------------------
#define ADD2(o, a, b) asm("add.rn.f32x2 %0, %1, %2;" : "=l"(o) : "l"(a), "l"(b))
#define MUL2(o, a, b) asm("mul.rn.f32x2 %0, %1, %2;" : "=l"(o) : "l"(a), "l"(b))
#define FMA2(o, a, b, c) asm("fma.rn.f32x2 %0, %1, %2, %3;" : "=l"(o) : "l"(a), "l"(b), "l"(c))

__device__ __forceinline__ ull bcast2(float v) {
    unsigned u = __float_as_uint(v);
    return ((ull)u << 32) | (ull)u;
}
__device__ __forceinline__ float lo2(ull m) { return __uint_as_float((unsigned)m); }
__device__ __forceinline__ float hi2(ull m) { return __uint_as_float((unsigned)(m >> 32)); }

__device__ __forceinline__ uint pk_bf2(float a, float b) {
    uint r;
    asm("cvt.rn.bf16x2.f32 %0, %1, %2;" : "=r"(r) : "f"(b), "f"(a));
    return r;
}
__device__ __forceinline__ void split2(float v0, float v1, uint& wh, uint& wl) {
    wh = pk_bf2(v0, v1);
    __nv_bfloat162 h2 = *(__nv_bfloat162*)&wh;
    float h0 = __bfloat162float(h2.x), h1 = __bfloat162float(h2.y);
    wl = pk_bf2(v0 - h0, v1 - h1);
}

// BN finalize formula (gemm preamble + final_out); bit-identical both places
__device__ __forceinline__ void bn_coef(int layer, int c,
                                        const float* __restrict__ gamma,
                                        const float* __restrict__ beta,
                                        float& s, float& sh) {
    const float invM = 1.f / (float)MTOT;
    float mu  = g_sum[layer*256 + c] * invM;
    float var = g_sqs[layer*256 + c] * invM - mu*mu;
    if (var < 0.f) var = 0.f;
    s  = gamma[c] * rsqrtf(var + EPSV);
    sh = fmaf(-mu, s, beta[c]);
}

// store float4 (row r in 0..63, chunk-local col base = c4*4) into A frag smem
// layout: [kst][mb=r>>4 (4 blocks)][lane][reg]
__device__ __forceinline__ void frag_store4(uint* Ah, uint* Al, int r, int c4, float4 v) {
    int r16 = r & 15, mb = r >> 4;
    int kk0 = (c4*4) & 15, kst = (c4*4) >> 4;
    int reg = (r16 >> 3) + ((kk0 >> 3) << 1);
    int l0  = ((r16 & 7) << 2) | ((kk0 >> 1) & 3);
    int i0  = ((kst*4 + mb)*32 + l0)*4 + reg;
    uint wh, wl;
    split2(v.x, v.y, wh, wl);
    Ah[i0] = wh; Al[i0] = wl;
    split2(v.z, v.w, wh, wl);
    Ah[i0 + 4] = wh; Al[i0 + 4] = wl;
}

// ---------------- FRONT: fps (blocks 0..7) + prep/transpose (blocks 8+) ------
#define FPS_SMEM ((3*NPT + 64) * 4)
#define NTRB 4096   // transpose blocks (2 tiles each -> 8192 tiles)
__global__ void __launch_bounds__(512, 1)
front_kernel(const float* __restrict__ xyz, const int* __restrict__ idx,
             const float* __restrict__ pts,
             const float* __restrict__ w0, const float* __restrict__ w1,
             const float* __restrict__ w2,
             float* __restrict__ out_xyz) {
    extern __shared__ float fsm[];
    const int t = threadIdx.x;

    if (blockIdx.x >= 8) {
        int bid = blockIdx.x - 8;
        int gi = bid*512 + t;
        if (gi < 768) { g_sum[gi] = 0.f; g_sqs[gi] = 0.f; }
        if (gi < B_*NPT) {
            int b = gi >> 14, n = gi & (NPT-1);
            const float* px = xyz + (size_t)b*3*NPT;
            g_pk[gi] = make_float4(px[n], px[NPT+n], px[2*NPT+n], __int_as_float(idx[gi]));
        }
        if (gi < TOTALW) {
            int layer, j, otile = 0;
            if (gi < W0WORDS) { layer = 0; j = gi; }
            else if (gi < W0WORDS + W1WORDS) { layer = 1; j = gi - W0WORDS; }
            else { layer = 2; j = gi - W0WORDS - W1WORDS; otile = j >> 13; j &= 8191; }
            int reg = j & 1, ln = (j >> 1) & 31, nb = (j >> 6) & 15, ksg = j >> 10;
            int o  = otile*128 + nb*8 + (ln >> 2);
            int c0 = ksg*16 + reg*8 + (ln & 3)*2;
            float v0, v1;
            if (layer == 0) {
                int s0 = (c0   < 64) ? (c0   + 3) : (c0   - 64);
                int s1 = (c0+1 < 64) ? (c0+1 + 3) : (c0+1 - 64);
                v0 = (c0   < C0) ? w0[o*C0 + s0] : 0.f;
                v1 = (c0+1 < C0) ? w0[o*C0 + s1] : 0.f;
            } else if (layer == 1) {
                v0 = w1[o*128 + c0]; v1 = w1[o*128 + c0 + 1];
            } else {
                v0 = w2[o*128 + c0]; v1 = w2[o*128 + c0 + 1];
            }
            uint wh, wl;
            split2(v0, v1, wh, wl);
            if (layer == 0)      { g_wf0h[j] = wh; g_wf0l[j] = wl; }
            else if (layer == 1) { g_wf1h[j] = wh; g_wf1l[j] = wl; }
            else { int k2 = (otile << 13) | j; g_wf2h[k2] = wh; g_wf2l[k2] = wl; }
        }
        int tile_id = bid*2 + (t >> 8);
        int sub = t & 255, tx = sub & 31, ty = sub >> 5;   // 32 x 8
        int bx = tile_id & 511, byz = tile_id >> 9;
        int by = byz & 1, bz = byz >> 1;
        int n0 = bx * 32, c0 = by * 32;
        float* tb = fsm + (t >> 8) * 1088;
        #pragma unroll
        for (int j = 0; j < 32; j += 8)
            tb[(ty + j)*33 + tx] = pts[((size_t)bz*DD + c0 + ty + j)*NPT + n0 + tx];
        __syncthreads();
        #pragma unroll
        for (int j = 0; j < 32; j += 8)
            g_ptsT[((size_t)bz*NPT + n0 + ty + j)*DD + c0 + tx] = tb[tx*33 + ty + j];
        return;
    }

    // ===================== FPS role =====================
    float* sx = fsm;
    float* sy = sx + NPT;
    float* sz = sy + NPT;
    float* redv = sz + NPT;
    __shared__ int s_idx[2];

    const int b = blockIdx.x;
    const float* px = xyz + (size_t)b*3*NPT;
    const float* py = px + NPT;
    const float* pz = py + NPT;

    for (int n = t; n < NPT; n += 512) { sx[n]=px[n]; sy[n]=py[n]; sz[n]=pz[n]; }
    if (t == 0) s_idx[0] = 0;
    __syncthreads();

    ull xp[16], yp[16];
    float dist[32];
    #pragma unroll
    for (int i = 0; i < 16; i++) {
        int p = t + (i << 9);
        xp[i] = *(const ull*)&sx[2*p];
        yp[i] = *(const ull*)&sy[2*p];
        dist[2*i] = 1e10f; dist[2*i+1] = 1e10f;
    }

    const int lane = t & 31;
    for (int s = 0; s < SPT; s++) {
        int far = s_idx[s & 1];
        float cx = sx[far], cy = sy[far], cz = sz[far];
        if (t == 0) {
            g_fpsidx[b*SPT + s] = far;
            g_newptr[b*SPT + s] = idx[b*NPT + far];
            g_newxyz[(b*SPT + s)*3 + 0] = cx;
            g_newxyz[(b*SPT + s)*3 + 1] = cy;
            g_newxyz[(b*SPT + s)*3 + 2] = cz;
            out_xyz[(b*3 + 0)*SPT + s] = cx;
            out_xyz[(b*3 + 1)*SPT + s] = cy;
            out_xyz[(b*3 + 2)*SPT + s] = cz;
            s_idx[(s + 1) & 1] = 0x7fffffff;
        }
        if (s == SPT - 1) break;

        ull ncx = bcast2(-cx), ncy = bcast2(-cy), ncz = bcast2(-cz);
        float best = -1.f;
        #pragma unroll
        for (int i = 0; i < 16; i++) {
            int p = t + (i << 9);
            ull z2 = *(const ull*)&sz[2*p];
            ull dx2, dy2, dz2, m;
            ADD2(dx2, xp[i], ncx);
            ADD2(dy2, yp[i], ncy);
            ADD2(dz2, z2,    ncz);
            MUL2(m, dx2, dx2);
            FMA2(m, dy2, dy2, m);
            FMA2(m, dz2, dz2, m);
            float d0 = fminf(dist[2*i],   lo2(m));
            float d1 = fminf(dist[2*i+1], hi2(m));
            dist[2*i] = d0; dist[2*i+1] = d1;
            best = fmaxf(best, d0);
            best = fmaxf(best, d1);
        }
        float wmax = best;
        #pragma unroll
        for (int o = 16; o > 0; o >>= 1)
            wmax = fmaxf(wmax, __shfl_xor_sync(0xffffffffu, wmax, o));
        if (lane == 0) redv[t >> 5] = wmax;
        __syncthreads();
        float vmax = redv[lane & 15];
        #pragma unroll
        for (int o = 8; o > 0; o >>= 1)
            vmax = fmaxf(vmax, __shfl_xor_sync(0xffffffffu, vmax, o));
        if (best == vmax) {
            int found = 0x7fffffff;
            #pragma unroll
            for (int i = 0; i < 16; i++) {
                int p2 = 2*(t + (i << 9));
                if (dist[2*i]   == vmax) found = min(found, p2);
                if (dist[2*i+1] == vmax) found = min(found, p2 + 1);
            }
            atomicMin(&s_idx[(s + 1) & 1], found);
        }
        __syncthreads();
    }
}

// ---------------- ball query: one warp per (b,s), packed float4 --------------
__global__ void __launch_bounds__(256)
ballquery_kernel() {
    int warp = (blockIdx.x * blockDim.x + threadIdx.x) >> 5;
    int lane = threadIdx.x & 31;
    if (warp >= B_*SPT) return;
    int b = warp / SPT;
    float cx = g_newxyz[warp*3+0], cy = g_newxyz[warp*3+1], cz = g_newxyz[warp*3+2];
    int np = g_newptr[warp];
    float cn = cx*cx + cy*cy + cz*cz;
    const float4* pk = g_pk + (size_t)b*NPT;
    int* gout = g_gid + (size_t)warp*NS;

    int cnt = 0, first = -1;
    for (int n0 = 0; n0 < NPT && cnt < NS; n0 += 128) {
        float4 vv[4];
        #pragma unroll
        for (int sb = 0; sb < 4; sb++) vv[sb] = pk[n0 + sb*32 + lane];
        #pragma unroll
        for (int sb = 0; sb < 4; sb++) {
            int n = n0 + sb*32 + lane;
            float x = vv[sb].x, y = vv[sb].y, z = vv[sb].z;
            float pn = x*x + y*y + z*z;
            float sq = cn + pn - 2.f*(cx*x + cy*y + cz*z);
            bool hit = !(sq > RR2) && (__float_as_int(vv[sb].w) == np);
            unsigned m = __ballot_sync(0xffffffffu, hit);
            if (m) {
                if (first < 0) first = n0 + sb*32 + __ffs(m) - 1;
                int pos = cnt + __popc(m & ((1u << lane) - 1));
                if (hit && pos < NS) gout[pos] = n;
                cnt += __popc(m);
                if (cnt > NS) cnt = NS;
            }
        }
    }
    if (first < 0) { first = g_fpsidx[warp]; }
    if (cnt == 0) { if (lane == 0) gout[0] = first; cnt = 1; }
    for (int p = cnt + lane; p < NS; p += 32) gout[p] = first;
}

// ---------------- bf16 mma helpers -------------------------------------------
#define MMAB(d, a, b) asm volatile( \
    "mma.sync.aligned.m16n8k16.row.col.f32.bf16.bf16.f32 " \
    "{%0,%1,%2,%3},{%4,%5,%6,%7},{%8,%9},{%0,%1,%2,%3};\n" \
    : "+f"(d[0]), "+f"(d[1]), "+f"(d[2]), "+f"(d[3]) \
    : "r"(a[0]), "r"(a[1]), "r"(a[2]), "r"(a[3]), "r"(b[0]), "r"(b[1]))

// ---------------- one K-chunk (CTA tile 64x128, 128 threads) -----------------
template<int KS16, int LAYER>
__device__ __forceinline__ void do_chunk(
    const float* __restrict__ A, const float* __restrict__ xyz, size_t m0, int kc,
    const float* sc, const float* sh,
    const uint* __restrict__ Wfh, const uint* __restrict__ Wfl, int wfbase,
    uint* Ah, uint* Al, uint* Bh, uint* Bl,
    int t, int lane, int w, int wc, float acc[2][8][4])
{
    constexpr int KP = 128;
    constexpr int CW = KS16 * 4;

    if (LAYER == 0) {
        const int bb = (int)(m0 >> 16);
        if (KS16 == 4) {
            for (int i = t; i < 64*16; i += 128) {
                int r = i >> 4, c4 = i & 15;
                int g = g_gid[m0 + r];
                float4 v = *(const float4*)&g_ptsT[((size_t)bb*NPT + g)*DD + c4*4];
                frag_store4(Ah, Al, r, c4, v);
            }
        } else {
            const float* px = xyz + (size_t)bb*3*NPT;
            for (int i = t; i < 64*4; i += 128) {
                int r = i >> 2, c4 = i & 3;
                float4 v = make_float4(0.f, 0.f, 0.f, 0.f);
                if (c4 == 0) {
                    int g = g_gid[m0 + r];
                    int bs = (int)((m0 + r) >> 6);
                    v = make_float4(px[g]        - g_newxyz[bs*3+0],
                                    px[NPT+g]    - g_newxyz[bs*3+1],
                                    px[2*NPT+g]  - g_newxyz[bs*3+2], 0.f);
                }
                frag_store4(Ah, Al, r, c4, v);
            }
        }
    } else {
        for (int i = t; i < 64*CW; i += 128) {
            int r = i / CW, c4 = i - r*CW;
            float4 v = *(const float4*)&A[(m0 + r)*KP + kc + c4*4];
            int ch = kc + c4*4;
            v.x = fmaxf(0.f, fmaf(sc[ch+0], v.x, sh[ch+0]));
            v.y = fmaxf(0.f, fmaf(sc[ch+1], v.y, sh[ch+1]));
            v.z = fmaxf(0.f, fmaf(sc[ch+2], v.z, sh[ch+2]));
            v.w = fmaxf(0.f, fmaf(sc[ch+3], v.w, sh[ch+3]));
            frag_store4(Ah, Al, r, c4, v);
        }
    }
    {
        const uint4* shp = (const uint4*)(Wfh + wfbase);
        const uint4* slp = (const uint4*)(Wfl + wfbase);
        for (int i = t; i < KS16*256; i += 128) {
            ((uint4*)Bh)[i] = shp[i];
            ((uint4*)Bl)[i] = slp[i];
        }
    }
    __syncthreads();

    #pragma unroll
    for (int kstep = 0; kstep < KS16; kstep++) {
        uint ah[2][4], al[2][4];
        #pragma unroll
        for (int mb = 0; mb < 2; mb++) {
            int base = ((kstep*4 + (w & 1)*2 + mb)*32 + lane)*4;
            uint4 vh = *(const uint4*)&Ah[base];
            uint4 vl = *(const uint4*)&Al[base];
            ah[mb][0]=vh.x; ah[mb][1]=vh.y; ah[mb][2]=vh.z; ah[mb][3]=vh.w;
            al[mb][0]=vl.x; al[mb][1]=vl.y; al[mb][2]=vl.z; al[mb][3]=vl.w;
        }
        #pragma unroll
        for (int nf = 0; nf < 8; nf++) {
            int baseb = ((kstep*16 + (wc >> 3) + nf)*32 + lane)*2;
            uint2 bhv = *(const uint2*)&Bh[baseb];
            uint2 blv = *(const uint2*)&Bl[baseb];
            uint bh[2] = {bhv.x, bhv.y};
            uint bl[2] = {blv.x, blv.y};
            #pragma unroll
            for (int mb = 0; mb < 2; mb++) {
                MMAB(acc[mb][nf], ah[mb], bh);
                MMAB(acc[mb][nf], al[mb], bh);
                MMAB(acc[mb][nf], ah[mb], bl);
            }
        }
    }
    __syncthreads();
}

// ---------------- bf16x3 GEMM: CTA 64x128, 128 thr, 4 CTAs/SM ----------------
#define GSM ((12288 + 256) * 4)   // 48KB tiles + 1KB scale/shift
template<int LAYER>
__global__ void __launch_bounds__(128, 4)
gemm_tc(const float* __restrict__ xyz,
        const float* __restrict__ gprev, const float* __restrict__ beprev,
        int otile) {
    const float* A = (LAYER == 1) ? g_y1 : g_y2;   // unused for LAYER==0
    float*       Y = (LAYER == 0) ? g_y1 : g_y2;
    const uint* Wfh = (LAYER == 0) ? g_wf0h : ((LAYER == 1) ? g_wf1h : g_wf2h);
    const uint* Wfl = (LAYER == 0) ? g_wf0l : ((LAYER == 1) ? g_wf1l : g_wf2l);

    extern __shared__ uint usm[];
    uint* Ah = usm;              // 2048 words
    uint* Al = usm + 2048;
    uint* Bh = usm + 4096;       // 4096 words
    uint* Bl = usm + 8192;
    float* scs = (float*)(usm + 12288);   // 128
    float* shs = (float*)(usm + 12416);   // 128

    const int t = threadIdx.x;
    const int lane = t & 31, w = t >> 5;            // 4 warps
    const int wr = (w & 1) * 32, wc = (w >> 1) * 64;
    const size_t m0 = (size_t)blockIdx.x * 64;
    const int o0 = otile * 128;

    if (LAYER > 0) {
        float s, sh;
        bn_coef(LAYER - 1, t, gprev, beprev, s, sh);
        scs[t] = s; shs[t] = sh;
    }
    __syncthreads();

    float acc[2][8][4];
    #pragma unroll
    for (int mb = 0; mb < 2; mb++)
        #pragma unroll
        for (int nf = 0; nf < 8; nf++)
            #pragma unroll
            for (int c = 0; c < 4; c++) acc[mb][nf][c] = 0.f;

    int wb0 = (LAYER == 2) ? (otile*8)*1024 : 0;
    do_chunk<4, LAYER>(A, xyz, m0, 0, scs, shs, Wfh, Wfl, wb0, Ah, Al, Bh, Bl, t, lane, w, wc, acc);
    if (LAYER == 0)
        do_chunk<1, LAYER>(A, xyz, m0, 64, scs, shs, Wfh, Wfl, 4*1024, Ah, Al, Bh, Bl, t, lane, w, wc, acc);
    else
        do_chunk<4, LAYER>(A, xyz, m0, 64, scs, shs, Wfh, Wfl, wb0 + 4*1024, Ah, Al, Bh, Bl, t, lane, w, wc, acc);

    // ---- epilogue: store Y (layers 0,1) ----
    if (LAYER < 2) {
        #pragma unroll
        for (int mb = 0; mb < 2; mb++)
            #pragma unroll
            for (int h = 0; h < 2; h++) {
                size_t row = m0 + wr + mb*16 + (lane >> 2) + h*8;
                float* yr = &Y[row*128 + wc + (lane & 3)*2];
                #pragma unroll
                for (int nf = 0; nf < 8; nf++)
                    *(float2*)&yr[nf*8] = make_float2(acc[mb][nf][h*2], acc[mb][nf][h*2+1]);
            }
    }

    // ---- per-column partial stats, and max/min for LAYER 2 ----
    float csum[8][2], csq[8][2];
    #pragma unroll
    for (int nf = 0; nf < 8; nf++)
        #pragma unroll
        for (int j = 0; j < 2; j++) { csum[nf][j] = 0.f; csq[nf][j] = 0.f; }
    float cmx[8][2], cmn[8][2];
    if (LAYER == 2) {
        #pragma unroll
        for (int nf = 0; nf < 8; nf++)
            #pragma unroll
            for (int j = 0; j < 2; j++) { cmx[nf][j] = -3.4e38f; cmn[nf][j] = 3.4e38f; }
    }
    #pragma unroll
    for (int mb = 0; mb < 2; mb++)
        #pragma unroll
        for (int nf = 0; nf < 8; nf++)
            #pragma unroll
            for (int c = 0; c < 4; c++) {
                int j = c & 1;
                float v = acc[mb][nf][c];
                csum[nf][j] += v;
                csq[nf][j] = fmaf(v, v, csq[nf][j]);
                if (LAYER == 2) {
                    cmx[nf][j] = fmaxf(cmx[nf][j], v);
                    cmn[nf][j] = fminf(cmn[nf][j], v);
                }
            }

    float* red = (float*)usm;   // [2][128] reuse
    #pragma unroll
    for (int nf = 0; nf < 8; nf++)
        #pragma unroll
        for (int j = 0; j < 2; j++) {
            float v = csum[nf][j];
            #pragma unroll
            for (int o = 4; o < 32; o <<= 1) v += __shfl_xor_sync(0xffffffffu, v, o);
            if (lane < 4) red[(w & 1)*128 + wc + nf*8 + lane*2 + j] = v;
        }
    __syncthreads();
    if (t < 128) atomicAdd(&g_sum[LAYER*256 + o0 + t], red[t] + red[128 + t]);
    __syncthreads();
    #pragma unroll
    for (int nf = 0; nf < 8; nf++)
        #pragma unroll
        for (int j = 0; j < 2; j++) {
            float v = csq[nf][j];
            #pragma unroll
            for (int o = 4; o < 32; o <<= 1) v += __shfl_xor_sync(0xffffffffu, v, o);
            if (lane < 4) red[(w & 1)*128 + wc + nf*8 + lane*2 + j] = v;
        }
    __syncthreads();
    if (t < 128) atomicAdd(&g_sqs[LAYER*256 + o0 + t], red[t] + red[128 + t]);

    if (LAYER == 2) {
        __syncthreads();
        #pragma unroll
        for (int nf = 0; nf < 8; nf++)
            #pragma unroll
            for (int j = 0; j < 2; j++) {
                float v = cmx[nf][j];
                #pragma unroll
                for (int o = 4; o < 32; o <<= 1) v = fmaxf(v, __shfl_xor_sync(0xffffffffu, v, o));
                if (lane < 4) red[(w & 1)*128 + wc + nf*8 + lane*2 + j] = v;
            }
        __syncthreads();
        if (t < 128)
            g_mx[((size_t)blockIdx.x)*256 + o0 + t] = fmaxf(red[t], red[128 + t]);
        __syncthreads();
        #pragma unroll
        for (int nf = 0; nf < 8; nf++)
            #pragma unroll
            for (int j = 0; j < 2; j++) {
                float v = cmn[nf][j];
                #pragma unroll
                for (int o = 4; o < 32; o <<= 1) v = fminf(v, __shfl_xor_sync(0xffffffffu, v, o));
                if (lane < 4) red[(w & 1)*128 + wc + nf*8 + lane*2 + j] = v;
            }
        __syncthreads();
        if (t < 128)
            g_mn[((size_t)blockIdx.x)*256 + o0 + t] = fminf(red[t], red[128 + t]);
    }
}

// ---------------- final: BN3 (in-kernel coef) + relu on extremum, transpose --
__global__ void final_out_kernel(const float* __restrict__ g2,
                                 const float* __restrict__ be2,
                                 float* __restrict__ out_feat) {
    __shared__ float tile[32][33];
    int bs0 = blockIdx.x * 32, c0 = blockIdx.y * 32;
    int tx = threadIdx.x, ty = threadIdx.y;   // 32 x 8
    float s, shv;
    bn_coef(2, c0 + tx, g2, be2, s, shv);
    #pragma unroll
    for (int j = 0; j < 32; j += 8) {
        int bs = bs0 + ty + j;
        float mx = g_mx[(size_t)bs*256 + c0 + tx];
        float mn = g_mn[(size_t)bs*256 + c0 + tx];
        float e = (s >= 0.f) ? mx : mn;
        tile[ty + j][tx] = fmaxf(0.f, fmaf(s, e, shv));
    }
    __syncthreads();
    int b = bs0 >> 10, sl = bs0 & 1023;
    #pragma unroll
    for (int j = 0; j < 32; j += 8)
        out_feat[((size_t)(b*256 + c0 + ty + j))*1024 + sl + tx] = tile[tx][ty + j];
}

// ---------------- launcher ---------------------------------------------------
extern "C" void kernel_launch(void* const* d_in, const int* in_sizes, int n_in,
                              void* d_out, int out_size) {
    const float* xyz = (const float*)d_in[0];
    const float* pts = (const float*)d_in[1];
    const int*   idx = (const int*)d_in[2];
    const float* w0  = (const float*)d_in[3];
    const float* g0  = (const float*)d_in[5];
    const float* be0 = (const float*)d_in[6];
    const float* w1  = (const float*)d_in[7];
    const float* g1  = (const float*)d_in[9];
    const float* be1 = (const float*)d_in[10];
    const float* w2  = (const float*)d_in[11];
    const float* g2  = (const float*)d_in[13];
    const float* be2 = (const float*)d_in[14];

    float* out      = (float*)d_out;
    float* out_xyz  = out;                       // [B,3,SPT]
    float* out_feat = out + (size_t)B_*3*SPT;    // [B,256,SPT]

    cudaFuncSetAttribute(front_kernel, cudaFuncAttributeMaxDynamicSharedMemorySize, FPS_SMEM);
    cudaFuncSetAttribute(gemm_tc<0>, cudaFuncAttributeMaxDynamicSharedMemorySize, GSM);
    cudaFuncSetAttribute(gemm_tc<1>, cudaFuncAttributeMaxDynamicSharedMemorySize, GSM);
    cudaFuncSetAttribute(gemm_tc<2>, cudaFuncAttributeMaxDynamicSharedMemorySize, GSM);

    front_kernel<<<8 + NTRB, 512, FPS_SMEM>>>(xyz, idx, pts, w0, w1, w2, out_xyz);
    ballquery_kernel<<<(B_*SPT)/8, 256>>>();

    gemm_tc<0><<<MTOT/64, 128, GSM>>>(xyz, (const float*)0, (const float*)0, 0);
    gemm_tc<1><<<MTOT/64, 128, GSM>>>(xyz, g0, be0, 0);
    gemm_tc<2><<<MTOT/64, 128, GSM>>>(xyz, g1, be1, 0);
    gemm_tc<2><<<MTOT/64, 128, GSM>>>(xyz, g1, be1, 1);   // launch #6 -> ncu capture

    final_out_kernel<<<dim3(NGRP/32, 256/32), dim3(32, 8)>>>(g2, be2, out_feat);
}